// round 5
// baseline (speedup 1.0000x reference)
#include <cuda_runtime.h>
#include <cuda_bf16.h>
#include <math.h>
#include <stdint.h>

// ---------------- problem constants ----------------
#define BIMG 8
#define OPI_ 64
#define RPI_ 1024
#define NN 512            // N objects
#define RR 8192           // R relations
#define OBJD 4096
#define HD 512
#define NOC_ 151
#define NRC_ 51
#define TSTEPS 3
#define IOU_THR_ 0.3f

// ---------------- helpers ----------------------------------------------------
__device__ __forceinline__ void split_tf32(float v, uint32_t& hi, uint32_t& lo) {
    uint32_t h;
    asm("cvt.rna.tf32.f32 %0, %1;" : "=r"(h) : "f"(v));
    float l = v - __uint_as_float(h);
    uint32_t lb;
    asm("cvt.rna.tf32.f32 %0, %1;" : "=r"(lb) : "f"(l));
    hi = h; lo = lb;
}
__device__ __forceinline__ void mma_tf32(float* c, const uint32_t* a, const uint32_t* b) {
    asm volatile(
        "mma.sync.aligned.m16n8k8.row.col.f32.tf32.tf32.f32 "
        "{%0,%1,%2,%3},{%4,%5,%6,%7},{%8,%9},{%0,%1,%2,%3};"
        : "+f"(c[0]), "+f"(c[1]), "+f"(c[2]), "+f"(c[3])
        : "r"(a[0]), "r"(a[1]), "r"(a[2]), "r"(a[3]), "r"(b[0]), "r"(b[1]));
}
__device__ __forceinline__ void cp16(uint32_t dst, const void* src) {
    asm volatile("cp.async.cg.shared.global [%0], [%1], 16;" :: "r"(dst), "l"(src));
}

// ---------------- scratch (device globals; no runtime alloc allowed) -------
__device__ float g_obj_probs[NN * NOC_];
__device__ float g_fo[NN * HD];
__device__ float g_h_obj[NN * HD];
__device__ float g_h_rel[RR * HD];
__device__ float g_sumso[RR * HD];
__device__ float g_m_rel[RR * HD];
__device__ float g_hm[RR * HD];
__device__ float g_m_obj[NN * HD];
__device__ float g_xw_rel[RR * 3 * HD];
__device__ float g_hu_rel[RR * 2 * HD];
__device__ float g_z_rel[RR * HD];
__device__ float g_rh_rel[RR * HD];
__device__ float g_nu_rel[RR * HD];
__device__ float g_xw_obj[NN * 3 * HD];
__device__ float g_hu_obj[NN * 2 * HD];
__device__ float g_z_obj[NN * HD];
__device__ float g_rh_obj[NN * HD];
__device__ float g_nu_obj[NN * HD];
__device__ float g_sp[NN * NOC_];
__device__ unsigned char g_keep[150 * NN];
__device__ int g_s_idx[RR];
__device__ int g_o_idx[RR];

// split planes: A buffers
__device__ uint32_t g_A1h[RR * OBJD];
__device__ uint32_t g_A1l[RR * OBJD];
__device__ uint32_t g_A2h[RR * HD];
__device__ uint32_t g_A2l[RR * HD];
// weight planes (transposed [N,K])
__device__ uint32_t g_Wop_h[HD * OBJD],  g_Wop_l[HD * OBJD];
__device__ uint32_t g_Wrp_h[HD * OBJD],  g_Wrp_l[HD * OBJD];
__device__ uint32_t g_Wmr_h[HD * HD],    g_Wmr_l[HD * HD];
__device__ uint32_t g_Wmo_h[HD * HD],    g_Wmo_l[HD * HD];
__device__ uint32_t g_Wgr_h[3 * HD * HD], g_Wgr_l[3 * HD * HD];
__device__ uint32_t g_Ugr_h[3 * HD * HD], g_Ugr_l[3 * HD * HD];
__device__ uint32_t g_Wgo_h[3 * HD * HD], g_Wgo_l[3 * HD * HD];
__device__ uint32_t g_Ugo_h[3 * HD * HD], g_Ugo_l[3 * HD * HD];

// ============================================================================
// plane GEMM (mma.sync 3xTF32, pre-split operands):
//   C[M,N] = A[M,K] @ B^T (+bias),  A planes [M,K], B planes [N,K], K-major.
// 128x128x16 tile, 256 threads, 8 warps (2x4), warp tile 64x32, cp.async
// double buffering. Inner loop: LDS + MMA only.
// ============================================================================
#define PBK 16
#define ROWW 20                       // smem row stride in words (16 + 4 pad)
#define PLANE_BYTES (128 * ROWW * 4)  // 10240
#define STAGE_BYTES (4 * PLANE_BYTES) // Ah, Al, Bh, Bl
#define PSMEM (2 * STAGE_BYTES)       // 81920

__global__ __launch_bounds__(256, 1) void pgemm_kernel(
    const uint32_t* __restrict__ Ah, const uint32_t* __restrict__ Al,
    const uint32_t* __restrict__ Bh, const uint32_t* __restrict__ Bl,
    float* __restrict__ C, int ldc,
    int M, int N, int K, const float* __restrict__ bias)
{
    extern __shared__ uint32_t sm[];
    const int tid = threadIdx.x;
    const int lane = tid & 31;
    const int warp = tid >> 5;
    const int wm = warp >> 2;     // 0..1
    const int wn = warp & 3;      // 0..3
    const int lr = lane >> 2;     // 0..7
    const int lc = lane & 3;      // 0..3
    const int m0 = blockIdx.y * 128;
    const int n0 = blockIdx.x * 128;
    const int KT = K / PBK;

    const uint32_t sbase = (uint32_t)__cvta_generic_to_shared(sm);

    float acc[4][4][4];
#pragma unroll
    for (int i = 0; i < 4; i++)
#pragma unroll
        for (int j = 0; j < 4; j++)
#pragma unroll
            for (int l = 0; l < 4; l++) acc[i][j][l] = 0.f;

    // per-stage smem word offsets
    auto stage_off = [&](int buf) { return buf * (STAGE_BYTES / 4); };

    auto load_stage = [&](int kt, int buf) {
        const int k0 = kt * PBK;
        uint32_t base = sbase + (uint32_t)(stage_off(buf) * 4);
        // A planes: 128 rows x 4 16B-chunks each = 512 chunks/plane -> 2/thread
#pragma unroll
        for (int i = 0; i < 2; i++) {
            int cid = tid * 2 + i;
            int row = cid >> 2, ch = cid & 3;
            uint32_t d = base + (uint32_t)(row * ROWW * 4 + ch * 16);
            size_t src = (size_t)(m0 + row) * K + k0 + ch * 4;
            cp16(d, Ah + src);
            cp16(d + PLANE_BYTES, Al + src);
        }
        // B planes: 128 n-rows x 4 chunks = 512 chunks/plane -> 2/thread
#pragma unroll
        for (int i = 0; i < 2; i++) {
            int cid = tid * 2 + i;
            int row = cid >> 2, ch = cid & 3;
            uint32_t d = base + (uint32_t)(2 * PLANE_BYTES + row * ROWW * 4 + ch * 16);
            size_t src = (size_t)(n0 + row) * K + k0 + ch * 4;
            cp16(d, Bh + src);
            cp16(d + PLANE_BYTES, Bl + src);
        }
        asm volatile("cp.async.commit_group;");
    };

    load_stage(0, 0);
    if (KT > 1) load_stage(1, 1);
    asm volatile("cp.async.wait_group 1;");
    __syncthreads();

    for (int kt = 0; kt < KT; kt++) {
        const int cur = kt & 1;
        const uint32_t* As_h = sm + stage_off(cur);
        const uint32_t* As_l = As_h + PLANE_BYTES / 4;
        const uint32_t* Bs_h = As_h + 2 * PLANE_BYTES / 4;
        const uint32_t* Bs_l = As_h + 3 * PLANE_BYTES / 4;

#pragma unroll
        for (int kk = 0; kk < PBK; kk += 8) {
            uint32_t aH[4][4], aL[4][4], bH[4][2], bL[4][2];
#pragma unroll
            for (int mt = 0; mt < 4; mt++) {
                int r0 = (wm * 64 + mt * 16 + lr) * ROWW + kk + lc;
                int r1 = r0 + 8 * ROWW;
                aH[mt][0] = As_h[r0];     aL[mt][0] = As_l[r0];
                aH[mt][1] = As_h[r1];     aL[mt][1] = As_l[r1];
                aH[mt][2] = As_h[r0 + 4]; aL[mt][2] = As_l[r0 + 4];
                aH[mt][3] = As_h[r1 + 4]; aL[mt][3] = As_l[r1 + 4];
            }
#pragma unroll
            for (int nt = 0; nt < 4; nt++) {
                int r = (wn * 32 + nt * 8 + lr) * ROWW + kk + lc;
                bH[nt][0] = Bs_h[r];     bL[nt][0] = Bs_l[r];
                bH[nt][1] = Bs_h[r + 4]; bL[nt][1] = Bs_l[r + 4];
            }
#pragma unroll
            for (int mt = 0; mt < 4; mt++)
#pragma unroll
                for (int nt = 0; nt < 4; nt++) {
                    mma_tf32(acc[mt][nt], aH[mt], bH[nt]);  // hi*hi
                    mma_tf32(acc[mt][nt], aH[mt], bL[nt]);  // hi*lo
                    mma_tf32(acc[mt][nt], aL[mt], bH[nt]);  // lo*hi
                }
        }
        __syncthreads();
        if (kt + 2 < KT) {
            load_stage(kt + 2, cur);
            asm volatile("cp.async.wait_group 1;");
        } else if (kt + 1 < KT) {
            asm volatile("cp.async.wait_group 0;");
        }
        __syncthreads();
    }

    // epilogue
#pragma unroll
    for (int mt = 0; mt < 4; mt++) {
        int gm0 = m0 + wm * 64 + mt * 16 + lr;
        int gm1 = gm0 + 8;
#pragma unroll
        for (int nt = 0; nt < 4; nt++) {
            int gn = n0 + wn * 32 + nt * 8 + lc * 2;
            float b0 = 0.f, b1 = 0.f;
            if (bias) { b0 = bias[gn]; b1 = bias[gn + 1]; }
            float2 v0 = make_float2(acc[mt][nt][0] + b0, acc[mt][nt][1] + b1);
            float2 v1 = make_float2(acc[mt][nt][2] + b0, acc[mt][nt][3] + b1);
            *(float2*)(C + (size_t)gm0 * ldc + gn) = v0;
            *(float2*)(C + (size_t)gm1 * ldc + gn) = v1;
        }
    }
}

// ---------------- split kernels ---------------------------------------------
__global__ void asplit_kernel(const float4* __restrict__ in,
                              uint4* __restrict__ hi, uint4* __restrict__ lo, int n4) {
    int i = blockIdx.x * blockDim.x + threadIdx.x;
    if (i >= n4) return;
    float4 v = in[i];
    uint4 h, l;
    split_tf32(v.x, h.x, l.x);
    split_tf32(v.y, h.y, l.y);
    split_tf32(v.z, h.z, l.z);
    split_tf32(v.w, h.w, l.w);
    hi[i] = h; lo[i] = l;
}

// W [K,N] row-major -> T_hi/T_lo [N,K]
__global__ void tsplit_kernel(const float* __restrict__ W,
                              uint32_t* __restrict__ Th, uint32_t* __restrict__ Tl,
                              int K, int N) {
    __shared__ float t[32][33];
    int kb = blockIdx.y * 32, nb = blockIdx.x * 32;
    int tx = threadIdx.x, ty = threadIdx.y;  // 32 x 8
#pragma unroll
    for (int i = 0; i < 32; i += 8)
        t[ty + i][tx] = W[(size_t)(kb + ty + i) * N + nb + tx];
    __syncthreads();
#pragma unroll
    for (int i = 0; i < 32; i += 8) {
        int n = nb + ty + i, k = kb + tx;
        uint32_t h, l;
        split_tf32(t[tx][ty + i], h, l);
        Th[(size_t)n * K + k] = h;
        Tl[(size_t)n * K + k] = l;
    }
}

// ---------------- generic fp32 SGEMM (small/odd shapes only) ----------------
__global__ __launch_bounds__(256) void sgemm_kernel(
    const float* __restrict__ A, int lda,
    const float* __restrict__ B, int ldb,
    float* __restrict__ C, int ldc,
    int M, int N, int K,
    const float* __restrict__ bias,
    const float* __restrict__ addm)
{
    __shared__ float As[8][132];
    __shared__ float Bs[8][128];
    const int tid = threadIdx.x;
    const int tx = tid & 15;
    const int ty = tid >> 4;
    const int m0 = blockIdx.y * 128;
    const int n0 = blockIdx.x * 128;

    float acc[8][8];
#pragma unroll
    for (int i = 0; i < 8; i++)
#pragma unroll
        for (int j = 0; j < 8; j++) acc[i][j] = 0.f;

    for (int k0 = 0; k0 < K; k0 += 8) {
#pragma unroll
        for (int l = 0; l < 4; l++) {
            int e = tid + l * 256;
            int r = e >> 3, c = e & 7;
            float v = 0.f;
            int gm = m0 + r, gk = k0 + c;
            if (gm < M && gk < K) v = A[(size_t)gm * lda + gk];
            As[c][r] = v;
        }
#pragma unroll
        for (int l = 0; l < 4; l++) {
            int e = tid + l * 256;
            int r = e >> 7, c = e & 127;
            float v = 0.f;
            int gk = k0 + r, gn = n0 + c;
            if (gk < K && gn < N) v = B[(size_t)gk * ldb + gn];
            Bs[r][c] = v;
        }
        __syncthreads();
#pragma unroll
        for (int k = 0; k < 8; k++) {
            float a[8], b[8];
#pragma unroll
            for (int i = 0; i < 8; i++) a[i] = As[k][ty * 8 + i];
#pragma unroll
            for (int j = 0; j < 8; j++) b[j] = Bs[k][tx * 8 + j];
#pragma unroll
            for (int i = 0; i < 8; i++)
#pragma unroll
                for (int j = 0; j < 8; j++)
                    acc[i][j] = fmaf(a[i], b[j], acc[i][j]);
        }
        __syncthreads();
    }
#pragma unroll
    for (int i = 0; i < 8; i++) {
        int gm = m0 + ty * 8 + i;
        if (gm >= M) continue;
#pragma unroll
        for (int j = 0; j < 8; j++) {
            int gn = n0 + tx * 8 + j;
            if (gn >= N) continue;
            float v = acc[i][j];
            if (bias) v += bias[gn];
            if (addm) v += addm[(size_t)gm * ldc + gn];
            C[(size_t)gm * ldc + gn] = v;
        }
    }
}

// ---------------- decode rel_inds (handles int64 OR int32 storage) ---------
__global__ __launch_bounds__(1024) void decode_rel_kernel(const void* rel_raw) {
    __shared__ int s_or;
    int tid = threadIdx.x;
    if (tid == 0) s_or = 0;
    __syncthreads();
    const int* v32 = (const int*)rel_raw;
    int acc = 0;
    for (int i = tid; i < (3 * RR) / 2; i += 1024) acc |= v32[2 * i + 1];
    if (acc) atomicOr(&s_or, 1);
    __syncthreads();
    bool is64 = (s_or == 0);
    if (is64) {
        const long long* v = (const long long*)rel_raw;
        for (int r = tid; r < RR; r += 1024) {
            g_s_idx[r] = (int)v[3 * r + 1];
            g_o_idx[r] = (int)v[3 * r + 2];
        }
    } else {
        for (int r = tid; r < RR; r += 1024) {
            g_s_idx[r] = v32[3 * r + 1];
            g_o_idx[r] = v32[3 * r + 2];
        }
    }
}

// ---------------- row softmax over NOC columns ------------------------------
__global__ void softmax_kernel(const float* __restrict__ X, float* __restrict__ Y) {
    int row = blockIdx.x;
    int tid = threadIdx.x;  // 256
    __shared__ float red[256];
    const float* x = X + (size_t)row * NOC_;
    float m = -3.4e38f;
    for (int c = tid; c < NOC_; c += 256) m = fmaxf(m, x[c]);
    red[tid] = m; __syncthreads();
    for (int s = 128; s > 0; s >>= 1) {
        if (tid < s) red[tid] = fmaxf(red[tid], red[tid + s]);
        __syncthreads();
    }
    m = red[0]; __syncthreads();
    float sum = 0.f;
    for (int c = tid; c < NOC_; c += 256) sum += expf(x[c] - m);
    red[tid] = sum; __syncthreads();
    for (int s = 128; s > 0; s >>= 1) {
        if (tid < s) red[tid] += red[tid + s];
        __syncthreads();
    }
    float inv = 1.f / red[0];
    for (int c = tid; c < NOC_; c += 256)
        Y[(size_t)row * NOC_ + c] = expf(x[c] - m) * inv;
}

// ---------------- SUMSO[r] = h_obj[s_r] + h_obj[o_r] ------------------------
__global__ void gather_sum_kernel(const float* __restrict__ Hobj, float* __restrict__ out) {
    int idx = blockIdx.x * blockDim.x + threadIdx.x;
    if (idx >= RR * HD) return;
    int r = idx >> 9;
    int c = idx & 511;
    int s = g_s_idx[r];
    int o = g_o_idx[r];
    out[idx] = Hobj[(size_t)s * HD + c] + Hobj[(size_t)o * HD + c];
}

// ---------------- m_obj scatter: deterministic block-per-object scan --------
__global__ __launch_bounds__(512) void scatter_obj_kernel(const float* __restrict__ HM,
                                                          float* __restrict__ MOBJ) {
    int obj = blockIdx.x;
    int c = threadIdx.x;
    int img = obj >> 6;
    int base = img * RPI_;
    __shared__ int ss[RPI_];
    __shared__ int oo[RPI_];
    for (int j = c; j < RPI_; j += 512) {
        ss[j] = g_s_idx[base + j];
        oo[j] = g_o_idx[base + j];
    }
    __syncthreads();
    float acc = 0.f;
    for (int j = 0; j < RPI_; j++) {
        if (ss[j] == obj) acc += HM[(size_t)(base + j) * HD + c];
        if (oo[j] == obj) acc += HM[(size_t)(base + j) * HD + c];
    }
    MOBJ[(size_t)obj * HD + c] = acc;
}

// ---------------- GRU elementwise: z, r*h ------------------------------------
__global__ void gru_zr_kernel(const float* __restrict__ XW, const float* __restrict__ HU,
                              const float* __restrict__ b, const float* __restrict__ Hh,
                              float* __restrict__ Z, float* __restrict__ RH, int M) {
    int idx = blockIdx.x * blockDim.x + threadIdx.x;
    if (idx >= M * HD) return;
    int row = idx >> 9;
    int c = idx & 511;
    float z = XW[(size_t)row * 1536 + c] + HU[(size_t)row * 1024 + c] + b[c];
    float r = XW[(size_t)row * 1536 + 512 + c] + HU[(size_t)row * 1024 + 512 + c] + b[512 + c];
    z = 1.f / (1.f + expf(-z));
    r = 1.f / (1.f + expf(-r));
    Z[idx] = z;
    RH[idx] = r * Hh[idx];
}

// ---------------- GRU elementwise: n, h update (in place) -------------------
__global__ void gru_fin_kernel(const float* __restrict__ XW, const float* __restrict__ NU,
                               const float* __restrict__ b, const float* __restrict__ Z,
                               float* __restrict__ Hh, int M) {
    int idx = blockIdx.x * blockDim.x + threadIdx.x;
    if (idx >= M * HD) return;
    int row = idx >> 9;
    int c = idx & 511;
    float n = tanhf(XW[(size_t)row * 1536 + 1024 + c] + NU[idx] + b[1024 + c]);
    float z = Z[idx];
    Hh[idx] = (1.f - z) * Hh[idx] + z * n;
}

// ---------------- NMS: one block per class (1..150) -------------------------
__global__ __launch_bounds__(512) void nms_kernel(const float* __restrict__ SP,
                                                  const float* __restrict__ BOX,
                                                  unsigned char* __restrict__ KEEP) {
    int cls = blockIdx.x + 1;
    int tid = threadIdx.x;
    __shared__ float sc[NN];
    __shared__ int sidx[NN];
    __shared__ float bx[NN][4];
    __shared__ float area[NN];
    __shared__ unsigned char keep[NN];

    sc[tid] = SP[(size_t)tid * NOC_ + cls];
    sidx[tid] = tid;
    __syncthreads();

    for (int k = 2; k <= NN; k <<= 1) {
        for (int j = k >> 1; j > 0; j >>= 1) {
            int ixj = tid ^ j;
            if (ixj > tid) {
                float s1 = sc[tid], s2 = sc[ixj];
                int i1 = sidx[tid], i2 = sidx[ixj];
                bool dir = ((tid & k) == 0);
                bool precBA = (s2 > s1) || (s2 == s1 && i2 < i1);
                if (precBA == dir) {
                    sc[tid] = s2; sc[ixj] = s1;
                    sidx[tid] = i2; sidx[ixj] = i1;
                }
            }
            __syncthreads();
        }
    }

    int oi = sidx[tid];
    float x1 = BOX[((size_t)oi * NOC_ + cls) * 4 + 0];
    float y1 = BOX[((size_t)oi * NOC_ + cls) * 4 + 1];
    float x2 = BOX[((size_t)oi * NOC_ + cls) * 4 + 2];
    float y2 = BOX[((size_t)oi * NOC_ + cls) * 4 + 3];
    bx[tid][0] = x1; bx[tid][1] = y1; bx[tid][2] = x2; bx[tid][3] = y2;
    area[tid] = (x2 - x1) * (y2 - y1);
    keep[tid] = 1;
    __syncthreads();

    for (int i = 0; i < NN - 1; i++) {
        if (tid > i && keep[i] && keep[tid]) {
            float lx = fmaxf(bx[i][0], x1);
            float ly = fmaxf(bx[i][1], y1);
            float rx = fminf(bx[i][2], x2);
            float ry = fminf(bx[i][3], y2);
            float w = fmaxf(rx - lx, 0.f);
            float h = fmaxf(ry - ly, 0.f);
            float inter = w * h;
            float iou = inter / (area[i] + area[tid] - inter + 1e-9f);
            if (iou > IOU_THR_) keep[tid] = 0;
        }
        __syncthreads();
    }
    KEEP[(size_t)(cls - 1) * NN + oi] = keep[tid];
}

// ---------------- obj_preds: argmax over kept class scores ------------------
__global__ void preds_kernel(const float* __restrict__ SP, const unsigned char* __restrict__ KEEP,
                             float* __restrict__ out) {
    int n = blockIdx.x * blockDim.x + threadIdx.x;
    if (n >= NN) return;
    float best = -1.f;
    int bi = 0;
    for (int c = 0; c < 150; c++) {
        float v = KEEP[(size_t)c * NN + n] ? SP[(size_t)n * NOC_ + c + 1] : 0.f;
        if (v > best) { best = v; bi = c; }
    }
    out[n] = (float)(bi + 1);
}

// ---------------- host orchestration ----------------------------------------
static void sgemm(const float* A, int lda, const float* B, int ldb,
                  float* C, int ldc, int M, int N, int K,
                  const float* bias, const float* addm) {
    dim3 g((N + 127) / 128, (M + 127) / 128);
    sgemm_kernel<<<g, 256>>>(A, lda, B, ldb, C, ldc, M, N, K, bias, addm);
}

struct Scratch {
    float *OBJ_PROBS, *FO, *HOBJ, *HREL, *SUMSO, *MREL, *HM, *MOBJ;
    float *XWR, *HUR, *ZR, *RHR, *NUR, *XWO, *HUO, *ZO, *RHO, *NUO, *SP;
    unsigned char* KEEP;
    uint32_t *A1h, *A1l, *A2h, *A2l;
    uint32_t *Wop_h, *Wop_l, *Wrp_h, *Wrp_l, *Wmr_h, *Wmr_l, *Wmo_h, *Wmo_l;
    uint32_t *Wgr_h, *Wgr_l, *Ugr_h, *Ugr_l, *Wgo_h, *Wgo_l, *Ugo_h, *Ugo_l;
    bool init = false;
};
static Scratch g_sc;

static void init_scratch() {
    if (g_sc.init) return;
    void* p;
#define GET(sym, fld, T) cudaGetSymbolAddress(&p, sym); g_sc.fld = (T*)p;
    GET(g_obj_probs, OBJ_PROBS, float)
    GET(g_fo, FO, float)
    GET(g_h_obj, HOBJ, float)
    GET(g_h_rel, HREL, float)
    GET(g_sumso, SUMSO, float)
    GET(g_m_rel, MREL, float)
    GET(g_hm, HM, float)
    GET(g_m_obj, MOBJ, float)
    GET(g_xw_rel, XWR, float)
    GET(g_hu_rel, HUR, float)
    GET(g_z_rel, ZR, float)
    GET(g_rh_rel, RHR, float)
    GET(g_nu_rel, NUR, float)
    GET(g_xw_obj, XWO, float)
    GET(g_hu_obj, HUO, float)
    GET(g_z_obj, ZO, float)
    GET(g_rh_obj, RHO, float)
    GET(g_nu_obj, NUO, float)
    GET(g_sp, SP, float)
    GET(g_keep, KEEP, unsigned char)
    GET(g_A1h, A1h, uint32_t)  GET(g_A1l, A1l, uint32_t)
    GET(g_A2h, A2h, uint32_t)  GET(g_A2l, A2l, uint32_t)
    GET(g_Wop_h, Wop_h, uint32_t) GET(g_Wop_l, Wop_l, uint32_t)
    GET(g_Wrp_h, Wrp_h, uint32_t) GET(g_Wrp_l, Wrp_l, uint32_t)
    GET(g_Wmr_h, Wmr_h, uint32_t) GET(g_Wmr_l, Wmr_l, uint32_t)
    GET(g_Wmo_h, Wmo_h, uint32_t) GET(g_Wmo_l, Wmo_l, uint32_t)
    GET(g_Wgr_h, Wgr_h, uint32_t) GET(g_Wgr_l, Wgr_l, uint32_t)
    GET(g_Ugr_h, Ugr_h, uint32_t) GET(g_Ugr_l, Ugr_l, uint32_t)
    GET(g_Wgo_h, Wgo_h, uint32_t) GET(g_Wgo_l, Wgo_l, uint32_t)
    GET(g_Ugo_h, Ugo_h, uint32_t) GET(g_Ugo_l, Ugo_l, uint32_t)
#undef GET
    cudaFuncSetAttribute(pgemm_kernel, cudaFuncAttributeMaxDynamicSharedMemorySize, PSMEM);
    g_sc.init = true;
}

static void pgemm(const uint32_t* Ah, const uint32_t* Al,
                  const uint32_t* Bh, const uint32_t* Bl,
                  float* C, int ldc, int M, int N, int K, const float* bias) {
    dim3 g(N / 128, M / 128);
    pgemm_kernel<<<g, 256, PSMEM>>>(Ah, Al, Bh, Bl, C, ldc, M, N, K, bias);
}

static void asplit(const float* A, uint32_t* hi, uint32_t* lo, int n) {
    int n4 = n / 4;
    asplit_kernel<<<(n4 + 255) / 256, 256>>>((const float4*)A, (uint4*)hi, (uint4*)lo, n4);
}

static void tsplit(const float* W, uint32_t* Th, uint32_t* Tl, int K, int N) {
    dim3 g(N / 32, K / 32);
    tsplit_kernel<<<g, dim3(32, 8)>>>(W, Th, Tl, K, N);
}

extern "C" void kernel_launch(void* const* d_in, const int* in_sizes, int n_in,
                              void* d_out, int out_size) {
    (void)in_sizes; (void)n_in; (void)out_size;
    init_scratch();

    const float* obj_fmaps  = (const float*)d_in[1];
    const float* obj_logits = (const float*)d_in[2];
    const void*  rel_raw    = d_in[3];
    const float* vr         = (const float*)d_in[4];
    const float* boxes      = (const float*)d_in[5];
    const float* W_obj_proj = (const float*)d_in[6];
    const float* b_obj_proj = (const float*)d_in[7];
    const float* W_rel_proj = (const float*)d_in[8];
    const float* b_rel_proj = (const float*)d_in[9];
    const float* W_emb      = (const float*)d_in[10];
    const float* W_msg_rel  = (const float*)d_in[11];
    const float* W_msg_obj  = (const float*)d_in[12];
    const float* W_gru_obj  = (const float*)d_in[13];
    const float* U_gru_obj  = (const float*)d_in[14];
    const float* b_gru_obj  = (const float*)d_in[15];
    const float* W_gru_rel  = (const float*)d_in[16];
    const float* U_gru_rel  = (const float*)d_in[17];
    const float* b_gru_rel  = (const float*)d_in[18];
    const float* W_cls_rel  = (const float*)d_in[19];
    const float* b_cls_rel  = (const float*)d_in[20];
    const float* W_cls_obj  = (const float*)d_in[21];
    const float* b_cls_obj  = (const float*)d_in[22];

    float* out_obj_logits = (float*)d_out;                 // 512*151
    float* out_preds      = out_obj_logits + NN * NOC_;    // 512
    float* out_rel_logits = out_preds + NN;                // 8192*51

    // 0. decode rel indices + weight transpose/splits
    decode_rel_kernel<<<1, 1024>>>(rel_raw);
    tsplit(W_obj_proj, g_sc.Wop_h, g_sc.Wop_l, OBJD, HD);
    tsplit(W_rel_proj, g_sc.Wrp_h, g_sc.Wrp_l, OBJD, HD);
    tsplit(W_msg_rel,  g_sc.Wmr_h, g_sc.Wmr_l, HD, HD);
    tsplit(W_msg_obj,  g_sc.Wmo_h, g_sc.Wmo_l, HD, HD);
    tsplit(W_gru_rel,  g_sc.Wgr_h, g_sc.Wgr_l, HD, 3 * HD);
    tsplit(U_gru_rel,  g_sc.Ugr_h, g_sc.Ugr_l, HD, 3 * HD);
    tsplit(W_gru_obj,  g_sc.Wgo_h, g_sc.Wgo_l, HD, 3 * HD);
    tsplit(U_gru_obj,  g_sc.Ugo_h, g_sc.Ugo_l, HD, 3 * HD);

    // 1. obj_probs = softmax(obj_logits)
    softmax_kernel<<<NN, 256>>>(obj_logits, g_sc.OBJ_PROBS);

    // 2. fo = obj_fmaps @ W_obj_proj + b
    asplit(obj_fmaps, g_sc.A1h, g_sc.A1l, NN * OBJD);
    pgemm(g_sc.A1h, g_sc.A1l, g_sc.Wop_h, g_sc.Wop_l, g_sc.FO, HD, NN, HD, OBJD, b_obj_proj);

    // 3. h_obj = fo + obj_probs @ W_emb           (K=151 -> SIMT, addm)
    sgemm(g_sc.OBJ_PROBS, NOC_, W_emb, HD, g_sc.HOBJ, HD, NN, HD, NOC_, nullptr, g_sc.FO);

    // 4. h_rel = vr @ W_rel_proj + b              (big)
    asplit(vr, g_sc.A1h, g_sc.A1l, RR * OBJD);
    pgemm(g_sc.A1h, g_sc.A1l, g_sc.Wrp_h, g_sc.Wrp_l, g_sc.HREL, HD, RR, HD, OBJD, b_rel_proj);

    const int EW_REL_BLOCKS = (RR * HD + 255) / 256;
    const int EW_OBJ_BLOCKS = (NN * HD + 255) / 256;
    const uint32_t* Ugr2_h = g_sc.Ugr_h + 2 * HD * HD;  // rows [1024,1536) of U^T
    const uint32_t* Ugr2_l = g_sc.Ugr_l + 2 * HD * HD;
    const uint32_t* Ugo2_h = g_sc.Ugo_h + 2 * HD * HD;
    const uint32_t* Ugo2_l = g_sc.Ugo_l + 2 * HD * HD;

    for (int t = 0; t < TSTEPS; t++) {
        // messages (all from pre-update states)
        gather_sum_kernel<<<EW_REL_BLOCKS, 256>>>(g_sc.HOBJ, g_sc.SUMSO);
        asplit(g_sc.SUMSO, g_sc.A1h, g_sc.A1l, RR * HD);
        pgemm(g_sc.A1h, g_sc.A1l, g_sc.Wmr_h, g_sc.Wmr_l, g_sc.MREL, HD, RR, HD, HD, nullptr);
        asplit(g_sc.HREL, g_sc.A2h, g_sc.A2l, RR * HD);   // pre-update h_rel snapshot
        pgemm(g_sc.A2h, g_sc.A2l, g_sc.Wmo_h, g_sc.Wmo_l, g_sc.HM, HD, RR, HD, HD, nullptr);
        scatter_obj_kernel<<<NN, 512>>>(g_sc.HM, g_sc.MOBJ);

        // GRU on relations
        asplit(g_sc.MREL, g_sc.A1h, g_sc.A1l, RR * HD);
        pgemm(g_sc.A1h, g_sc.A1l, g_sc.Wgr_h, g_sc.Wgr_l, g_sc.XWR, 3 * HD, RR, 3 * HD, HD, nullptr);
        pgemm(g_sc.A2h, g_sc.A2l, g_sc.Ugr_h, g_sc.Ugr_l, g_sc.HUR, 2 * HD, RR, 2 * HD, HD, nullptr);
        gru_zr_kernel<<<EW_REL_BLOCKS, 256>>>(g_sc.XWR, g_sc.HUR, b_gru_rel, g_sc.HREL, g_sc.ZR, g_sc.RHR, RR);
        asplit(g_sc.RHR, g_sc.A1h, g_sc.A1l, RR * HD);
        pgemm(g_sc.A1h, g_sc.A1l, Ugr2_h, Ugr2_l, g_sc.NUR, HD, RR, HD, HD, nullptr);
        gru_fin_kernel<<<EW_REL_BLOCKS, 256>>>(g_sc.XWR, g_sc.NUR, b_gru_rel, g_sc.ZR, g_sc.HREL, RR);

        // GRU on objects
        asplit(g_sc.MOBJ, g_sc.A1h, g_sc.A1l, NN * HD);
        pgemm(g_sc.A1h, g_sc.A1l, g_sc.Wgo_h, g_sc.Wgo_l, g_sc.XWO, 3 * HD, NN, 3 * HD, HD, nullptr);
        asplit(g_sc.HOBJ, g_sc.A2h, g_sc.A2l, NN * HD);
        pgemm(g_sc.A2h, g_sc.A2l, g_sc.Ugo_h, g_sc.Ugo_l, g_sc.HUO, 2 * HD, NN, 2 * HD, HD, nullptr);
        gru_zr_kernel<<<EW_OBJ_BLOCKS, 256>>>(g_sc.XWO, g_sc.HUO, b_gru_obj, g_sc.HOBJ, g_sc.ZO, g_sc.RHO, NN);
        asplit(g_sc.RHO, g_sc.A1h, g_sc.A1l, NN * HD);
        pgemm(g_sc.A1h, g_sc.A1l, Ugo2_h, Ugo2_l, g_sc.NUO, HD, NN, HD, HD, nullptr);
        gru_fin_kernel<<<EW_OBJ_BLOCKS, 256>>>(g_sc.XWO, g_sc.NUO, b_gru_obj, g_sc.ZO, g_sc.HOBJ, NN);
    }

    // classifiers (odd N -> SIMT)
    sgemm(g_sc.HREL, HD, W_cls_rel, NRC_, out_rel_logits, NRC_, RR, NRC_, HD, b_cls_rel, nullptr);
    sgemm(g_sc.HOBJ, HD, W_cls_obj, NOC_, out_obj_logits, NOC_, NN, NOC_, HD, b_cls_obj, nullptr);

    // softmax -> NMS -> preds
    softmax_kernel<<<NN, 256>>>(out_obj_logits, g_sc.SP);
    nms_kernel<<<150, 512>>>(g_sc.SP, boxes, g_sc.KEEP);
    preds_kernel<<<(NN + 255) / 256, 256>>>(g_sc.SP, g_sc.KEEP, out_preds);
}

// round 6
// speedup vs baseline: 1.2540x; 1.2540x over previous
#include <cuda_runtime.h>
#include <cuda_bf16.h>
#include <math.h>
#include <stdint.h>

// ---------------- problem constants ----------------
#define BIMG 8
#define OPI_ 64
#define RPI_ 1024
#define NN 512            // N objects
#define RR 8192           // R relations
#define OBJD 4096
#define HD 512
#define NOC_ 151
#define NRC_ 51
#define TSTEPS 3
#define IOU_THR_ 0.3f

// ---------------- helpers ----------------------------------------------------
__device__ __forceinline__ void split_tf32(float v, uint32_t& hi, uint32_t& lo) {
    uint32_t h;
    asm("cvt.rna.tf32.f32 %0, %1;" : "=r"(h) : "f"(v));
    float l = v - __uint_as_float(h);
    uint32_t lb;
    asm("cvt.rna.tf32.f32 %0, %1;" : "=r"(lb) : "f"(l));
    hi = h; lo = lb;
}
__device__ __forceinline__ void mma_tf32(float* c, const uint32_t* a, const uint32_t* b) {
    asm volatile(
        "mma.sync.aligned.m16n8k8.row.col.f32.tf32.tf32.f32 "
        "{%0,%1,%2,%3},{%4,%5,%6,%7},{%8,%9},{%0,%1,%2,%3};"
        : "+f"(c[0]), "+f"(c[1]), "+f"(c[2]), "+f"(c[3])
        : "r"(a[0]), "r"(a[1]), "r"(a[2]), "r"(a[3]), "r"(b[0]), "r"(b[1]));
}

// ---------------- scratch (device globals; no runtime alloc allowed) -------
__device__ float g_obj_probs[NN * NOC_];
__device__ float g_fo[NN * HD];
__device__ float g_h_obj[NN * HD];
__device__ float g_h_rel[RR * HD];
__device__ float g_sumso[RR * HD];
__device__ float g_xw_rel[RR * 3 * HD];      // XWR [8192,1536]
__device__ float g_hmhu[RR * 3 * HD];        // [HM | HU01] [8192,1536]
__device__ float g_m_obj[NN * HD];
__device__ float g_z_rel[RR * HD];
__device__ float g_rh_rel[RR * HD];
__device__ float g_nu_rel[RR * HD];
__device__ float g_xw_obj[NN * 3 * HD];
__device__ float g_hu_obj[NN * 2 * HD];
__device__ float g_z_obj[NN * HD];
__device__ float g_rh_obj[NN * HD];
__device__ float g_nu_obj[NN * HD];
__device__ float g_sp[NN * NOC_];
__device__ unsigned char g_keep[150 * NN];
__device__ int g_s_idx[RR];
__device__ int g_o_idx[RR];
__device__ float g_wcomb[HD * 3 * HD];       // W_msg_rel @ W_gru_rel  [512,1536]
__device__ float g_wcat[HD * 3 * HD];        // [W_msg_obj | U_gru_rel[:, :1024]]

// ============================================================================
// 3xTF32 tensor-core GEMM, fp32 operands, split at smem staging.
//   C[M,N] = A[M,K] @ B[K,N] (+bias).  M%128==0, N%128==0, K%16==0.
// 128x128x16 tile, 256 threads, 8 warps (2x4), warp tile 64x32.
// Double-buffered reg->smem staging; inner loop = LDS + MMA only.
// ============================================================================
#define AW 2560   // A plane words per buf (128 rows * 20)
#define BW 2176   // B plane words per buf (16 rows * 136)
#define TG_SMEM ((4 * AW + 4 * BW) * 4)   // 75776 bytes

__global__ __launch_bounds__(256, 2) void tgemm2_kernel(
    const float* __restrict__ A, int lda,
    const float* __restrict__ B, int ldb,
    float* __restrict__ C, int ldc,
    int M, int N, int K, const float* __restrict__ bias)
{
    extern __shared__ uint32_t sm[];
    const int tid = threadIdx.x;
    const int lane = tid & 31;
    const int warp = tid >> 5;
    const int wm = warp >> 2;     // 0..1
    const int wn = warp & 3;      // 0..3
    const int lr = lane >> 2;     // 0..7
    const int lc = lane & 3;      // 0..3
    const int m0 = blockIdx.y * 128;
    const int n0 = blockIdx.x * 128;
    const int KT = K / 16;

    const int a_row = tid >> 1;          // 0..127
    const int a_col = (tid & 1) * 8;     // 0 or 8
    const int b_row = tid >> 4;          // 0..15
    const int b_col = (tid & 15) * 8;    // 0..120

    float4 ra0, ra1, rb0, rb1;

    auto load = [&](int kt) {
        const float* ap = A + (size_t)(m0 + a_row) * lda + kt * 16 + a_col;
        ra0 = *(const float4*)ap;
        ra1 = *(const float4*)(ap + 4);
        const float* bp = B + (size_t)(kt * 16 + b_row) * ldb + n0 + b_col;
        rb0 = *(const float4*)bp;
        rb1 = *(const float4*)(bp + 4);
    };

    auto store = [&](int buf) {
        uint32_t* Ah = sm + buf * 2 * AW;
        uint32_t* Al = Ah + AW;
        uint32_t* Bh = sm + 4 * AW + buf * 2 * BW;
        uint32_t* Bl = Bh + BW;
        float av[8] = {ra0.x, ra0.y, ra0.z, ra0.w, ra1.x, ra1.y, ra1.z, ra1.w};
        float bv[8] = {rb0.x, rb0.y, rb0.z, rb0.w, rb1.x, rb1.y, rb1.z, rb1.w};
        uint32_t h[8], l[8];
#pragma unroll
        for (int i = 0; i < 8; i++) split_tf32(av[i], h[i], l[i]);
        int ab = a_row * 20 + a_col;
        *(uint4*)(Ah + ab)     = make_uint4(h[0], h[1], h[2], h[3]);
        *(uint4*)(Ah + ab + 4) = make_uint4(h[4], h[5], h[6], h[7]);
        *(uint4*)(Al + ab)     = make_uint4(l[0], l[1], l[2], l[3]);
        *(uint4*)(Al + ab + 4) = make_uint4(l[4], l[5], l[6], l[7]);
#pragma unroll
        for (int i = 0; i < 8; i++) split_tf32(bv[i], h[i], l[i]);
        int bb = b_row * 136 + b_col;
        *(uint4*)(Bh + bb)     = make_uint4(h[0], h[1], h[2], h[3]);
        *(uint4*)(Bh + bb + 4) = make_uint4(h[4], h[5], h[6], h[7]);
        *(uint4*)(Bl + bb)     = make_uint4(l[0], l[1], l[2], l[3]);
        *(uint4*)(Bl + bb + 4) = make_uint4(l[4], l[5], l[6], l[7]);
    };

    float acc[4][4][4];
#pragma unroll
    for (int i = 0; i < 4; i++)
#pragma unroll
        for (int j = 0; j < 4; j++)
#pragma unroll
            for (int l = 0; l < 4; l++) acc[i][j][l] = 0.f;

    load(0);
    store(0);
    __syncthreads();
    if (KT > 1) load(1);

    for (int kt = 0; kt < KT; kt++) {
        const int cur = kt & 1;
        const uint32_t* Ah = sm + cur * 2 * AW;
        const uint32_t* Al = Ah + AW;
        const uint32_t* Bh = sm + 4 * AW + cur * 2 * BW;
        const uint32_t* Bl = Bh + BW;

#pragma unroll
        for (int kk = 0; kk < 16; kk += 8) {
            uint32_t aH[4][4], aL[4][4], bH[4][2], bL[4][2];
#pragma unroll
            for (int mt = 0; mt < 4; mt++) {
                int r0 = (wm * 64 + mt * 16 + lr) * 20 + kk + lc;
                int r1 = r0 + 8 * 20;
                aH[mt][0] = Ah[r0];     aL[mt][0] = Al[r0];
                aH[mt][1] = Ah[r1];     aL[mt][1] = Al[r1];
                aH[mt][2] = Ah[r0 + 4]; aL[mt][2] = Al[r0 + 4];
                aH[mt][3] = Ah[r1 + 4]; aL[mt][3] = Al[r1 + 4];
            }
#pragma unroll
            for (int nt = 0; nt < 4; nt++) {
                int nc = wn * 32 + nt * 8 + lr;
                int r0 = (kk + lc) * 136 + nc;
                int r1 = r0 + 4 * 136;
                bH[nt][0] = Bh[r0]; bL[nt][0] = Bl[r0];
                bH[nt][1] = Bh[r1]; bL[nt][1] = Bl[r1];
            }
#pragma unroll
            for (int mt = 0; mt < 4; mt++)
#pragma unroll
                for (int nt = 0; nt < 4; nt++) {
                    mma_tf32(acc[mt][nt], aH[mt], bH[nt]);  // hi*hi
                    mma_tf32(acc[mt][nt], aH[mt], bL[nt]);  // hi*lo
                    mma_tf32(acc[mt][nt], aL[mt], bH[nt]);  // lo*hi
                }
        }
        if (kt + 1 < KT) {
            store(cur ^ 1);
            if (kt + 2 < KT) load(kt + 2);
            __syncthreads();
        }
    }

    // epilogue
#pragma unroll
    for (int mt = 0; mt < 4; mt++) {
        int gm0 = m0 + wm * 64 + mt * 16 + lr;
        int gm1 = gm0 + 8;
#pragma unroll
        for (int nt = 0; nt < 4; nt++) {
            int gn = n0 + wn * 32 + nt * 8 + lc * 2;
            float b0 = 0.f, b1 = 0.f;
            if (bias) { b0 = bias[gn]; b1 = bias[gn + 1]; }
            float2 v0 = make_float2(acc[mt][nt][0] + b0, acc[mt][nt][1] + b1);
            float2 v1 = make_float2(acc[mt][nt][2] + b0, acc[mt][nt][3] + b1);
            *(float2*)(C + (size_t)gm0 * ldc + gn) = v0;
            *(float2*)(C + (size_t)gm1 * ldc + gn) = v1;
        }
    }
}

// ---------------- generic fp32 SGEMM (small/odd shapes only) ----------------
__global__ __launch_bounds__(256) void sgemm_kernel(
    const float* __restrict__ A, int lda,
    const float* __restrict__ B, int ldb,
    float* __restrict__ C, int ldc,
    int M, int N, int K,
    const float* __restrict__ bias,
    const float* __restrict__ addm)
{
    __shared__ float As[8][132];
    __shared__ float Bs[8][128];
    const int tid = threadIdx.x;
    const int tx = tid & 15;
    const int ty = tid >> 4;
    const int m0 = blockIdx.y * 128;
    const int n0 = blockIdx.x * 128;

    float acc[8][8];
#pragma unroll
    for (int i = 0; i < 8; i++)
#pragma unroll
        for (int j = 0; j < 8; j++) acc[i][j] = 0.f;

    for (int k0 = 0; k0 < K; k0 += 8) {
#pragma unroll
        for (int l = 0; l < 4; l++) {
            int e = tid + l * 256;
            int r = e >> 3, c = e & 7;
            float v = 0.f;
            int gm = m0 + r, gk = k0 + c;
            if (gm < M && gk < K) v = A[(size_t)gm * lda + gk];
            As[c][r] = v;
        }
#pragma unroll
        for (int l = 0; l < 4; l++) {
            int e = tid + l * 256;
            int r = e >> 7, c = e & 127;
            float v = 0.f;
            int gk = k0 + r, gn = n0 + c;
            if (gk < K && gn < N) v = B[(size_t)gk * ldb + gn];
            Bs[r][c] = v;
        }
        __syncthreads();
#pragma unroll
        for (int k = 0; k < 8; k++) {
            float a[8], b[8];
#pragma unroll
            for (int i = 0; i < 8; i++) a[i] = As[k][ty * 8 + i];
#pragma unroll
            for (int j = 0; j < 8; j++) b[j] = Bs[k][tx * 8 + j];
#pragma unroll
            for (int i = 0; i < 8; i++)
#pragma unroll
                for (int j = 0; j < 8; j++)
                    acc[i][j] = fmaf(a[i], b[j], acc[i][j]);
        }
        __syncthreads();
    }
#pragma unroll
    for (int i = 0; i < 8; i++) {
        int gm = m0 + ty * 8 + i;
        if (gm >= M) continue;
#pragma unroll
        for (int j = 0; j < 8; j++) {
            int gn = n0 + tx * 8 + j;
            if (gn >= N) continue;
            float v = acc[i][j];
            if (bias) v += bias[gn];
            if (addm) v += addm[(size_t)gm * ldc + gn];
            C[(size_t)gm * ldc + gn] = v;
        }
    }
}

// ---------------- build [W_msg_obj | U_gru_rel[:, :1024]] -------------------
__global__ void wcat_kernel(const float* __restrict__ Wmo, const float* __restrict__ Ugr,
                            float* __restrict__ out) {
    int idx = blockIdx.x * blockDim.x + threadIdx.x;
    if (idx >= HD * 3 * HD) return;
    int k = idx / (3 * HD);
    int j = idx % (3 * HD);
    out[idx] = (j < HD) ? Wmo[k * HD + j] : Ugr[(size_t)k * 3 * HD + (j - HD)];
}

// ---------------- decode rel_inds (handles int64 OR int32 storage) ---------
__global__ __launch_bounds__(1024) void decode_rel_kernel(const void* rel_raw) {
    __shared__ int s_or;
    int tid = threadIdx.x;
    if (tid == 0) s_or = 0;
    __syncthreads();
    const int* v32 = (const int*)rel_raw;
    int acc = 0;
    for (int i = tid; i < (3 * RR) / 2; i += 1024) acc |= v32[2 * i + 1];
    if (acc) atomicOr(&s_or, 1);
    __syncthreads();
    bool is64 = (s_or == 0);
    if (is64) {
        const long long* v = (const long long*)rel_raw;
        for (int r = tid; r < RR; r += 1024) {
            g_s_idx[r] = (int)v[3 * r + 1];
            g_o_idx[r] = (int)v[3 * r + 2];
        }
    } else {
        for (int r = tid; r < RR; r += 1024) {
            g_s_idx[r] = v32[3 * r + 1];
            g_o_idx[r] = v32[3 * r + 2];
        }
    }
}

// ---------------- row softmax over NOC columns ------------------------------
__global__ void softmax_kernel(const float* __restrict__ X, float* __restrict__ Y) {
    int row = blockIdx.x;
    int tid = threadIdx.x;  // 256
    __shared__ float red[256];
    const float* x = X + (size_t)row * NOC_;
    float m = -3.4e38f;
    for (int c = tid; c < NOC_; c += 256) m = fmaxf(m, x[c]);
    red[tid] = m; __syncthreads();
    for (int s = 128; s > 0; s >>= 1) {
        if (tid < s) red[tid] = fmaxf(red[tid], red[tid + s]);
        __syncthreads();
    }
    m = red[0]; __syncthreads();
    float sum = 0.f;
    for (int c = tid; c < NOC_; c += 256) sum += expf(x[c] - m);
    red[tid] = sum; __syncthreads();
    for (int s = 128; s > 0; s >>= 1) {
        if (tid < s) red[tid] += red[tid + s];
        __syncthreads();
    }
    float inv = 1.f / red[0];
    for (int c = tid; c < NOC_; c += 256)
        Y[(size_t)row * NOC_ + c] = expf(x[c] - m) * inv;
}

// ---------------- SUMSO[r] = h_obj[s_r] + h_obj[o_r] ------------------------
__global__ void gather_sum_kernel(const float* __restrict__ Hobj, float* __restrict__ out) {
    int idx = blockIdx.x * blockDim.x + threadIdx.x;
    if (idx >= RR * HD) return;
    int r = idx >> 9;
    int c = idx & 511;
    int s = g_s_idx[r];
    int o = g_o_idx[r];
    out[idx] = Hobj[(size_t)s * HD + c] + Hobj[(size_t)o * HD + c];
}

// ---------------- m_obj scatter (HM has row stride ldhm) --------------------
__global__ __launch_bounds__(512) void scatter_obj_kernel(const float* __restrict__ HM, int ldhm,
                                                          float* __restrict__ MOBJ) {
    int obj = blockIdx.x;
    int c = threadIdx.x;
    int img = obj >> 6;
    int base = img * RPI_;
    __shared__ int ss[RPI_];
    __shared__ int oo[RPI_];
    for (int j = c; j < RPI_; j += 512) {
        ss[j] = g_s_idx[base + j];
        oo[j] = g_o_idx[base + j];
    }
    __syncthreads();
    float acc = 0.f;
    for (int j = 0; j < RPI_; j++) {
        if (ss[j] == obj) acc += HM[(size_t)(base + j) * ldhm + c];
        if (oo[j] == obj) acc += HM[(size_t)(base + j) * ldhm + c];
    }
    MOBJ[(size_t)obj * HD + c] = acc;
}

// ---------------- GRU elementwise: z, r*h (strided inputs) ------------------
__global__ void gru_zr_kernel(const float* __restrict__ XW, int ldxw,
                              const float* __restrict__ HU, int ldhu,
                              const float* __restrict__ b, const float* __restrict__ Hh,
                              float* __restrict__ Z, float* __restrict__ RH, int M) {
    int idx = blockIdx.x * blockDim.x + threadIdx.x;
    if (idx >= M * HD) return;
    int row = idx >> 9;
    int c = idx & 511;
    float z = XW[(size_t)row * ldxw + c] + HU[(size_t)row * ldhu + c] + b[c];
    float r = XW[(size_t)row * ldxw + 512 + c] + HU[(size_t)row * ldhu + 512 + c] + b[512 + c];
    z = 1.f / (1.f + expf(-z));
    r = 1.f / (1.f + expf(-r));
    Z[idx] = z;
    RH[idx] = r * Hh[idx];
}

// ---------------- GRU elementwise: n, h update (in place) -------------------
__global__ void gru_fin_kernel(const float* __restrict__ XW, int ldxw,
                               const float* __restrict__ NU,
                               const float* __restrict__ b, const float* __restrict__ Z,
                               float* __restrict__ Hh, int M) {
    int idx = blockIdx.x * blockDim.x + threadIdx.x;
    if (idx >= M * HD) return;
    int row = idx >> 9;
    int c = idx & 511;
    float n = tanhf(XW[(size_t)row * ldxw + 1024 + c] + NU[idx] + b[1024 + c]);
    float z = Z[idx];
    Hh[idx] = (1.f - z) * Hh[idx] + z * n;
}

// ---------------- NMS: one block per class (1..150) -------------------------
__global__ __launch_bounds__(512) void nms_kernel(const float* __restrict__ SP,
                                                  const float* __restrict__ BOX,
                                                  unsigned char* __restrict__ KEEP) {
    int cls = blockIdx.x + 1;
    int tid = threadIdx.x;
    __shared__ float sc[NN];
    __shared__ int sidx[NN];
    __shared__ float bx[NN][4];
    __shared__ float area[NN];
    __shared__ unsigned char keep[NN];

    sc[tid] = SP[(size_t)tid * NOC_ + cls];
    sidx[tid] = tid;
    __syncthreads();

    for (int k = 2; k <= NN; k <<= 1) {
        for (int j = k >> 1; j > 0; j >>= 1) {
            int ixj = tid ^ j;
            if (ixj > tid) {
                float s1 = sc[tid], s2 = sc[ixj];
                int i1 = sidx[tid], i2 = sidx[ixj];
                bool dir = ((tid & k) == 0);
                bool precBA = (s2 > s1) || (s2 == s1 && i2 < i1);
                if (precBA == dir) {
                    sc[tid] = s2; sc[ixj] = s1;
                    sidx[tid] = i2; sidx[ixj] = i1;
                }
            }
            __syncthreads();
        }
    }

    int oi = sidx[tid];
    float x1 = BOX[((size_t)oi * NOC_ + cls) * 4 + 0];
    float y1 = BOX[((size_t)oi * NOC_ + cls) * 4 + 1];
    float x2 = BOX[((size_t)oi * NOC_ + cls) * 4 + 2];
    float y2 = BOX[((size_t)oi * NOC_ + cls) * 4 + 3];
    bx[tid][0] = x1; bx[tid][1] = y1; bx[tid][2] = x2; bx[tid][3] = y2;
    area[tid] = (x2 - x1) * (y2 - y1);
    keep[tid] = 1;
    __syncthreads();

    for (int i = 0; i < NN - 1; i++) {
        if (tid > i && keep[i] && keep[tid]) {
            float lx = fmaxf(bx[i][0], x1);
            float ly = fmaxf(bx[i][1], y1);
            float rx = fminf(bx[i][2], x2);
            float ry = fminf(bx[i][3], y2);
            float w = fmaxf(rx - lx, 0.f);
            float h = fmaxf(ry - ly, 0.f);
            float inter = w * h;
            float iou = inter / (area[i] + area[tid] - inter + 1e-9f);
            if (iou > IOU_THR_) keep[tid] = 0;
        }
        __syncthreads();
    }
    KEEP[(size_t)(cls - 1) * NN + oi] = keep[tid];
}

// ---------------- obj_preds: argmax over kept class scores ------------------
__global__ void preds_kernel(const float* __restrict__ SP, const unsigned char* __restrict__ KEEP,
                             float* __restrict__ out) {
    int n = blockIdx.x * blockDim.x + threadIdx.x;
    if (n >= NN) return;
    float best = -1.f;
    int bi = 0;
    for (int c = 0; c < 150; c++) {
        float v = KEEP[(size_t)c * NN + n] ? SP[(size_t)n * NOC_ + c + 1] : 0.f;
        if (v > best) { best = v; bi = c; }
    }
    out[n] = (float)(bi + 1);
}

// ---------------- host orchestration ----------------------------------------
static void sgemm(const float* A, int lda, const float* B, int ldb,
                  float* C, int ldc, int M, int N, int K,
                  const float* bias, const float* addm) {
    dim3 g((N + 127) / 128, (M + 127) / 128);
    sgemm_kernel<<<g, 256>>>(A, lda, B, ldb, C, ldc, M, N, K, bias, addm);
}

static void tgemm(const float* A, int lda, const float* B, int ldb,
                  float* C, int ldc, int M, int N, int K, const float* bias) {
    dim3 g(N / 128, M / 128);
    tgemm2_kernel<<<g, 256, TG_SMEM>>>(A, lda, B, ldb, C, ldc, M, N, K, bias);
}

struct Scratch {
    float *OBJ_PROBS, *FO, *HOBJ, *HREL, *SUMSO, *XWR, *HMHU, *MOBJ;
    float *ZR, *RHR, *NUR, *XWO, *HUO, *ZO, *RHO, *NUO, *SP, *WCOMB, *WCAT;
    unsigned char* KEEP;
    bool init = false;
};
static Scratch g_sc;

static void init_scratch() {
    if (g_sc.init) return;
    void* p;
#define GET(sym, fld, T) cudaGetSymbolAddress(&p, sym); g_sc.fld = (T*)p;
    GET(g_obj_probs, OBJ_PROBS, float)
    GET(g_fo, FO, float)
    GET(g_h_obj, HOBJ, float)
    GET(g_h_rel, HREL, float)
    GET(g_sumso, SUMSO, float)
    GET(g_xw_rel, XWR, float)
    GET(g_hmhu, HMHU, float)
    GET(g_m_obj, MOBJ, float)
    GET(g_z_rel, ZR, float)
    GET(g_rh_rel, RHR, float)
    GET(g_nu_rel, NUR, float)
    GET(g_xw_obj, XWO, float)
    GET(g_hu_obj, HUO, float)
    GET(g_z_obj, ZO, float)
    GET(g_rh_obj, RHO, float)
    GET(g_nu_obj, NUO, float)
    GET(g_sp, SP, float)
    GET(g_wcomb, WCOMB, float)
    GET(g_wcat, WCAT, float)
    GET(g_keep, KEEP, unsigned char)
#undef GET
    cudaFuncSetAttribute(tgemm2_kernel, cudaFuncAttributeMaxDynamicSharedMemorySize, TG_SMEM);
    g_sc.init = true;
}

extern "C" void kernel_launch(void* const* d_in, const int* in_sizes, int n_in,
                              void* d_out, int out_size) {
    (void)in_sizes; (void)n_in; (void)out_size;
    init_scratch();

    const float* obj_fmaps  = (const float*)d_in[1];
    const float* obj_logits = (const float*)d_in[2];
    const void*  rel_raw    = d_in[3];
    const float* vr         = (const float*)d_in[4];
    const float* boxes      = (const float*)d_in[5];
    const float* W_obj_proj = (const float*)d_in[6];
    const float* b_obj_proj = (const float*)d_in[7];
    const float* W_rel_proj = (const float*)d_in[8];
    const float* b_rel_proj = (const float*)d_in[9];
    const float* W_emb      = (const float*)d_in[10];
    const float* W_msg_rel  = (const float*)d_in[11];
    const float* W_msg_obj  = (const float*)d_in[12];
    const float* W_gru_obj  = (const float*)d_in[13];
    const float* U_gru_obj  = (const float*)d_in[14];
    const float* b_gru_obj  = (const float*)d_in[15];
    const float* W_gru_rel  = (const float*)d_in[16];
    const float* U_gru_rel  = (const float*)d_in[17];
    const float* b_gru_rel  = (const float*)d_in[18];
    const float* W_cls_rel  = (const float*)d_in[19];
    const float* b_cls_rel  = (const float*)d_in[20];
    const float* W_cls_obj  = (const float*)d_in[21];
    const float* b_cls_obj  = (const float*)d_in[22];

    float* out_obj_logits = (float*)d_out;                 // 512*151
    float* out_preds      = out_obj_logits + NN * NOC_;    // 512
    float* out_rel_logits = out_preds + NN;                // 8192*51

    // 0. decode rel indices; fused weights
    decode_rel_kernel<<<1, 1024>>>(rel_raw);
    // WCOMB = W_msg_rel @ W_gru_rel   [512,1536]
    tgemm(W_msg_rel, HD, W_gru_rel, 3 * HD, g_sc.WCOMB, 3 * HD, HD, 3 * HD, HD, nullptr);
    // WCAT = [W_msg_obj | U_gru_rel[:, :1024]]   [512,1536]
    wcat_kernel<<<(HD * 3 * HD + 255) / 256, 256>>>(W_msg_obj, U_gru_rel, g_sc.WCAT);

    // 1. obj_probs = softmax(obj_logits)
    softmax_kernel<<<NN, 256>>>(obj_logits, g_sc.OBJ_PROBS);

    // 2. fo = obj_fmaps @ W_obj_proj + b
    tgemm(obj_fmaps, OBJD, W_obj_proj, HD, g_sc.FO, HD, NN, HD, OBJD, b_obj_proj);

    // 3. h_obj = fo + obj_probs @ W_emb           (K=151 -> SIMT, addm)
    sgemm(g_sc.OBJ_PROBS, NOC_, W_emb, HD, g_sc.HOBJ, HD, NN, HD, NOC_, nullptr, g_sc.FO);

    // 4. h_rel = vr @ W_rel_proj + b
    tgemm(vr, OBJD, W_rel_proj, HD, g_sc.HREL, HD, RR, HD, OBJD, b_rel_proj);

    const int EW_REL_BLOCKS = (RR * HD + 255) / 256;
    const int EW_OBJ_BLOCKS = (NN * HD + 255) / 256;

    for (int t = 0; t < TSTEPS; t++) {
        // XWR = (h_obj[s]+h_obj[o]) @ (W_msg_rel @ W_gru_rel)
        gather_sum_kernel<<<EW_REL_BLOCKS, 256>>>(g_sc.HOBJ, g_sc.SUMSO);
        tgemm(g_sc.SUMSO, HD, g_sc.WCOMB, 3 * HD, g_sc.XWR, 3 * HD, RR, 3 * HD, HD, nullptr);

        // HMHU = h_rel @ [W_msg_obj | U_gru_rel[:, :1024]]
        tgemm(g_sc.HREL, HD, g_sc.WCAT, 3 * HD, g_sc.HMHU, 3 * HD, RR, 3 * HD, HD, nullptr);
        scatter_obj_kernel<<<NN, 512>>>(g_sc.HMHU, 3 * HD, g_sc.MOBJ);

        // GRU on relations (HU = HMHU cols [512,1536))
        gru_zr_kernel<<<EW_REL_BLOCKS, 256>>>(g_sc.XWR, 3 * HD, g_sc.HMHU + HD, 3 * HD,
                                              b_gru_rel, g_sc.HREL, g_sc.ZR, g_sc.RHR, RR);
        tgemm(g_sc.RHR, HD, U_gru_rel + 2 * HD, 3 * HD, g_sc.NUR, HD, RR, HD, HD, nullptr);
        gru_fin_kernel<<<EW_REL_BLOCKS, 256>>>(g_sc.XWR, 3 * HD, g_sc.NUR, b_gru_rel,
                                               g_sc.ZR, g_sc.HREL, RR);

        // GRU on objects
        tgemm(g_sc.MOBJ, HD, W_gru_obj, 3 * HD, g_sc.XWO, 3 * HD, NN, 3 * HD, HD, nullptr);
        tgemm(g_sc.HOBJ, HD, U_gru_obj, 3 * HD, g_sc.HUO, 2 * HD, NN, 2 * HD, HD, nullptr);
        gru_zr_kernel<<<EW_OBJ_BLOCKS, 256>>>(g_sc.XWO, 3 * HD, g_sc.HUO, 2 * HD,
                                              b_gru_obj, g_sc.HOBJ, g_sc.ZO, g_sc.RHO, NN);
        tgemm(g_sc.RHO, HD, U_gru_obj + 2 * HD, 3 * HD, g_sc.NUO, HD, NN, HD, HD, nullptr);
        gru_fin_kernel<<<EW_OBJ_BLOCKS, 256>>>(g_sc.XWO, 3 * HD, g_sc.NUO, b_gru_obj,
                                               g_sc.ZO, g_sc.HOBJ, NN);
    }

    // classifiers (odd N -> SIMT)
    sgemm(g_sc.HREL, HD, W_cls_rel, NRC_, out_rel_logits, NRC_, RR, NRC_, HD, b_cls_rel, nullptr);
    sgemm(g_sc.HOBJ, HD, W_cls_obj, NOC_, out_obj_logits, NOC_, NN, NOC_, HD, b_cls_obj, nullptr);

    // softmax -> NMS -> preds
    softmax_kernel<<<NN, 256>>>(out_obj_logits, g_sc.SP);
    nms_kernel<<<150, 512>>>(g_sc.SP, boxes, g_sc.KEEP);
    preds_kernel<<<(NN + 255) / 256, 256>>>(g_sc.SP, g_sc.KEEP, out_preds);
}

// round 7
// speedup vs baseline: 1.2540x; 1.0000x over previous
#include <cuda_runtime.h>
#include <cuda_bf16.h>
#include <math.h>
#include <stdint.h>

// ---------------- problem constants ----------------
#define BIMG 8
#define OPI_ 64
#define RPI_ 1024
#define NN 512            // N objects
#define RR 8192           // R relations
#define OBJD 4096
#define HD 512
#define NOC_ 151
#define NRC_ 51
#define TSTEPS 3
#define IOU_THR_ 0.3f

// ---------------- helpers ----------------------------------------------------
__device__ __forceinline__ void split_tf32(float v, uint32_t& hi, uint32_t& lo) {
    uint32_t h;
    asm("cvt.rna.tf32.f32 %0, %1;" : "=r"(h) : "f"(v));
    float l = v - __uint_as_float(h);
    uint32_t lb;
    asm("cvt.rna.tf32.f32 %0, %1;" : "=r"(lb) : "f"(l));
    hi = h; lo = lb;
}
__device__ __forceinline__ void mma_tf32(float* c, const uint32_t* a, const uint32_t* b) {
    asm volatile(
        "mma.sync.aligned.m16n8k8.row.col.f32.tf32.tf32.f32 "
        "{%0,%1,%2,%3},{%4,%5,%6,%7},{%8,%9},{%0,%1,%2,%3};"
        : "+f"(c[0]), "+f"(c[1]), "+f"(c[2]), "+f"(c[3])
        : "r"(a[0]), "r"(a[1]), "r"(a[2]), "r"(a[3]), "r"(b[0]), "r"(b[1]));
}

// ---------------- scratch (device globals; no runtime alloc allowed) -------
__device__ float g_obj_probs[NN * NOC_];
__device__ float g_fo[NN * HD];
__device__ float g_h_obj[NN * HD];
__device__ float g_h_rel[RR * HD];
__device__ float g_sumso[RR * HD];
__device__ float g_xw_rel[RR * 3 * HD];      // XWR [8192,1536]
__device__ float g_hmhu[RR * 3 * HD];        // [HM | HU01] [8192,1536]
__device__ float g_m_obj[NN * HD];
__device__ float g_z_rel[RR * HD];
__device__ float g_rh_rel[RR * HD];
__device__ float g_nu_rel[RR * HD];
__device__ float g_xw_obj[NN * 3 * HD];
__device__ float g_hu_obj[NN * 2 * HD];
__device__ float g_z_obj[NN * HD];
__device__ float g_rh_obj[NN * HD];
__device__ float g_nu_obj[NN * HD];
__device__ float g_sp[NN * NOC_];
__device__ unsigned char g_keep[150 * NN];
__device__ int g_s_idx[RR];
__device__ int g_o_idx[RR];
__device__ float g_wcomb[HD * 3 * HD];       // W_msg_rel @ W_gru_rel  [512,1536]
__device__ float g_wcat[HD * 3 * HD];        // [W_msg_obj | U_gru_rel[:, :1024]]

// ============================================================================
// 3xTF32 tensor-core GEMM, fp32 operands, split at smem staging.
//   C[M,N] = A[M,K] @ B[K,N] (+bias).  M%128==0, N%128==0, K%16==0.
// 128x128x16 tile, 256 threads, 8 warps (2x4), warp tile 64x32.
// Double-buffered reg->smem staging; inner loop = LDS + MMA only.
// ============================================================================
#define AW 2560   // A plane words per buf (128 rows * 20)
#define BW 2176   // B plane words per buf (16 rows * 136)
#define TG_SMEM ((4 * AW + 4 * BW) * 4)   // 75776 bytes

__global__ __launch_bounds__(256, 2) void tgemm2_kernel(
    const float* __restrict__ A, int lda,
    const float* __restrict__ B, int ldb,
    float* __restrict__ C, int ldc,
    int M, int N, int K, const float* __restrict__ bias)
{
    extern __shared__ uint32_t sm[];
    const int tid = threadIdx.x;
    const int lane = tid & 31;
    const int warp = tid >> 5;
    const int wm = warp >> 2;     // 0..1
    const int wn = warp & 3;      // 0..3
    const int lr = lane >> 2;     // 0..7
    const int lc = lane & 3;      // 0..3
    const int m0 = blockIdx.y * 128;
    const int n0 = blockIdx.x * 128;
    const int KT = K / 16;

    const int a_row = tid >> 1;          // 0..127
    const int a_col = (tid & 1) * 8;     // 0 or 8
    const int b_row = tid >> 4;          // 0..15
    const int b_col = (tid & 15) * 8;    // 0..120

    float4 ra0, ra1, rb0, rb1;

    auto load = [&](int kt) {
        const float* ap = A + (size_t)(m0 + a_row) * lda + kt * 16 + a_col;
        ra0 = *(const float4*)ap;
        ra1 = *(const float4*)(ap + 4);
        const float* bp = B + (size_t)(kt * 16 + b_row) * ldb + n0 + b_col;
        rb0 = *(const float4*)bp;
        rb1 = *(const float4*)(bp + 4);
    };

    auto store = [&](int buf) {
        uint32_t* Ah = sm + buf * 2 * AW;
        uint32_t* Al = Ah + AW;
        uint32_t* Bh = sm + 4 * AW + buf * 2 * BW;
        uint32_t* Bl = Bh + BW;
        float av[8] = {ra0.x, ra0.y, ra0.z, ra0.w, ra1.x, ra1.y, ra1.z, ra1.w};
        float bv[8] = {rb0.x, rb0.y, rb0.z, rb0.w, rb1.x, rb1.y, rb1.z, rb1.w};
        uint32_t h[8], l[8];
#pragma unroll
        for (int i = 0; i < 8; i++) split_tf32(av[i], h[i], l[i]);
        int ab = a_row * 20 + a_col;
        *(uint4*)(Ah + ab)     = make_uint4(h[0], h[1], h[2], h[3]);
        *(uint4*)(Ah + ab + 4) = make_uint4(h[4], h[5], h[6], h[7]);
        *(uint4*)(Al + ab)     = make_uint4(l[0], l[1], l[2], l[3]);
        *(uint4*)(Al + ab + 4) = make_uint4(l[4], l[5], l[6], l[7]);
#pragma unroll
        for (int i = 0; i < 8; i++) split_tf32(bv[i], h[i], l[i]);
        int bb = b_row * 136 + b_col;
        *(uint4*)(Bh + bb)     = make_uint4(h[0], h[1], h[2], h[3]);
        *(uint4*)(Bh + bb + 4) = make_uint4(h[4], h[5], h[6], h[7]);
        *(uint4*)(Bl + bb)     = make_uint4(l[0], l[1], l[2], l[3]);
        *(uint4*)(Bl + bb + 4) = make_uint4(l[4], l[5], l[6], l[7]);
    };

    float acc[4][4][4];
#pragma unroll
    for (int i = 0; i < 4; i++)
#pragma unroll
        for (int j = 0; j < 4; j++)
#pragma unroll
            for (int l = 0; l < 4; l++) acc[i][j][l] = 0.f;

    load(0);
    store(0);
    __syncthreads();
    if (KT > 1) load(1);

    for (int kt = 0; kt < KT; kt++) {
        const int cur = kt & 1;
        const uint32_t* Ah = sm + cur * 2 * AW;
        const uint32_t* Al = Ah + AW;
        const uint32_t* Bh = sm + 4 * AW + cur * 2 * BW;
        const uint32_t* Bl = Bh + BW;

#pragma unroll
        for (int kk = 0; kk < 16; kk += 8) {
            uint32_t aH[4][4], aL[4][4], bH[4][2], bL[4][2];
#pragma unroll
            for (int mt = 0; mt < 4; mt++) {
                int r0 = (wm * 64 + mt * 16 + lr) * 20 + kk + lc;
                int r1 = r0 + 8 * 20;
                aH[mt][0] = Ah[r0];     aL[mt][0] = Al[r0];
                aH[mt][1] = Ah[r1];     aL[mt][1] = Al[r1];
                aH[mt][2] = Ah[r0 + 4]; aL[mt][2] = Al[r0 + 4];
                aH[mt][3] = Ah[r1 + 4]; aL[mt][3] = Al[r1 + 4];
            }
#pragma unroll
            for (int nt = 0; nt < 4; nt++) {
                int nc = wn * 32 + nt * 8 + lr;
                int r0 = (kk + lc) * 136 + nc;
                int r1 = r0 + 4 * 136;
                bH[nt][0] = Bh[r0]; bL[nt][0] = Bl[r0];
                bH[nt][1] = Bh[r1]; bL[nt][1] = Bl[r1];
            }
#pragma unroll
            for (int mt = 0; mt < 4; mt++)
#pragma unroll
                for (int nt = 0; nt < 4; nt++) {
                    mma_tf32(acc[mt][nt], aH[mt], bH[nt]);  // hi*hi
                    mma_tf32(acc[mt][nt], aH[mt], bL[nt]);  // hi*lo
                    mma_tf32(acc[mt][nt], aL[mt], bH[nt]);  // lo*hi
                }
        }
        if (kt + 1 < KT) {
            store(cur ^ 1);
            if (kt + 2 < KT) load(kt + 2);
            __syncthreads();
        }
    }

    // epilogue
#pragma unroll
    for (int mt = 0; mt < 4; mt++) {
        int gm0 = m0 + wm * 64 + mt * 16 + lr;
        int gm1 = gm0 + 8;
#pragma unroll
        for (int nt = 0; nt < 4; nt++) {
            int gn = n0 + wn * 32 + nt * 8 + lc * 2;
            float b0 = 0.f, b1 = 0.f;
            if (bias) { b0 = bias[gn]; b1 = bias[gn + 1]; }
            float2 v0 = make_float2(acc[mt][nt][0] + b0, acc[mt][nt][1] + b1);
            float2 v1 = make_float2(acc[mt][nt][2] + b0, acc[mt][nt][3] + b1);
            *(float2*)(C + (size_t)gm0 * ldc + gn) = v0;
            *(float2*)(C + (size_t)gm1 * ldc + gn) = v1;
        }
    }
}

// ---------------- generic fp32 SGEMM (small/odd shapes only) ----------------
__global__ __launch_bounds__(256) void sgemm_kernel(
    const float* __restrict__ A, int lda,
    const float* __restrict__ B, int ldb,
    float* __restrict__ C, int ldc,
    int M, int N, int K,
    const float* __restrict__ bias,
    const float* __restrict__ addm)
{
    __shared__ float As[8][132];
    __shared__ float Bs[8][128];
    const int tid = threadIdx.x;
    const int tx = tid & 15;
    const int ty = tid >> 4;
    const int m0 = blockIdx.y * 128;
    const int n0 = blockIdx.x * 128;

    float acc[8][8];
#pragma unroll
    for (int i = 0; i < 8; i++)
#pragma unroll
        for (int j = 0; j < 8; j++) acc[i][j] = 0.f;

    for (int k0 = 0; k0 < K; k0 += 8) {
#pragma unroll
        for (int l = 0; l < 4; l++) {
            int e = tid + l * 256;
            int r = e >> 3, c = e & 7;
            float v = 0.f;
            int gm = m0 + r, gk = k0 + c;
            if (gm < M && gk < K) v = A[(size_t)gm * lda + gk];
            As[c][r] = v;
        }
#pragma unroll
        for (int l = 0; l < 4; l++) {
            int e = tid + l * 256;
            int r = e >> 7, c = e & 127;
            float v = 0.f;
            int gk = k0 + r, gn = n0 + c;
            if (gk < K && gn < N) v = B[(size_t)gk * ldb + gn];
            Bs[r][c] = v;
        }
        __syncthreads();
#pragma unroll
        for (int k = 0; k < 8; k++) {
            float a[8], b[8];
#pragma unroll
            for (int i = 0; i < 8; i++) a[i] = As[k][ty * 8 + i];
#pragma unroll
            for (int j = 0; j < 8; j++) b[j] = Bs[k][tx * 8 + j];
#pragma unroll
            for (int i = 0; i < 8; i++)
#pragma unroll
                for (int j = 0; j < 8; j++)
                    acc[i][j] = fmaf(a[i], b[j], acc[i][j]);
        }
        __syncthreads();
    }
#pragma unroll
    for (int i = 0; i < 8; i++) {
        int gm = m0 + ty * 8 + i;
        if (gm >= M) continue;
#pragma unroll
        for (int j = 0; j < 8; j++) {
            int gn = n0 + tx * 8 + j;
            if (gn >= N) continue;
            float v = acc[i][j];
            if (bias) v += bias[gn];
            if (addm) v += addm[(size_t)gm * ldc + gn];
            C[(size_t)gm * ldc + gn] = v;
        }
    }
}

// ---------------- build [W_msg_obj | U_gru_rel[:, :1024]] -------------------
__global__ void wcat_kernel(const float* __restrict__ Wmo, const float* __restrict__ Ugr,
                            float* __restrict__ out) {
    int idx = blockIdx.x * blockDim.x + threadIdx.x;
    if (idx >= HD * 3 * HD) return;
    int k = idx / (3 * HD);
    int j = idx % (3 * HD);
    out[idx] = (j < HD) ? Wmo[k * HD + j] : Ugr[(size_t)k * 3 * HD + (j - HD)];
}

// ---------------- decode rel_inds (handles int64 OR int32 storage) ---------
__global__ __launch_bounds__(1024) void decode_rel_kernel(const void* rel_raw) {
    __shared__ int s_or;
    int tid = threadIdx.x;
    if (tid == 0) s_or = 0;
    __syncthreads();
    const int* v32 = (const int*)rel_raw;
    int acc = 0;
    for (int i = tid; i < (3 * RR) / 2; i += 1024) acc |= v32[2 * i + 1];
    if (acc) atomicOr(&s_or, 1);
    __syncthreads();
    bool is64 = (s_or == 0);
    if (is64) {
        const long long* v = (const long long*)rel_raw;
        for (int r = tid; r < RR; r += 1024) {
            g_s_idx[r] = (int)v[3 * r + 1];
            g_o_idx[r] = (int)v[3 * r + 2];
        }
    } else {
        for (int r = tid; r < RR; r += 1024) {
            g_s_idx[r] = v32[3 * r + 1];
            g_o_idx[r] = v32[3 * r + 2];
        }
    }
}

// ---------------- row softmax over NOC columns ------------------------------
__global__ void softmax_kernel(const float* __restrict__ X, float* __restrict__ Y) {
    int row = blockIdx.x;
    int tid = threadIdx.x;  // 256
    __shared__ float red[256];
    const float* x = X + (size_t)row * NOC_;
    float m = -3.4e38f;
    for (int c = tid; c < NOC_; c += 256) m = fmaxf(m, x[c]);
    red[tid] = m; __syncthreads();
    for (int s = 128; s > 0; s >>= 1) {
        if (tid < s) red[tid] = fmaxf(red[tid], red[tid + s]);
        __syncthreads();
    }
    m = red[0]; __syncthreads();
    float sum = 0.f;
    for (int c = tid; c < NOC_; c += 256) sum += expf(x[c] - m);
    red[tid] = sum; __syncthreads();
    for (int s = 128; s > 0; s >>= 1) {
        if (tid < s) red[tid] += red[tid + s];
        __syncthreads();
    }
    float inv = 1.f / red[0];
    for (int c = tid; c < NOC_; c += 256)
        Y[(size_t)row * NOC_ + c] = expf(x[c] - m) * inv;
}

// ---------------- SUMSO[r] = h_obj[s_r] + h_obj[o_r] ------------------------
__global__ void gather_sum_kernel(const float* __restrict__ Hobj, float* __restrict__ out) {
    int idx = blockIdx.x * blockDim.x + threadIdx.x;
    if (idx >= RR * HD) return;
    int r = idx >> 9;
    int c = idx & 511;
    int s = g_s_idx[r];
    int o = g_o_idx[r];
    out[idx] = Hobj[(size_t)s * HD + c] + Hobj[(size_t)o * HD + c];
}

// ---------------- m_obj scatter (HM has row stride ldhm) --------------------
__global__ __launch_bounds__(512) void scatter_obj_kernel(const float* __restrict__ HM, int ldhm,
                                                          float* __restrict__ MOBJ) {
    int obj = blockIdx.x;
    int c = threadIdx.x;
    int img = obj >> 6;
    int base = img * RPI_;
    __shared__ int ss[RPI_];
    __shared__ int oo[RPI_];
    for (int j = c; j < RPI_; j += 512) {
        ss[j] = g_s_idx[base + j];
        oo[j] = g_o_idx[base + j];
    }
    __syncthreads();
    float acc = 0.f;
    for (int j = 0; j < RPI_; j++) {
        if (ss[j] == obj) acc += HM[(size_t)(base + j) * ldhm + c];
        if (oo[j] == obj) acc += HM[(size_t)(base + j) * ldhm + c];
    }
    MOBJ[(size_t)obj * HD + c] = acc;
}

// ---------------- GRU elementwise: z, r*h (strided inputs) ------------------
__global__ void gru_zr_kernel(const float* __restrict__ XW, int ldxw,
                              const float* __restrict__ HU, int ldhu,
                              const float* __restrict__ b, const float* __restrict__ Hh,
                              float* __restrict__ Z, float* __restrict__ RH, int M) {
    int idx = blockIdx.x * blockDim.x + threadIdx.x;
    if (idx >= M * HD) return;
    int row = idx >> 9;
    int c = idx & 511;
    float z = XW[(size_t)row * ldxw + c] + HU[(size_t)row * ldhu + c] + b[c];
    float r = XW[(size_t)row * ldxw + 512 + c] + HU[(size_t)row * ldhu + 512 + c] + b[512 + c];
    z = 1.f / (1.f + expf(-z));
    r = 1.f / (1.f + expf(-r));
    Z[idx] = z;
    RH[idx] = r * Hh[idx];
}

// ---------------- GRU elementwise: n, h update (in place) -------------------
__global__ void gru_fin_kernel(const float* __restrict__ XW, int ldxw,
                               const float* __restrict__ NU,
                               const float* __restrict__ b, const float* __restrict__ Z,
                               float* __restrict__ Hh, int M) {
    int idx = blockIdx.x * blockDim.x + threadIdx.x;
    if (idx >= M * HD) return;
    int row = idx >> 9;
    int c = idx & 511;
    float n = tanhf(XW[(size_t)row * ldxw + 1024 + c] + NU[idx] + b[1024 + c]);
    float z = Z[idx];
    Hh[idx] = (1.f - z) * Hh[idx] + z * n;
}

// ---------------- NMS: one block per class (1..150) -------------------------
__global__ __launch_bounds__(512) void nms_kernel(const float* __restrict__ SP,
                                                  const float* __restrict__ BOX,
                                                  unsigned char* __restrict__ KEEP) {
    int cls = blockIdx.x + 1;
    int tid = threadIdx.x;
    __shared__ float sc[NN];
    __shared__ int sidx[NN];
    __shared__ float bx[NN][4];
    __shared__ float area[NN];
    __shared__ unsigned char keep[NN];

    sc[tid] = SP[(size_t)tid * NOC_ + cls];
    sidx[tid] = tid;
    __syncthreads();

    for (int k = 2; k <= NN; k <<= 1) {
        for (int j = k >> 1; j > 0; j >>= 1) {
            int ixj = tid ^ j;
            if (ixj > tid) {
                float s1 = sc[tid], s2 = sc[ixj];
                int i1 = sidx[tid], i2 = sidx[ixj];
                bool dir = ((tid & k) == 0);
                bool precBA = (s2 > s1) || (s2 == s1 && i2 < i1);
                if (precBA == dir) {
                    sc[tid] = s2; sc[ixj] = s1;
                    sidx[tid] = i2; sidx[ixj] = i1;
                }
            }
            __syncthreads();
        }
    }

    int oi = sidx[tid];
    float x1 = BOX[((size_t)oi * NOC_ + cls) * 4 + 0];
    float y1 = BOX[((size_t)oi * NOC_ + cls) * 4 + 1];
    float x2 = BOX[((size_t)oi * NOC_ + cls) * 4 + 2];
    float y2 = BOX[((size_t)oi * NOC_ + cls) * 4 + 3];
    bx[tid][0] = x1; bx[tid][1] = y1; bx[tid][2] = x2; bx[tid][3] = y2;
    area[tid] = (x2 - x1) * (y2 - y1);
    keep[tid] = 1;
    __syncthreads();

    for (int i = 0; i < NN - 1; i++) {
        if (tid > i && keep[i] && keep[tid]) {
            float lx = fmaxf(bx[i][0], x1);
            float ly = fmaxf(bx[i][1], y1);
            float rx = fminf(bx[i][2], x2);
            float ry = fminf(bx[i][3], y2);
            float w = fmaxf(rx - lx, 0.f);
            float h = fmaxf(ry - ly, 0.f);
            float inter = w * h;
            float iou = inter / (area[i] + area[tid] - inter + 1e-9f);
            if (iou > IOU_THR_) keep[tid] = 0;
        }
        __syncthreads();
    }
    KEEP[(size_t)(cls - 1) * NN + oi] = keep[tid];
}

// ---------------- obj_preds: argmax over kept class scores ------------------
__global__ void preds_kernel(const float* __restrict__ SP, const unsigned char* __restrict__ KEEP,
                             float* __restrict__ out) {
    int n = blockIdx.x * blockDim.x + threadIdx.x;
    if (n >= NN) return;
    float best = -1.f;
    int bi = 0;
    for (int c = 0; c < 150; c++) {
        float v = KEEP[(size_t)c * NN + n] ? SP[(size_t)n * NOC_ + c + 1] : 0.f;
        if (v > best) { best = v; bi = c; }
    }
    out[n] = (float)(bi + 1);
}

// ---------------- host orchestration ----------------------------------------
static void sgemm(const float* A, int lda, const float* B, int ldb,
                  float* C, int ldc, int M, int N, int K,
                  const float* bias, const float* addm) {
    dim3 g((N + 127) / 128, (M + 127) / 128);
    sgemm_kernel<<<g, 256>>>(A, lda, B, ldb, C, ldc, M, N, K, bias, addm);
}

static void tgemm(const float* A, int lda, const float* B, int ldb,
                  float* C, int ldc, int M, int N, int K, const float* bias) {
    dim3 g(N / 128, M / 128);
    tgemm2_kernel<<<g, 256, TG_SMEM>>>(A, lda, B, ldb, C, ldc, M, N, K, bias);
}

struct Scratch {
    float *OBJ_PROBS, *FO, *HOBJ, *HREL, *SUMSO, *XWR, *HMHU, *MOBJ;
    float *ZR, *RHR, *NUR, *XWO, *HUO, *ZO, *RHO, *NUO, *SP, *WCOMB, *WCAT;
    unsigned char* KEEP;
    bool init = false;
};
static Scratch g_sc;

static void init_scratch() {
    if (g_sc.init) return;
    void* p;
#define GET(sym, fld, T) cudaGetSymbolAddress(&p, sym); g_sc.fld = (T*)p;
    GET(g_obj_probs, OBJ_PROBS, float)
    GET(g_fo, FO, float)
    GET(g_h_obj, HOBJ, float)
    GET(g_h_rel, HREL, float)
    GET(g_sumso, SUMSO, float)
    GET(g_xw_rel, XWR, float)
    GET(g_hmhu, HMHU, float)
    GET(g_m_obj, MOBJ, float)
    GET(g_z_rel, ZR, float)
    GET(g_rh_rel, RHR, float)
    GET(g_nu_rel, NUR, float)
    GET(g_xw_obj, XWO, float)
    GET(g_hu_obj, HUO, float)
    GET(g_z_obj, ZO, float)
    GET(g_rh_obj, RHO, float)
    GET(g_nu_obj, NUO, float)
    GET(g_sp, SP, float)
    GET(g_wcomb, WCOMB, float)
    GET(g_wcat, WCAT, float)
    GET(g_keep, KEEP, unsigned char)
#undef GET
    cudaFuncSetAttribute(tgemm2_kernel, cudaFuncAttributeMaxDynamicSharedMemorySize, TG_SMEM);
    g_sc.init = true;
}

extern "C" void kernel_launch(void* const* d_in, const int* in_sizes, int n_in,
                              void* d_out, int out_size) {
    (void)in_sizes; (void)n_in; (void)out_size;
    init_scratch();

    const float* obj_fmaps  = (const float*)d_in[1];
    const float* obj_logits = (const float*)d_in[2];
    const void*  rel_raw    = d_in[3];
    const float* vr         = (const float*)d_in[4];
    const float* boxes      = (const float*)d_in[5];
    const float* W_obj_proj = (const float*)d_in[6];
    const float* b_obj_proj = (const float*)d_in[7];
    const float* W_rel_proj = (const float*)d_in[8];
    const float* b_rel_proj = (const float*)d_in[9];
    const float* W_emb      = (const float*)d_in[10];
    const float* W_msg_rel  = (const float*)d_in[11];
    const float* W_msg_obj  = (const float*)d_in[12];
    const float* W_gru_obj  = (const float*)d_in[13];
    const float* U_gru_obj  = (const float*)d_in[14];
    const float* b_gru_obj  = (const float*)d_in[15];
    const float* W_gru_rel  = (const float*)d_in[16];
    const float* U_gru_rel  = (const float*)d_in[17];
    const float* b_gru_rel  = (const float*)d_in[18];
    const float* W_cls_rel  = (const float*)d_in[19];
    const float* b_cls_rel  = (const float*)d_in[20];
    const float* W_cls_obj  = (const float*)d_in[21];
    const float* b_cls_obj  = (const float*)d_in[22];

    float* out_obj_logits = (float*)d_out;                 // 512*151
    float* out_preds      = out_obj_logits + NN * NOC_;    // 512
    float* out_rel_logits = out_preds + NN;                // 8192*51

    // 0. decode rel indices; fused weights
    decode_rel_kernel<<<1, 1024>>>(rel_raw);
    // WCOMB = W_msg_rel @ W_gru_rel   [512,1536]
    tgemm(W_msg_rel, HD, W_gru_rel, 3 * HD, g_sc.WCOMB, 3 * HD, HD, 3 * HD, HD, nullptr);
    // WCAT = [W_msg_obj | U_gru_rel[:, :1024]]   [512,1536]
    wcat_kernel<<<(HD * 3 * HD + 255) / 256, 256>>>(W_msg_obj, U_gru_rel, g_sc.WCAT);

    // 1. obj_probs = softmax(obj_logits)
    softmax_kernel<<<NN, 256>>>(obj_logits, g_sc.OBJ_PROBS);

    // 2. fo = obj_fmaps @ W_obj_proj + b
    tgemm(obj_fmaps, OBJD, W_obj_proj, HD, g_sc.FO, HD, NN, HD, OBJD, b_obj_proj);

    // 3. h_obj = fo + obj_probs @ W_emb           (K=151 -> SIMT, addm)
    sgemm(g_sc.OBJ_PROBS, NOC_, W_emb, HD, g_sc.HOBJ, HD, NN, HD, NOC_, nullptr, g_sc.FO);

    // 4. h_rel = vr @ W_rel_proj + b
    tgemm(vr, OBJD, W_rel_proj, HD, g_sc.HREL, HD, RR, HD, OBJD, b_rel_proj);

    const int EW_REL_BLOCKS = (RR * HD + 255) / 256;
    const int EW_OBJ_BLOCKS = (NN * HD + 255) / 256;

    for (int t = 0; t < TSTEPS; t++) {
        // XWR = (h_obj[s]+h_obj[o]) @ (W_msg_rel @ W_gru_rel)
        gather_sum_kernel<<<EW_REL_BLOCKS, 256>>>(g_sc.HOBJ, g_sc.SUMSO);
        tgemm(g_sc.SUMSO, HD, g_sc.WCOMB, 3 * HD, g_sc.XWR, 3 * HD, RR, 3 * HD, HD, nullptr);

        // HMHU = h_rel @ [W_msg_obj | U_gru_rel[:, :1024]]
        tgemm(g_sc.HREL, HD, g_sc.WCAT, 3 * HD, g_sc.HMHU, 3 * HD, RR, 3 * HD, HD, nullptr);
        scatter_obj_kernel<<<NN, 512>>>(g_sc.HMHU, 3 * HD, g_sc.MOBJ);

        // GRU on relations (HU = HMHU cols [512,1536))
        gru_zr_kernel<<<EW_REL_BLOCKS, 256>>>(g_sc.XWR, 3 * HD, g_sc.HMHU + HD, 3 * HD,
                                              b_gru_rel, g_sc.HREL, g_sc.ZR, g_sc.RHR, RR);
        tgemm(g_sc.RHR, HD, U_gru_rel + 2 * HD, 3 * HD, g_sc.NUR, HD, RR, HD, HD, nullptr);
        gru_fin_kernel<<<EW_REL_BLOCKS, 256>>>(g_sc.XWR, 3 * HD, g_sc.NUR, b_gru_rel,
                                               g_sc.ZR, g_sc.HREL, RR);

        // GRU on objects
        tgemm(g_sc.MOBJ, HD, W_gru_obj, 3 * HD, g_sc.XWO, 3 * HD, NN, 3 * HD, HD, nullptr);
        tgemm(g_sc.HOBJ, HD, U_gru_obj, 3 * HD, g_sc.HUO, 2 * HD, NN, 2 * HD, HD, nullptr);
        gru_zr_kernel<<<EW_OBJ_BLOCKS, 256>>>(g_sc.XWO, 3 * HD, g_sc.HUO, 2 * HD,
                                              b_gru_obj, g_sc.HOBJ, g_sc.ZO, g_sc.RHO, NN);
        tgemm(g_sc.RHO, HD, U_gru_obj + 2 * HD, 3 * HD, g_sc.NUO, HD, NN, HD, HD, nullptr);
        gru_fin_kernel<<<EW_OBJ_BLOCKS, 256>>>(g_sc.XWO, 3 * HD, g_sc.NUO, b_gru_obj,
                                               g_sc.ZO, g_sc.HOBJ, NN);
    }

    // classifiers (odd N -> SIMT)
    sgemm(g_sc.HREL, HD, W_cls_rel, NRC_, out_rel_logits, NRC_, RR, NRC_, HD, b_cls_rel, nullptr);
    sgemm(g_sc.HOBJ, HD, W_cls_obj, NOC_, out_obj_logits, NOC_, NN, NOC_, HD, b_cls_obj, nullptr);

    // softmax -> NMS -> preds
    softmax_kernel<<<NN, 256>>>(out_obj_logits, g_sc.SP);
    nms_kernel<<<150, 512>>>(g_sc.SP, boxes, g_sc.KEEP);
    preds_kernel<<<(NN + 255) / 256, 256>>>(g_sc.SP, g_sc.KEEP, out_preds);
}

// round 8
// speedup vs baseline: 1.7316x; 1.3808x over previous
#include <cuda_runtime.h>
#include <cuda_bf16.h>
#include <cuda_fp16.h>
#include <math.h>
#include <stdint.h>

// ---------------- problem constants ----------------
#define BIMG 8
#define OPI_ 64
#define RPI_ 1024
#define NN 512
#define RR 8192
#define OBJD 4096
#define HD 512
#define NOC_ 151
#define NRC_ 51
#define TSTEPS 3
#define IOU_THR_ 0.3f

// ---------------- helpers ----------------------------------------------------
__device__ __forceinline__ void split_h(float v, __half& hi, __half& lo) {
    hi = __float2half_rn(v);
    lo = __float2half_rn(v - __half2float(hi));
}
__device__ __forceinline__ void mma_f16(float* c, const uint32_t* a, const uint32_t* b) {
    asm volatile(
        "mma.sync.aligned.m16n8k16.row.col.f32.f16.f16.f32 "
        "{%0,%1,%2,%3},{%4,%5,%6,%7},{%8,%9},{%0,%1,%2,%3};"
        : "+f"(c[0]), "+f"(c[1]), "+f"(c[2]), "+f"(c[3])
        : "r"(a[0]), "r"(a[1]), "r"(a[2]), "r"(a[3]), "r"(b[0]), "r"(b[1]));
}
__device__ __forceinline__ void cp16(uint32_t dst, const void* src) {
    asm volatile("cp.async.cg.shared.global [%0], [%1], 16;" :: "r"(dst), "l"(src));
}

// ---------------- f32 scratch ------------------------------------------------
__device__ float g_obj_probs[NN * NOC_];
__device__ float g_fo[NN * HD];
__device__ float g_h_obj[NN * HD];
__device__ float g_h_rel[RR * HD];
__device__ float g_xw_rel[RR * 3 * HD];
__device__ float g_hmhu[RR * 3 * HD];
__device__ float g_z_rel[RR * HD];
__device__ float g_nu_rel[RR * HD];
__device__ float g_xw_obj[NN * 3 * HD];
__device__ float g_hu_obj[NN * 2 * HD];   // written strided into g_xw? no: separate buf via hgemm ldc
__device__ float g_z_obj[NN * HD];
__device__ float g_nu_obj[NN * HD];
__device__ float g_sp[NN * NOC_];
__device__ float g_wcomb[HD * 3 * HD];
__device__ unsigned char g_keep[150 * NN];
__device__ int g_s_idx[RR];
__device__ int g_o_idx[RR];

// ---------------- fp16 plane scratch -----------------------------------------
__device__ __half g_Pa_h[RR * OBJD], g_Pa_l[RR * OBJD];     // big activation (vr / obj_fmaps)
__device__ __half g_Ps_h[RR * HD],  g_Ps_l[RR * HD];        // SUMSO, then RHR
__device__ __half g_Ph_h[RR * HD],  g_Ph_l[RR * HD];        // HREL planes
__device__ __half g_Po1_h[NN * HD], g_Po1_l[NN * HD];       // MOBJ
__device__ __half g_Po2_h[NN * HD], g_Po2_l[NN * HD];       // HOBJ
__device__ __half g_Po3_h[NN * HD], g_Po3_l[NN * HD];       // RHO
// weight planes, transposed [N,K]
__device__ __half g_Wop_h[HD * OBJD], g_Wop_l[HD * OBJD];
__device__ __half g_Wrp_h[HD * OBJD], g_Wrp_l[HD * OBJD];
__device__ __half g_Wcb_h[3 * HD * HD], g_Wcb_l[3 * HD * HD];
__device__ __half g_Wmo_h[HD * HD],   g_Wmo_l[HD * HD];
__device__ __half g_Ugr_h[3 * HD * HD], g_Ugr_l[3 * HD * HD];
__device__ __half g_Wgo_h[3 * HD * HD], g_Wgo_l[3 * HD * HD];
__device__ __half g_Ugo_h[3 * HD * HD], g_Ugo_l[3 * HD * HD];

// ============================================================================
// fp16 3-pass GEMM: C[M,N] = A[M,K] @ B^T (+bias), A planes [M,K], B planes
// [N,K], hi/lo fp16. 128x128x32 tile, 256 thr, 8 warps (2x4), warp 64x32.
// cp.async double buffer. Optional fp16 plane epilogue output.
// ============================================================================
#define HROW 20                          // smem row stride in words (16 used + 4 pad)
#define HPLW (128 * HROW)                // plane words = 2560
#define HSTW (4 * HPLW)                  // stage words = 10240
#define HG_SMEM (2 * HSTW * 4)           // 81920 bytes

__global__ __launch_bounds__(256, 2) void hgemm_kernel(
    const __half* __restrict__ Ah, const __half* __restrict__ Al,
    const __half* __restrict__ Bh, const __half* __restrict__ Bl,
    float* __restrict__ C, int ldc,
    int M, int N, int K, const float* __restrict__ bias,
    __half* __restrict__ Ch, __half* __restrict__ Cl)
{
    extern __shared__ uint32_t sm[];
    const int tid = threadIdx.x;
    const int lane = tid & 31;
    const int warp = tid >> 5;
    const int wm = warp >> 2;
    const int wn = warp & 3;
    const int lr = lane >> 2;
    const int lc = lane & 3;
    const int m0 = blockIdx.y * 128;
    const int n0 = blockIdx.x * 128;
    const int KT = K / 32;

    const uint32_t sbase = (uint32_t)__cvta_generic_to_shared(sm);

    auto load_stage = [&](int kt, int buf) {
        const int k0 = kt * 32;
        uint32_t sb = sbase + (uint32_t)(buf * HSTW * 4);
#pragma unroll
        for (int i = 0; i < 2; i++) {
            int cid = tid * 2 + i;
            int row = cid >> 2, ch = cid & 3;
            uint32_t d = sb + (uint32_t)((row * HROW + ch * 4) * 4);
            size_t src = (size_t)(m0 + row) * K + k0 + ch * 8;
            cp16(d, Ah + src);
            cp16(d + HPLW * 4, Al + src);
        }
#pragma unroll
        for (int i = 0; i < 2; i++) {
            int cid = tid * 2 + i;
            int row = cid >> 2, ch = cid & 3;
            uint32_t d = sb + (uint32_t)((2 * HPLW + row * HROW + ch * 4) * 4);
            size_t src = (size_t)(n0 + row) * K + k0 + ch * 8;
            cp16(d, Bh + src);
            cp16(d + HPLW * 4, Bl + src);
        }
        asm volatile("cp.async.commit_group;");
    };

    float acc[4][4][4];
#pragma unroll
    for (int i = 0; i < 4; i++)
#pragma unroll
        for (int j = 0; j < 4; j++)
#pragma unroll
            for (int l = 0; l < 4; l++) acc[i][j][l] = 0.f;

    load_stage(0, 0);
    if (KT > 1) load_stage(1, 1);
    asm volatile("cp.async.wait_group 1;");
    __syncthreads();

    for (int kt = 0; kt < KT; kt++) {
        const int cur = kt & 1;
        const uint32_t* sAh = sm + cur * HSTW;
        const uint32_t* sAl = sAh + HPLW;
        const uint32_t* sBh = sAh + 2 * HPLW;
        const uint32_t* sBl = sAh + 3 * HPLW;

#pragma unroll
        for (int wc = 0; wc < 16; wc += 8) {   // two k16 chunks per stage
            uint32_t aH[4][4], aL[4][4], bH[4][2], bL[4][2];
#pragma unroll
            for (int mt = 0; mt < 4; mt++) {
                int r0 = (wm * 64 + mt * 16 + lr) * HROW + wc + lc;
                int r1 = r0 + 8 * HROW;
                aH[mt][0] = sAh[r0];     aL[mt][0] = sAl[r0];
                aH[mt][1] = sAh[r1];     aL[mt][1] = sAl[r1];
                aH[mt][2] = sAh[r0 + 4]; aL[mt][2] = sAl[r0 + 4];
                aH[mt][3] = sAh[r1 + 4]; aL[mt][3] = sAl[r1 + 4];
            }
#pragma unroll
            for (int nt = 0; nt < 4; nt++) {
                int r = (wn * 32 + nt * 8 + lr) * HROW + wc + lc;
                bH[nt][0] = sBh[r];     bL[nt][0] = sBl[r];
                bH[nt][1] = sBh[r + 4]; bL[nt][1] = sBl[r + 4];
            }
#pragma unroll
            for (int mt = 0; mt < 4; mt++)
#pragma unroll
                for (int nt = 0; nt < 4; nt++) {
                    mma_f16(acc[mt][nt], aH[mt], bH[nt]);  // hi*hi
                    mma_f16(acc[mt][nt], aH[mt], bL[nt]);  // hi*lo
                    mma_f16(acc[mt][nt], aL[mt], bH[nt]);  // lo*hi
                }
        }
        __syncthreads();
        if (kt + 2 < KT) {
            load_stage(kt + 2, cur);
            asm volatile("cp.async.wait_group 1;");
        } else if (kt + 1 < KT) {
            asm volatile("cp.async.wait_group 0;");
        }
        __syncthreads();
    }

    // epilogue
#pragma unroll
    for (int mt = 0; mt < 4; mt++) {
        int gm0 = m0 + wm * 64 + mt * 16 + lr;
        int gm1 = gm0 + 8;
#pragma unroll
        for (int nt = 0; nt < 4; nt++) {
            int gn = n0 + wn * 32 + nt * 8 + lc * 2;
            float b0 = 0.f, b1 = 0.f;
            if (bias) { b0 = bias[gn]; b1 = bias[gn + 1]; }
            float2 v0 = make_float2(acc[mt][nt][0] + b0, acc[mt][nt][1] + b1);
            float2 v1 = make_float2(acc[mt][nt][2] + b0, acc[mt][nt][3] + b1);
            *(float2*)(C + (size_t)gm0 * ldc + gn) = v0;
            *(float2*)(C + (size_t)gm1 * ldc + gn) = v1;
            if (Ch) {
                __half hx, lx, hy, ly;
                split_h(v0.x, hx, lx); split_h(v0.y, hy, ly);
                *(__half2*)(Ch + (size_t)gm0 * ldc + gn) = __halves2half2(hx, hy);
                *(__half2*)(Cl + (size_t)gm0 * ldc + gn) = __halves2half2(lx, ly);
                split_h(v1.x, hx, lx); split_h(v1.y, hy, ly);
                *(__half2*)(Ch + (size_t)gm1 * ldc + gn) = __halves2half2(hx, hy);
                *(__half2*)(Cl + (size_t)gm1 * ldc + gn) = __halves2half2(lx, ly);
            }
        }
    }
}

// ---------------- split kernels ---------------------------------------------
__global__ void asplit_kernel(const float2* __restrict__ in,
                              __half2* __restrict__ hi, __half2* __restrict__ lo, int n2) {
    int i = blockIdx.x * blockDim.x + threadIdx.x;
    if (i >= n2) return;
    float2 v = in[i];
    __half hx, lx, hy, ly;
    split_h(v.x, hx, lx);
    split_h(v.y, hy, ly);
    hi[i] = __halves2half2(hx, hy);
    lo[i] = __halves2half2(lx, ly);
}

// W [K,N] f32 -> planes [N,K] fp16
__global__ void wsplit_kernel(const float* __restrict__ W,
                              __half* __restrict__ Th, __half* __restrict__ Tl,
                              int K, int N) {
    __shared__ float t[32][33];
    int kb = blockIdx.y * 32, nb = blockIdx.x * 32;
    int tx = threadIdx.x, ty = threadIdx.y;  // 32 x 8
#pragma unroll
    for (int i = 0; i < 32; i += 8)
        t[ty + i][tx] = W[(size_t)(kb + ty + i) * N + nb + tx];
    __syncthreads();
#pragma unroll
    for (int i = 0; i < 32; i += 8) {
        int n = nb + ty + i, k = kb + tx;
        __half h, l;
        split_h(t[tx][ty + i], h, l);
        Th[(size_t)n * K + k] = h;
        Tl[(size_t)n * K + k] = l;
    }
}

// ---------------- generic fp32 SGEMM (small/odd shapes) ---------------------
__global__ __launch_bounds__(256) void sgemm_kernel(
    const float* __restrict__ A, int lda,
    const float* __restrict__ B, int ldb,
    float* __restrict__ C, int ldc,
    int M, int N, int K,
    const float* __restrict__ bias,
    const float* __restrict__ addm)
{
    __shared__ float As[8][132];
    __shared__ float Bs[8][128];
    const int tid = threadIdx.x;
    const int tx = tid & 15;
    const int ty = tid >> 4;
    const int m0 = blockIdx.y * 128;
    const int n0 = blockIdx.x * 128;

    float acc[8][8];
#pragma unroll
    for (int i = 0; i < 8; i++)
#pragma unroll
        for (int j = 0; j < 8; j++) acc[i][j] = 0.f;

    for (int k0 = 0; k0 < K; k0 += 8) {
#pragma unroll
        for (int l = 0; l < 4; l++) {
            int e = tid + l * 256;
            int r = e >> 3, c = e & 7;
            float v = 0.f;
            int gm = m0 + r, gk = k0 + c;
            if (gm < M && gk < K) v = A[(size_t)gm * lda + gk];
            As[c][r] = v;
        }
#pragma unroll
        for (int l = 0; l < 4; l++) {
            int e = tid + l * 256;
            int r = e >> 7, c = e & 127;
            float v = 0.f;
            int gk = k0 + r, gn = n0 + c;
            if (gk < K && gn < N) v = B[(size_t)gk * ldb + gn];
            Bs[r][c] = v;
        }
        __syncthreads();
#pragma unroll
        for (int k = 0; k < 8; k++) {
            float a[8], b[8];
#pragma unroll
            for (int i = 0; i < 8; i++) a[i] = As[k][ty * 8 + i];
#pragma unroll
            for (int j = 0; j < 8; j++) b[j] = Bs[k][tx * 8 + j];
#pragma unroll
            for (int i = 0; i < 8; i++)
#pragma unroll
                for (int j = 0; j < 8; j++)
                    acc[i][j] = fmaf(a[i], b[j], acc[i][j]);
        }
        __syncthreads();
    }
#pragma unroll
    for (int i = 0; i < 8; i++) {
        int gm = m0 + ty * 8 + i;
        if (gm >= M) continue;
#pragma unroll
        for (int j = 0; j < 8; j++) {
            int gn = n0 + tx * 8 + j;
            if (gn >= N) continue;
            float v = acc[i][j];
            if (bias) v += bias[gn];
            if (addm) v += addm[(size_t)gm * ldc + gn];
            C[(size_t)gm * ldc + gn] = v;
        }
    }
}

// ---------------- decode rel_inds --------------------------------------------
__global__ __launch_bounds__(1024) void decode_rel_kernel(const void* rel_raw) {
    __shared__ int s_or;
    int tid = threadIdx.x;
    if (tid == 0) s_or = 0;
    __syncthreads();
    const int* v32 = (const int*)rel_raw;
    int acc = 0;
    for (int i = tid; i < (3 * RR) / 2; i += 1024) acc |= v32[2 * i + 1];
    if (acc) atomicOr(&s_or, 1);
    __syncthreads();
    bool is64 = (s_or == 0);
    if (is64) {
        const long long* v = (const long long*)rel_raw;
        for (int r = tid; r < RR; r += 1024) {
            g_s_idx[r] = (int)v[3 * r + 1];
            g_o_idx[r] = (int)v[3 * r + 2];
        }
    } else {
        for (int r = tid; r < RR; r += 1024) {
            g_s_idx[r] = v32[3 * r + 1];
            g_o_idx[r] = v32[3 * r + 2];
        }
    }
}

// ---------------- row softmax -------------------------------------------------
__global__ void softmax_kernel(const float* __restrict__ X, float* __restrict__ Y) {
    int row = blockIdx.x;
    int tid = threadIdx.x;
    __shared__ float red[256];
    const float* x = X + (size_t)row * NOC_;
    float m = -3.4e38f;
    for (int c = tid; c < NOC_; c += 256) m = fmaxf(m, x[c]);
    red[tid] = m; __syncthreads();
    for (int s = 128; s > 0; s >>= 1) {
        if (tid < s) red[tid] = fmaxf(red[tid], red[tid + s]);
        __syncthreads();
    }
    m = red[0]; __syncthreads();
    float sum = 0.f;
    for (int c = tid; c < NOC_; c += 256) sum += expf(x[c] - m);
    red[tid] = sum; __syncthreads();
    for (int s = 128; s > 0; s >>= 1) {
        if (tid < s) red[tid] += red[tid + s];
        __syncthreads();
    }
    float inv = 1.f / red[0];
    for (int c = tid; c < NOC_; c += 256)
        Y[(size_t)row * NOC_ + c] = expf(x[c] - m) * inv;
}

// ---------------- gather + split: SUMSO planes --------------------------------
__global__ void gather_split_kernel(const float* __restrict__ Hobj,
                                    __half* __restrict__ Sh, __half* __restrict__ Sl) {
    int idx = blockIdx.x * blockDim.x + threadIdx.x;
    if (idx >= RR * HD) return;
    int r = idx >> 9;
    int c = idx & 511;
    float v = Hobj[(size_t)g_s_idx[r] * HD + c] + Hobj[(size_t)g_o_idx[r] * HD + c];
    __half h, l;
    split_h(v, h, l);
    Sh[idx] = h; Sl[idx] = l;
}

// ---------------- m_obj scatter -> planes -------------------------------------
__global__ __launch_bounds__(512) void scatter_obj_kernel(const float* __restrict__ HM, int ldhm,
                                                          __half* __restrict__ Mh,
                                                          __half* __restrict__ Ml) {
    int obj = blockIdx.x;
    int c = threadIdx.x;
    int img = obj >> 6;
    int base = img * RPI_;
    __shared__ int ss[RPI_];
    __shared__ int oo[RPI_];
    for (int j = c; j < RPI_; j += 512) {
        ss[j] = g_s_idx[base + j];
        oo[j] = g_o_idx[base + j];
    }
    __syncthreads();
    float acc = 0.f;
    for (int j = 0; j < RPI_; j++) {
        if (ss[j] == obj) acc += HM[(size_t)(base + j) * ldhm + c];
        if (oo[j] == obj) acc += HM[(size_t)(base + j) * ldhm + c];
    }
    __half h, l;
    split_h(acc, h, l);
    Mh[(size_t)obj * HD + c] = h;
    Ml[(size_t)obj * HD + c] = l;
}

// ---------------- GRU z, r*h -> planes ----------------------------------------
__global__ void gru_zr_kernel(const float* __restrict__ XW, int ldxw,
                              const float* __restrict__ HU, int ldhu,
                              const float* __restrict__ b, const float* __restrict__ Hh,
                              float* __restrict__ Z,
                              __half* __restrict__ RHh, __half* __restrict__ RHl, int M) {
    int idx = blockIdx.x * blockDim.x + threadIdx.x;
    if (idx >= M * HD) return;
    int row = idx >> 9;
    int c = idx & 511;
    float z = XW[(size_t)row * ldxw + c] + HU[(size_t)row * ldhu + c] + b[c];
    float r = XW[(size_t)row * ldxw + 512 + c] + HU[(size_t)row * ldhu + 512 + c] + b[512 + c];
    z = 1.f / (1.f + expf(-z));
    r = 1.f / (1.f + expf(-r));
    Z[idx] = z;
    __half h, l;
    split_h(r * Hh[idx], h, l);
    RHh[idx] = h; RHl[idx] = l;
}

// ---------------- GRU n + h update (+ optional planes) ------------------------
__global__ void gru_fin_kernel(const float* __restrict__ XW, int ldxw,
                               const float* __restrict__ NU,
                               const float* __restrict__ b, const float* __restrict__ Z,
                               float* __restrict__ Hh,
                               __half* __restrict__ Ph, __half* __restrict__ Pl, int M) {
    int idx = blockIdx.x * blockDim.x + threadIdx.x;
    if (idx >= M * HD) return;
    int row = idx >> 9;
    int c = idx & 511;
    float n = tanhf(XW[(size_t)row * ldxw + 1024 + c] + NU[idx] + b[1024 + c]);
    float z = Z[idx];
    float h = (1.f - z) * Hh[idx] + z * n;
    Hh[idx] = h;
    __half ph, pl;
    split_h(h, ph, pl);
    Ph[idx] = ph; Pl[idx] = pl;
}

// ---------------- NMS ----------------------------------------------------------
__global__ __launch_bounds__(512) void nms_kernel(const float* __restrict__ SP,
                                                  const float* __restrict__ BOX,
                                                  unsigned char* __restrict__ KEEP) {
    int cls = blockIdx.x + 1;
    int tid = threadIdx.x;
    __shared__ float sc[NN];
    __shared__ int sidx[NN];
    __shared__ float bx[NN][4];
    __shared__ float area[NN];
    __shared__ unsigned char keep[NN];

    sc[tid] = SP[(size_t)tid * NOC_ + cls];
    sidx[tid] = tid;
    __syncthreads();

    for (int k = 2; k <= NN; k <<= 1) {
        for (int j = k >> 1; j > 0; j >>= 1) {
            int ixj = tid ^ j;
            if (ixj > tid) {
                float s1 = sc[tid], s2 = sc[ixj];
                int i1 = sidx[tid], i2 = sidx[ixj];
                bool dir = ((tid & k) == 0);
                bool precBA = (s2 > s1) || (s2 == s1 && i2 < i1);
                if (precBA == dir) {
                    sc[tid] = s2; sc[ixj] = s1;
                    sidx[tid] = i2; sidx[ixj] = i1;
                }
            }
            __syncthreads();
        }
    }

    int oi = sidx[tid];
    float x1 = BOX[((size_t)oi * NOC_ + cls) * 4 + 0];
    float y1 = BOX[((size_t)oi * NOC_ + cls) * 4 + 1];
    float x2 = BOX[((size_t)oi * NOC_ + cls) * 4 + 2];
    float y2 = BOX[((size_t)oi * NOC_ + cls) * 4 + 3];
    bx[tid][0] = x1; bx[tid][1] = y1; bx[tid][2] = x2; bx[tid][3] = y2;
    area[tid] = (x2 - x1) * (y2 - y1);
    keep[tid] = 1;
    __syncthreads();

    for (int i = 0; i < NN - 1; i++) {
        if (tid > i && keep[i] && keep[tid]) {
            float lx = fmaxf(bx[i][0], x1);
            float ly = fmaxf(bx[i][1], y1);
            float rx = fminf(bx[i][2], x2);
            float ry = fminf(bx[i][3], y2);
            float w = fmaxf(rx - lx, 0.f);
            float h = fmaxf(ry - ly, 0.f);
            float inter = w * h;
            float iou = inter / (area[i] + area[tid] - inter + 1e-9f);
            if (iou > IOU_THR_) keep[tid] = 0;
        }
        __syncthreads();
    }
    KEEP[(size_t)(cls - 1) * NN + oi] = keep[tid];
}

// ---------------- obj_preds ----------------------------------------------------
__global__ void preds_kernel(const float* __restrict__ SP, const unsigned char* __restrict__ KEEP,
                             float* __restrict__ out) {
    int n = blockIdx.x * blockDim.x + threadIdx.x;
    if (n >= NN) return;
    float best = -1.f;
    int bi = 0;
    for (int c = 0; c < 150; c++) {
        float v = KEEP[(size_t)c * NN + n] ? SP[(size_t)n * NOC_ + c + 1] : 0.f;
        if (v > best) { best = v; bi = c; }
    }
    out[n] = (float)(bi + 1);
}

// ---------------- host orchestration ------------------------------------------
static void sgemm(const float* A, int lda, const float* B, int ldb,
                  float* C, int ldc, int M, int N, int K,
                  const float* bias, const float* addm) {
    dim3 g((N + 127) / 128, (M + 127) / 128);
    sgemm_kernel<<<g, 256>>>(A, lda, B, ldb, C, ldc, M, N, K, bias, addm);
}

struct Scratch {
    float *OBJ_PROBS, *FO, *HOBJ, *HREL, *XWR, *HMHU, *ZR, *NUR;
    float *XWO, *HUO, *ZO, *NUO, *SP, *WCOMB;
    unsigned char* KEEP;
    __half *Pa_h, *Pa_l, *Ps_h, *Ps_l, *Ph_h, *Ph_l;
    __half *Po1_h, *Po1_l, *Po2_h, *Po2_l, *Po3_h, *Po3_l;
    __half *Wop_h, *Wop_l, *Wrp_h, *Wrp_l, *Wcb_h, *Wcb_l, *Wmo_h, *Wmo_l;
    __half *Ugr_h, *Ugr_l, *Wgo_h, *Wgo_l, *Ugo_h, *Ugo_l;
    bool init = false;
};
static Scratch g_sc;

static void init_scratch() {
    if (g_sc.init) return;
    void* p;
#define GET(sym, fld, T) cudaGetSymbolAddress(&p, sym); g_sc.fld = (T*)p;
    GET(g_obj_probs, OBJ_PROBS, float)
    GET(g_fo, FO, float)
    GET(g_h_obj, HOBJ, float)
    GET(g_h_rel, HREL, float)
    GET(g_xw_rel, XWR, float)
    GET(g_hmhu, HMHU, float)
    GET(g_z_rel, ZR, float)
    GET(g_nu_rel, NUR, float)
    GET(g_xw_obj, XWO, float)
    GET(g_hu_obj, HUO, float)
    GET(g_z_obj, ZO, float)
    GET(g_nu_obj, NUO, float)
    GET(g_sp, SP, float)
    GET(g_wcomb, WCOMB, float)
    GET(g_keep, KEEP, unsigned char)
    GET(g_Pa_h, Pa_h, __half) GET(g_Pa_l, Pa_l, __half)
    GET(g_Ps_h, Ps_h, __half) GET(g_Ps_l, Ps_l, __half)
    GET(g_Ph_h, Ph_h, __half) GET(g_Ph_l, Ph_l, __half)
    GET(g_Po1_h, Po1_h, __half) GET(g_Po1_l, Po1_l, __half)
    GET(g_Po2_h, Po2_h, __half) GET(g_Po2_l, Po2_l, __half)
    GET(g_Po3_h, Po3_h, __half) GET(g_Po3_l, Po3_l, __half)
    GET(g_Wop_h, Wop_h, __half) GET(g_Wop_l, Wop_l, __half)
    GET(g_Wrp_h, Wrp_h, __half) GET(g_Wrp_l, Wrp_l, __half)
    GET(g_Wcb_h, Wcb_h, __half) GET(g_Wcb_l, Wcb_l, __half)
    GET(g_Wmo_h, Wmo_h, __half) GET(g_Wmo_l, Wmo_l, __half)
    GET(g_Ugr_h, Ugr_h, __half) GET(g_Ugr_l, Ugr_l, __half)
    GET(g_Wgo_h, Wgo_h, __half) GET(g_Wgo_l, Wgo_l, __half)
    GET(g_Ugo_h, Ugo_h, __half) GET(g_Ugo_l, Ugo_l, __half)
#undef GET
    cudaFuncSetAttribute(hgemm_kernel, cudaFuncAttributeMaxDynamicSharedMemorySize, HG_SMEM);
    g_sc.init = true;
}

static void hgemm(const __half* Ah, const __half* Al,
                  const __half* Bh, const __half* Bl,
                  float* C, int ldc, int M, int N, int K, const float* bias,
                  __half* Ch = nullptr, __half* Cl = nullptr) {
    dim3 g(N / 128, M / 128);
    hgemm_kernel<<<g, 256, HG_SMEM>>>(Ah, Al, Bh, Bl, C, ldc, M, N, K, bias, Ch, Cl);
}

static void asplit(const float* A, __half* hi, __half* lo, int n) {
    int n2 = n / 2;
    asplit_kernel<<<(n2 + 255) / 256, 256>>>((const float2*)A, (__half2*)hi, (__half2*)lo, n2);
}

static void wsplit(const float* W, __half* Th, __half* Tl, int K, int N) {
    dim3 g(N / 32, K / 32);
    wsplit_kernel<<<g, dim3(32, 8)>>>(W, Th, Tl, K, N);
}

extern "C" void kernel_launch(void* const* d_in, const int* in_sizes, int n_in,
                              void* d_out, int out_size) {
    (void)in_sizes; (void)n_in; (void)out_size;
    init_scratch();

    const float* obj_fmaps  = (const float*)d_in[1];
    const float* obj_logits = (const float*)d_in[2];
    const void*  rel_raw    = d_in[3];
    const float* vr         = (const float*)d_in[4];
    const float* boxes      = (const float*)d_in[5];
    const float* W_obj_proj = (const float*)d_in[6];
    const float* b_obj_proj = (const float*)d_in[7];
    const float* W_rel_proj = (const float*)d_in[8];
    const float* b_rel_proj = (const float*)d_in[9];
    const float* W_emb      = (const float*)d_in[10];
    const float* W_msg_rel  = (const float*)d_in[11];
    const float* W_msg_obj  = (const float*)d_in[12];
    const float* W_gru_obj  = (const float*)d_in[13];
    const float* U_gru_obj  = (const float*)d_in[14];
    const float* b_gru_obj  = (const float*)d_in[15];
    const float* W_gru_rel  = (const float*)d_in[16];
    const float* U_gru_rel  = (const float*)d_in[17];
    const float* b_gru_rel  = (const float*)d_in[18];
    const float* W_cls_rel  = (const float*)d_in[19];
    const float* b_cls_rel  = (const float*)d_in[20];
    const float* W_cls_obj  = (const float*)d_in[21];
    const float* b_cls_obj  = (const float*)d_in[22];

    float* out_obj_logits = (float*)d_out;
    float* out_preds      = out_obj_logits + NN * NOC_;
    float* out_rel_logits = out_preds + NN;

    // 0. decode rel indices; weight planes
    decode_rel_kernel<<<1, 1024>>>(rel_raw);
    wsplit(W_obj_proj, g_sc.Wop_h, g_sc.Wop_l, OBJD, HD);
    wsplit(W_rel_proj, g_sc.Wrp_h, g_sc.Wrp_l, OBJD, HD);
    wsplit(W_msg_obj,  g_sc.Wmo_h, g_sc.Wmo_l, HD, HD);
    wsplit(U_gru_rel,  g_sc.Ugr_h, g_sc.Ugr_l, HD, 3 * HD);
    wsplit(W_gru_obj,  g_sc.Wgo_h, g_sc.Wgo_l, HD, 3 * HD);
    wsplit(U_gru_obj,  g_sc.Ugo_h, g_sc.Ugo_l, HD, 3 * HD);
    // WCOMB = W_msg_rel @ W_gru_rel (f32), then split
    sgemm(W_msg_rel, HD, W_gru_rel, 3 * HD, g_sc.WCOMB, 3 * HD, HD, 3 * HD, HD, nullptr, nullptr);
    wsplit(g_sc.WCOMB, g_sc.Wcb_h, g_sc.Wcb_l, HD, 3 * HD);

    // 1. obj_probs
    softmax_kernel<<<NN, 256>>>(obj_logits, g_sc.OBJ_PROBS);

    // 2. fo = obj_fmaps @ W_obj_proj + b
    asplit(obj_fmaps, g_sc.Pa_h, g_sc.Pa_l, NN * OBJD);
    hgemm(g_sc.Pa_h, g_sc.Pa_l, g_sc.Wop_h, g_sc.Wop_l, g_sc.FO, HD, NN, HD, OBJD, b_obj_proj);

    // 3. h_obj = fo + obj_probs @ W_emb  (SIMT), then planes
    sgemm(g_sc.OBJ_PROBS, NOC_, W_emb, HD, g_sc.HOBJ, HD, NN, HD, NOC_, nullptr, g_sc.FO);
    asplit(g_sc.HOBJ, g_sc.Po2_h, g_sc.Po2_l, NN * HD);

    // 4. h_rel = vr @ W_rel_proj + b  (+ planes from epilogue)
    asplit(vr, g_sc.Pa_h, g_sc.Pa_l, RR * OBJD);
    hgemm(g_sc.Pa_h, g_sc.Pa_l, g_sc.Wrp_h, g_sc.Wrp_l, g_sc.HREL, HD, RR, HD, OBJD, b_rel_proj,
          g_sc.Ph_h, g_sc.Ph_l);

    const int EW_REL = (RR * HD + 255) / 256;
    const int EW_OBJ = (NN * HD + 255) / 256;
    const __half* Ugr2_h = g_sc.Ugr_h + (size_t)2 * HD * HD;
    const __half* Ugr2_l = g_sc.Ugr_l + (size_t)2 * HD * HD;
    const __half* Ugo2_h = g_sc.Ugo_h + (size_t)2 * HD * HD;
    const __half* Ugo2_l = g_sc.Ugo_l + (size_t)2 * HD * HD;

    for (int t = 0; t < TSTEPS; t++) {
        // XWR = (h_obj[s]+h_obj[o]) @ WCOMB
        gather_split_kernel<<<EW_REL, 256>>>(g_sc.HOBJ, g_sc.Ps_h, g_sc.Ps_l);
        hgemm(g_sc.Ps_h, g_sc.Ps_l, g_sc.Wcb_h, g_sc.Wcb_l, g_sc.XWR, 3 * HD, RR, 3 * HD, HD, nullptr);

        // HM -> HMHU[:, :512];  HU -> HMHU[:, 512:1536]  (pre-update h_rel planes)
        hgemm(g_sc.Ph_h, g_sc.Ph_l, g_sc.Wmo_h, g_sc.Wmo_l, g_sc.HMHU, 3 * HD, RR, HD, HD, nullptr);
        hgemm(g_sc.Ph_h, g_sc.Ph_l, g_sc.Ugr_h, g_sc.Ugr_l, g_sc.HMHU + HD, 3 * HD, RR, 2 * HD, HD, nullptr);
        scatter_obj_kernel<<<NN, 512>>>(g_sc.HMHU, 3 * HD, g_sc.Po1_h, g_sc.Po1_l);

        // GRU rel
        gru_zr_kernel<<<EW_REL, 256>>>(g_sc.XWR, 3 * HD, g_sc.HMHU + HD, 3 * HD,
                                       b_gru_rel, g_sc.HREL, g_sc.ZR, g_sc.Ps_h, g_sc.Ps_l, RR);
        hgemm(g_sc.Ps_h, g_sc.Ps_l, Ugr2_h, Ugr2_l, g_sc.NUR, HD, RR, HD, HD, nullptr);
        gru_fin_kernel<<<EW_REL, 256>>>(g_sc.XWR, 3 * HD, g_sc.NUR, b_gru_rel, g_sc.ZR,
                                        g_sc.HREL, g_sc.Ph_h, g_sc.Ph_l, RR);

        // GRU obj
        hgemm(g_sc.Po1_h, g_sc.Po1_l, g_sc.Wgo_h, g_sc.Wgo_l, g_sc.XWO, 3 * HD, NN, 3 * HD, HD, nullptr);
        hgemm(g_sc.Po2_h, g_sc.Po2_l, g_sc.Ugo_h, g_sc.Ugo_l, g_sc.HUO, 2 * HD, NN, 2 * HD, HD, nullptr);
        gru_zr_kernel<<<EW_OBJ, 256>>>(g_sc.XWO, 3 * HD, g_sc.HUO, 2 * HD,
                                       b_gru_obj, g_sc.HOBJ, g_sc.ZO, g_sc.Po3_h, g_sc.Po3_l, NN);
        hgemm(g_sc.Po3_h, g_sc.Po3_l, Ugo2_h, Ugo2_l, g_sc.NUO, HD, NN, HD, HD, nullptr);
        gru_fin_kernel<<<EW_OBJ, 256>>>(g_sc.XWO, 3 * HD, g_sc.NUO, b_gru_obj, g_sc.ZO,
                                        g_sc.HOBJ, g_sc.Po2_h, g_sc.Po2_l, NN);
    }

    // classifiers (odd N -> SIMT)
    sgemm(g_sc.HREL, HD, W_cls_rel, NRC_, out_rel_logits, NRC_, RR, NRC_, HD, b_cls_rel, nullptr);
    sgemm(g_sc.HOBJ, HD, W_cls_obj, NOC_, out_obj_logits, NOC_, NN, NOC_, HD, b_cls_obj, nullptr);

    // softmax -> NMS -> preds
    softmax_kernel<<<NN, 256>>>(out_obj_logits, g_sc.SP);
    nms_kernel<<<150, 512>>>(g_sc.SP, boxes, g_sc.KEEP);
    preds_kernel<<<(NN + 255) / 256, 256>>>(g_sc.SP, g_sc.KEEP, out_preds);
}

// round 9
// speedup vs baseline: 1.7925x; 1.0352x over previous
#include <cuda_runtime.h>
#include <cuda_bf16.h>
#include <cuda_fp16.h>
#include <math.h>
#include <stdint.h>

// ---------------- problem constants ----------------
#define BIMG 8
#define OPI_ 64
#define RPI_ 1024
#define NN 512
#define RR 8192
#define OBJD 4096
#define HD 512
#define NOC_ 151
#define NRC_ 51
#define TSTEPS 3
#define IOU_THR_ 0.3f

// ---------------- helpers ----------------------------------------------------
__device__ __forceinline__ void split_h(float v, __half& hi, __half& lo) {
    hi = __float2half_rn(v);
    lo = __float2half_rn(v - __half2float(hi));
}
__device__ __forceinline__ void mma_f16(float* c, const uint32_t* a, const uint32_t* b) {
    asm volatile(
        "mma.sync.aligned.m16n8k16.row.col.f32.f16.f16.f32 "
        "{%0,%1,%2,%3},{%4,%5,%6,%7},{%8,%9},{%0,%1,%2,%3};"
        : "+f"(c[0]), "+f"(c[1]), "+f"(c[2]), "+f"(c[3])
        : "r"(a[0]), "r"(a[1]), "r"(a[2]), "r"(a[3]), "r"(b[0]), "r"(b[1]));
}
__device__ __forceinline__ void cp16(uint32_t dst, const void* src) {
    asm volatile("cp.async.cg.shared.global [%0], [%1], 16;" :: "r"(dst), "l"(src));
}
#define LDSM_X4(r0, r1, r2, r3, addr) \
    asm volatile("ldmatrix.sync.aligned.m8n8.x4.shared.b16 {%0,%1,%2,%3}, [%4];" \
        : "=r"(r0), "=r"(r1), "=r"(r2), "=r"(r3) : "r"(addr))

// ---------------- f32 scratch ------------------------------------------------
__device__ float g_obj_probs[NN * NOC_];
__device__ float g_fo[NN * HD];
__device__ float g_h_obj[NN * HD];
__device__ float g_h_rel[RR * HD];
__device__ float g_xw_rel[RR * 3 * HD];
__device__ float g_hmhu[RR * 3 * HD];
__device__ float g_z_rel[RR * HD];
__device__ float g_nu_rel[RR * HD];
__device__ float g_xw_obj[NN * 3 * HD];
__device__ float g_hu_obj[NN * 2 * HD];
__device__ float g_z_obj[NN * HD];
__device__ float g_nu_obj[NN * HD];
__device__ float g_sp[NN * NOC_];
__device__ float g_wcomb[HD * 3 * HD];
__device__ unsigned char g_keep[150 * NN];
__device__ int g_s_idx[RR];
__device__ int g_o_idx[RR];

// ---------------- fp16 plane scratch -----------------------------------------
__device__ __half g_Pa_h[RR * OBJD], g_Pa_l[RR * OBJD];
__device__ __half g_Ps_h[RR * HD],  g_Ps_l[RR * HD];
__device__ __half g_Ph_h[RR * HD],  g_Ph_l[RR * HD];
__device__ __half g_Po1_h[NN * HD], g_Po1_l[NN * HD];
__device__ __half g_Po2_h[NN * HD], g_Po2_l[NN * HD];
__device__ __half g_Po3_h[NN * HD], g_Po3_l[NN * HD];
// weight planes, [N,K]
__device__ __half g_Wop_h[HD * OBJD], g_Wop_l[HD * OBJD];
__device__ __half g_Wrp_h[HD * OBJD], g_Wrp_l[HD * OBJD];
__device__ __half g_Wcb_h[3 * HD * HD], g_Wcb_l[3 * HD * HD];    // WCOMB^T
__device__ __half g_Wct_h[3 * HD * HD], g_Wct_l[3 * HD * HD];    // [Wmo | Ugr01]^T
__device__ __half g_Ugr2_h[HD * HD],   g_Ugr2_l[HD * HD];        // Ugr cols 1024-1535
__device__ __half g_Wgo_h[3 * HD * HD], g_Wgo_l[3 * HD * HD];
__device__ __half g_Ugo_h[3 * HD * HD], g_Ugo_l[3 * HD * HD];

// ============================================================================
// fp16 3-pass GEMM (hi/lo planes), ldmatrix fragments.
//   C[M,N] = A[M,K] @ B^T (+bias), A planes [M,K], B planes [N,K].
// 128x128x32 tile, 256 thr, 8 warps (2x4), warp 64x32, cp.async dbl buffer.
// ============================================================================
#define HROW 20
#define HPLW (128 * HROW)
#define HSTW (4 * HPLW)
#define HG_SMEM (2 * HSTW * 4)

__global__ __launch_bounds__(256, 2) void hgemm_kernel(
    const __half* __restrict__ Ah, const __half* __restrict__ Al,
    const __half* __restrict__ Bh, const __half* __restrict__ Bl,
    float* __restrict__ C, int ldc,
    int M, int N, int K, const float* __restrict__ bias,
    __half* __restrict__ Ch, __half* __restrict__ Cl)
{
    extern __shared__ uint32_t sm[];
    const int tid = threadIdx.x;
    const int lane = tid & 31;
    const int warp = tid >> 5;
    const int wm = warp >> 2;
    const int wn = warp & 3;
    const int lr = lane >> 2;
    const int lc = lane & 3;
    const int m0 = blockIdx.y * 128;
    const int n0 = blockIdx.x * 128;
    const int KT = K / 32;

    const uint32_t sbase = (uint32_t)__cvta_generic_to_shared(sm);

    // ldmatrix per-thread source coordinates
    const int aRowOff = (wm * 64 + (lane & 15)) * HROW + (lane >> 4) * 4;
    const int bRowOff = (wn * 32 + (lane & 7) + ((lane >> 4) << 3)) * HROW
                      + (((lane >> 3) & 1) * 4);

    auto load_stage = [&](int kt, int buf) {
        const int k0 = kt * 32;
        uint32_t sb = sbase + (uint32_t)(buf * HSTW * 4);
#pragma unroll
        for (int i = 0; i < 2; i++) {
            int cid = tid * 2 + i;
            int row = cid >> 2, ch = cid & 3;
            uint32_t d = sb + (uint32_t)((row * HROW + ch * 4) * 4);
            size_t src = (size_t)(m0 + row) * K + k0 + ch * 8;
            cp16(d, Ah + src);
            cp16(d + HPLW * 4, Al + src);
        }
#pragma unroll
        for (int i = 0; i < 2; i++) {
            int cid = tid * 2 + i;
            int row = cid >> 2, ch = cid & 3;
            uint32_t d = sb + (uint32_t)((2 * HPLW + row * HROW + ch * 4) * 4);
            size_t src = (size_t)(n0 + row) * K + k0 + ch * 8;
            cp16(d, Bh + src);
            cp16(d + HPLW * 4, Bl + src);
        }
        asm volatile("cp.async.commit_group;");
    };

    float acc[4][4][4];
#pragma unroll
    for (int i = 0; i < 4; i++)
#pragma unroll
        for (int j = 0; j < 4; j++)
#pragma unroll
            for (int l = 0; l < 4; l++) acc[i][j][l] = 0.f;

    load_stage(0, 0);
    if (KT > 1) load_stage(1, 1);
    asm volatile("cp.async.wait_group 1;");
    __syncthreads();

    for (int kt = 0; kt < KT; kt++) {
        const int cur = kt & 1;
        const uint32_t uA = sbase + (uint32_t)(cur * HSTW * 4);
        const uint32_t uB = uA + (uint32_t)(2 * HPLW * 4);

#pragma unroll
        for (int wc = 0; wc < 16; wc += 8) {   // two k16 chunks per stage
            uint32_t aH[4][4], aL[4][4], bH[4][2], bL[4][2];
#pragma unroll
            for (int mt = 0; mt < 4; mt++) {
                uint32_t ad = uA + (uint32_t)((aRowOff + mt * 16 * HROW + wc) * 4);
                LDSM_X4(aH[mt][0], aH[mt][1], aH[mt][2], aH[mt][3], ad);
                LDSM_X4(aL[mt][0], aL[mt][1], aL[mt][2], aL[mt][3], ad + HPLW * 4);
            }
#pragma unroll
            for (int pr = 0; pr < 2; pr++) {
                uint32_t bd = uB + (uint32_t)((bRowOff + pr * 16 * HROW + wc) * 4);
                LDSM_X4(bH[2 * pr][0], bH[2 * pr][1], bH[2 * pr + 1][0], bH[2 * pr + 1][1], bd);
                LDSM_X4(bL[2 * pr][0], bL[2 * pr][1], bL[2 * pr + 1][0], bL[2 * pr + 1][1],
                        bd + HPLW * 4);
            }
#pragma unroll
            for (int mt = 0; mt < 4; mt++)
#pragma unroll
                for (int nt = 0; nt < 4; nt++) {
                    mma_f16(acc[mt][nt], aH[mt], bH[nt]);  // hi*hi
                    mma_f16(acc[mt][nt], aH[mt], bL[nt]);  // hi*lo
                    mma_f16(acc[mt][nt], aL[mt], bH[nt]);  // lo*hi
                }
        }
        __syncthreads();
        if (kt + 2 < KT) {
            load_stage(kt + 2, cur);
            asm volatile("cp.async.wait_group 1;");
        } else if (kt + 1 < KT) {
            asm volatile("cp.async.wait_group 0;");
        }
        __syncthreads();
    }

    // epilogue
#pragma unroll
    for (int mt = 0; mt < 4; mt++) {
        int gm0 = m0 + wm * 64 + mt * 16 + lr;
        int gm1 = gm0 + 8;
#pragma unroll
        for (int nt = 0; nt < 4; nt++) {
            int gn = n0 + wn * 32 + nt * 8 + lc * 2;
            float b0 = 0.f, b1 = 0.f;
            if (bias) { b0 = bias[gn]; b1 = bias[gn + 1]; }
            float2 v0 = make_float2(acc[mt][nt][0] + b0, acc[mt][nt][1] + b1);
            float2 v1 = make_float2(acc[mt][nt][2] + b0, acc[mt][nt][3] + b1);
            *(float2*)(C + (size_t)gm0 * ldc + gn) = v0;
            *(float2*)(C + (size_t)gm1 * ldc + gn) = v1;
            if (Ch) {
                __half hx, lx, hy, ly;
                split_h(v0.x, hx, lx); split_h(v0.y, hy, ly);
                *(__half2*)(Ch + (size_t)gm0 * ldc + gn) = __halves2half2(hx, hy);
                *(__half2*)(Cl + (size_t)gm0 * ldc + gn) = __halves2half2(lx, ly);
                split_h(v1.x, hx, lx); split_h(v1.y, hy, ly);
                *(__half2*)(Ch + (size_t)gm1 * ldc + gn) = __halves2half2(hx, hy);
                *(__half2*)(Cl + (size_t)gm1 * ldc + gn) = __halves2half2(lx, ly);
            }
        }
    }
}

// ---------------- split kernels ---------------------------------------------
__global__ void asplit_kernel(const float2* __restrict__ in,
                              __half2* __restrict__ hi, __half2* __restrict__ lo, int n2) {
    int i = blockIdx.x * blockDim.x + threadIdx.x;
    if (i >= n2) return;
    float2 v = in[i];
    __half hx, lx, hy, ly;
    split_h(v.x, hx, lx);
    split_h(v.y, hy, ly);
    hi[i] = __halves2half2(hx, hy);
    lo[i] = __halves2half2(lx, ly);
}

// W [K, ldw] f32, columns [c0, c0+ncols) -> planes [ncols, K] fp16
__global__ void wsplit_kernel(const float* __restrict__ W, int ldw, int c0,
                              __half* __restrict__ Th, __half* __restrict__ Tl, int K) {
    __shared__ float t[32][33];
    int kb = blockIdx.y * 32, nb = blockIdx.x * 32;
    int tx = threadIdx.x, ty = threadIdx.y;  // 32 x 8
#pragma unroll
    for (int i = 0; i < 32; i += 8)
        t[ty + i][tx] = W[(size_t)(kb + ty + i) * ldw + c0 + nb + tx];
    __syncthreads();
#pragma unroll
    for (int i = 0; i < 32; i += 8) {
        int n = nb + ty + i, k = kb + tx;
        __half h, l;
        split_h(t[tx][ty + i], h, l);
        Th[(size_t)n * K + k] = h;
        Tl[(size_t)n * K + k] = l;
    }
}

// ---------------- generic fp32 SGEMM (small/odd shapes) ---------------------
__global__ __launch_bounds__(256) void sgemm_kernel(
    const float* __restrict__ A, int lda,
    const float* __restrict__ B, int ldb,
    float* __restrict__ C, int ldc,
    int M, int N, int K,
    const float* __restrict__ bias,
    const float* __restrict__ addm)
{
    __shared__ float As[8][132];
    __shared__ float Bs[8][128];
    const int tid = threadIdx.x;
    const int tx = tid & 15;
    const int ty = tid >> 4;
    const int m0 = blockIdx.y * 128;
    const int n0 = blockIdx.x * 128;

    float acc[8][8];
#pragma unroll
    for (int i = 0; i < 8; i++)
#pragma unroll
        for (int j = 0; j < 8; j++) acc[i][j] = 0.f;

    for (int k0 = 0; k0 < K; k0 += 8) {
#pragma unroll
        for (int l = 0; l < 4; l++) {
            int e = tid + l * 256;
            int r = e >> 3, c = e & 7;
            float v = 0.f;
            int gm = m0 + r, gk = k0 + c;
            if (gm < M && gk < K) v = A[(size_t)gm * lda + gk];
            As[c][r] = v;
        }
#pragma unroll
        for (int l = 0; l < 4; l++) {
            int e = tid + l * 256;
            int r = e >> 7, c = e & 127;
            float v = 0.f;
            int gk = k0 + r, gn = n0 + c;
            if (gk < K && gn < N) v = B[(size_t)gk * ldb + gn];
            Bs[r][c] = v;
        }
        __syncthreads();
#pragma unroll
        for (int k = 0; k < 8; k++) {
            float a[8], b[8];
#pragma unroll
            for (int i = 0; i < 8; i++) a[i] = As[k][ty * 8 + i];
#pragma unroll
            for (int j = 0; j < 8; j++) b[j] = Bs[k][tx * 8 + j];
#pragma unroll
            for (int i = 0; i < 8; i++)
#pragma unroll
                for (int j = 0; j < 8; j++)
                    acc[i][j] = fmaf(a[i], b[j], acc[i][j]);
        }
        __syncthreads();
    }
#pragma unroll
    for (int i = 0; i < 8; i++) {
        int gm = m0 + ty * 8 + i;
        if (gm >= M) continue;
#pragma unroll
        for (int j = 0; j < 8; j++) {
            int gn = n0 + tx * 8 + j;
            if (gn >= N) continue;
            float v = acc[i][j];
            if (bias) v += bias[gn];
            if (addm) v += addm[(size_t)gm * ldc + gn];
            C[(size_t)gm * ldc + gn] = v;
        }
    }
}

// ---------------- decode rel_inds --------------------------------------------
__global__ __launch_bounds__(1024) void decode_rel_kernel(const void* rel_raw) {
    __shared__ int s_or;
    int tid = threadIdx.x;
    if (tid == 0) s_or = 0;
    __syncthreads();
    const int* v32 = (const int*)rel_raw;
    int acc = 0;
    for (int i = tid; i < (3 * RR) / 2; i += 1024) acc |= v32[2 * i + 1];
    if (acc) atomicOr(&s_or, 1);
    __syncthreads();
    bool is64 = (s_or == 0);
    if (is64) {
        const long long* v = (const long long*)rel_raw;
        for (int r = tid; r < RR; r += 1024) {
            g_s_idx[r] = (int)v[3 * r + 1];
            g_o_idx[r] = (int)v[3 * r + 2];
        }
    } else {
        for (int r = tid; r < RR; r += 1024) {
            g_s_idx[r] = v32[3 * r + 1];
            g_o_idx[r] = v32[3 * r + 2];
        }
    }
}

// ---------------- row softmax -------------------------------------------------
__global__ void softmax_kernel(const float* __restrict__ X, float* __restrict__ Y) {
    int row = blockIdx.x;
    int tid = threadIdx.x;
    __shared__ float red[256];
    const float* x = X + (size_t)row * NOC_;
    float m = -3.4e38f;
    for (int c = tid; c < NOC_; c += 256) m = fmaxf(m, x[c]);
    red[tid] = m; __syncthreads();
    for (int s = 128; s > 0; s >>= 1) {
        if (tid < s) red[tid] = fmaxf(red[tid], red[tid + s]);
        __syncthreads();
    }
    m = red[0]; __syncthreads();
    float sum = 0.f;
    for (int c = tid; c < NOC_; c += 256) sum += expf(x[c] - m);
    red[tid] = sum; __syncthreads();
    for (int s = 128; s > 0; s >>= 1) {
        if (tid < s) red[tid] += red[tid + s];
        __syncthreads();
    }
    float inv = 1.f / red[0];
    for (int c = tid; c < NOC_; c += 256)
        Y[(size_t)row * NOC_ + c] = expf(x[c] - m) * inv;
}

// ---------------- gather + split: SUMSO planes --------------------------------
__global__ void gather_split_kernel(const float* __restrict__ Hobj,
                                    __half* __restrict__ Sh, __half* __restrict__ Sl) {
    int idx = blockIdx.x * blockDim.x + threadIdx.x;
    if (idx >= RR * HD) return;
    int r = idx >> 9;
    int c = idx & 511;
    float v = Hobj[(size_t)g_s_idx[r] * HD + c] + Hobj[(size_t)g_o_idx[r] * HD + c];
    __half h, l;
    split_h(v, h, l);
    Sh[idx] = h; Sl[idx] = l;
}

// ---------------- m_obj scatter -> planes -------------------------------------
__global__ __launch_bounds__(512) void scatter_obj_kernel(const float* __restrict__ HM, int ldhm,
                                                          __half* __restrict__ Mh,
                                                          __half* __restrict__ Ml) {
    int obj = blockIdx.x;
    int c = threadIdx.x;
    int img = obj >> 6;
    int base = img * RPI_;
    __shared__ int ss[RPI_];
    __shared__ int oo[RPI_];
    for (int j = c; j < RPI_; j += 512) {
        ss[j] = g_s_idx[base + j];
        oo[j] = g_o_idx[base + j];
    }
    __syncthreads();
    float acc = 0.f;
    for (int j = 0; j < RPI_; j++) {
        if (ss[j] == obj) acc += HM[(size_t)(base + j) * ldhm + c];
        if (oo[j] == obj) acc += HM[(size_t)(base + j) * ldhm + c];
    }
    __half h, l;
    split_h(acc, h, l);
    Mh[(size_t)obj * HD + c] = h;
    Ml[(size_t)obj * HD + c] = l;
}

// ---------------- GRU z, r*h -> planes ----------------------------------------
__global__ void gru_zr_kernel(const float* __restrict__ XW, int ldxw,
                              const float* __restrict__ HU, int ldhu,
                              const float* __restrict__ b, const float* __restrict__ Hh,
                              float* __restrict__ Z,
                              __half* __restrict__ RHh, __half* __restrict__ RHl, int M) {
    int idx = blockIdx.x * blockDim.x + threadIdx.x;
    if (idx >= M * HD) return;
    int row = idx >> 9;
    int c = idx & 511;
    float z = XW[(size_t)row * ldxw + c] + HU[(size_t)row * ldhu + c] + b[c];
    float r = XW[(size_t)row * ldxw + 512 + c] + HU[(size_t)row * ldhu + 512 + c] + b[512 + c];
    z = 1.f / (1.f + expf(-z));
    r = 1.f / (1.f + expf(-r));
    Z[idx] = z;
    __half h, l;
    split_h(r * Hh[idx], h, l);
    RHh[idx] = h; RHl[idx] = l;
}

// ---------------- GRU n + h update (+ planes) ----------------------------------
__global__ void gru_fin_kernel(const float* __restrict__ XW, int ldxw,
                               const float* __restrict__ NU,
                               const float* __restrict__ b, const float* __restrict__ Z,
                               float* __restrict__ Hh,
                               __half* __restrict__ Ph, __half* __restrict__ Pl, int M) {
    int idx = blockIdx.x * blockDim.x + threadIdx.x;
    if (idx >= M * HD) return;
    int row = idx >> 9;
    int c = idx & 511;
    float n = tanhf(XW[(size_t)row * ldxw + 1024 + c] + NU[idx] + b[1024 + c]);
    float z = Z[idx];
    float h = (1.f - z) * Hh[idx] + z * n;
    Hh[idx] = h;
    __half ph, pl;
    split_h(h, ph, pl);
    Ph[idx] = ph; Pl[idx] = pl;
}

// ---------------- NMS ----------------------------------------------------------
__global__ __launch_bounds__(512) void nms_kernel(const float* __restrict__ SP,
                                                  const float* __restrict__ BOX,
                                                  unsigned char* __restrict__ KEEP) {
    int cls = blockIdx.x + 1;
    int tid = threadIdx.x;
    __shared__ float sc[NN];
    __shared__ int sidx[NN];
    __shared__ float bx[NN][4];
    __shared__ float area[NN];
    __shared__ unsigned char keep[NN];

    sc[tid] = SP[(size_t)tid * NOC_ + cls];
    sidx[tid] = tid;
    __syncthreads();

    for (int k = 2; k <= NN; k <<= 1) {
        for (int j = k >> 1; j > 0; j >>= 1) {
            int ixj = tid ^ j;
            if (ixj > tid) {
                float s1 = sc[tid], s2 = sc[ixj];
                int i1 = sidx[tid], i2 = sidx[ixj];
                bool dir = ((tid & k) == 0);
                bool precBA = (s2 > s1) || (s2 == s1 && i2 < i1);
                if (precBA == dir) {
                    sc[tid] = s2; sc[ixj] = s1;
                    sidx[tid] = i2; sidx[ixj] = i1;
                }
            }
            __syncthreads();
        }
    }

    int oi = sidx[tid];
    float x1 = BOX[((size_t)oi * NOC_ + cls) * 4 + 0];
    float y1 = BOX[((size_t)oi * NOC_ + cls) * 4 + 1];
    float x2 = BOX[((size_t)oi * NOC_ + cls) * 4 + 2];
    float y2 = BOX[((size_t)oi * NOC_ + cls) * 4 + 3];
    bx[tid][0] = x1; bx[tid][1] = y1; bx[tid][2] = x2; bx[tid][3] = y2;
    area[tid] = (x2 - x1) * (y2 - y1);
    keep[tid] = 1;
    __syncthreads();

    for (int i = 0; i < NN - 1; i++) {
        if (tid > i && keep[i] && keep[tid]) {
            float lx = fmaxf(bx[i][0], x1);
            float ly = fmaxf(bx[i][1], y1);
            float rx = fminf(bx[i][2], x2);
            float ry = fminf(bx[i][3], y2);
            float w = fmaxf(rx - lx, 0.f);
            float h = fmaxf(ry - ly, 0.f);
            float inter = w * h;
            float iou = inter / (area[i] + area[tid] - inter + 1e-9f);
            if (iou > IOU_THR_) keep[tid] = 0;
        }
        __syncthreads();
    }
    KEEP[(size_t)(cls - 1) * NN + oi] = keep[tid];
}

// ---------------- obj_preds ----------------------------------------------------
__global__ void preds_kernel(const float* __restrict__ SP, const unsigned char* __restrict__ KEEP,
                             float* __restrict__ out) {
    int n = blockIdx.x * blockDim.x + threadIdx.x;
    if (n >= NN) return;
    float best = -1.f;
    int bi = 0;
    for (int c = 0; c < 150; c++) {
        float v = KEEP[(size_t)c * NN + n] ? SP[(size_t)n * NOC_ + c + 1] : 0.f;
        if (v > best) { best = v; bi = c; }
    }
    out[n] = (float)(bi + 1);
}

// ---------------- host orchestration ------------------------------------------
static void sgemm(const float* A, int lda, const float* B, int ldb,
                  float* C, int ldc, int M, int N, int K,
                  const float* bias, const float* addm) {
    dim3 g((N + 127) / 128, (M + 127) / 128);
    sgemm_kernel<<<g, 256>>>(A, lda, B, ldb, C, ldc, M, N, K, bias, addm);
}

struct Scratch {
    float *OBJ_PROBS, *FO, *HOBJ, *HREL, *XWR, *HMHU, *ZR, *NUR;
    float *XWO, *HUO, *ZO, *NUO, *SP, *WCOMB;
    unsigned char* KEEP;
    __half *Pa_h, *Pa_l, *Ps_h, *Ps_l, *Ph_h, *Ph_l;
    __half *Po1_h, *Po1_l, *Po2_h, *Po2_l, *Po3_h, *Po3_l;
    __half *Wop_h, *Wop_l, *Wrp_h, *Wrp_l, *Wcb_h, *Wcb_l, *Wct_h, *Wct_l;
    __half *Ugr2_h, *Ugr2_l, *Wgo_h, *Wgo_l, *Ugo_h, *Ugo_l;
    bool init = false;
};
static Scratch g_sc;

static void init_scratch() {
    if (g_sc.init) return;
    void* p;
#define GET(sym, fld, T) cudaGetSymbolAddress(&p, sym); g_sc.fld = (T*)p;
    GET(g_obj_probs, OBJ_PROBS, float)
    GET(g_fo, FO, float)
    GET(g_h_obj, HOBJ, float)
    GET(g_h_rel, HREL, float)
    GET(g_xw_rel, XWR, float)
    GET(g_hmhu, HMHU, float)
    GET(g_z_rel, ZR, float)
    GET(g_nu_rel, NUR, float)
    GET(g_xw_obj, XWO, float)
    GET(g_hu_obj, HUO, float)
    GET(g_z_obj, ZO, float)
    GET(g_nu_obj, NUO, float)
    GET(g_sp, SP, float)
    GET(g_wcomb, WCOMB, float)
    GET(g_keep, KEEP, unsigned char)
    GET(g_Pa_h, Pa_h, __half) GET(g_Pa_l, Pa_l, __half)
    GET(g_Ps_h, Ps_h, __half) GET(g_Ps_l, Ps_l, __half)
    GET(g_Ph_h, Ph_h, __half) GET(g_Ph_l, Ph_l, __half)
    GET(g_Po1_h, Po1_h, __half) GET(g_Po1_l, Po1_l, __half)
    GET(g_Po2_h, Po2_h, __half) GET(g_Po2_l, Po2_l, __half)
    GET(g_Po3_h, Po3_h, __half) GET(g_Po3_l, Po3_l, __half)
    GET(g_Wop_h, Wop_h, __half) GET(g_Wop_l, Wop_l, __half)
    GET(g_Wrp_h, Wrp_h, __half) GET(g_Wrp_l, Wrp_l, __half)
    GET(g_Wcb_h, Wcb_h, __half) GET(g_Wcb_l, Wcb_l, __half)
    GET(g_Wct_h, Wct_h, __half) GET(g_Wct_l, Wct_l, __half)
    GET(g_Ugr2_h, Ugr2_h, __half) GET(g_Ugr2_l, Ugr2_l, __half)
    GET(g_Wgo_h, Wgo_h, __half) GET(g_Wgo_l, Wgo_l, __half)
    GET(g_Ugo_h, Ugo_h, __half) GET(g_Ugo_l, Ugo_l, __half)
#undef GET
    cudaFuncSetAttribute(hgemm_kernel, cudaFuncAttributeMaxDynamicSharedMemorySize, HG_SMEM);
    g_sc.init = true;
}

static void hgemm(const __half* Ah, const __half* Al,
                  const __half* Bh, const __half* Bl,
                  float* C, int ldc, int M, int N, int K, const float* bias,
                  __half* Ch = nullptr, __half* Cl = nullptr) {
    dim3 g(N / 128, M / 128);
    hgemm_kernel<<<g, 256, HG_SMEM>>>(Ah, Al, Bh, Bl, C, ldc, M, N, K, bias, Ch, Cl);
}

static void asplit(const float* A, __half* hi, __half* lo, int n) {
    int n2 = n / 2;
    asplit_kernel<<<(n2 + 255) / 256, 256>>>((const float2*)A, (__half2*)hi, (__half2*)lo, n2);
}

static void wsplit(const float* W, int ldw, int c0, __half* Th, __half* Tl, int K, int ncols) {
    dim3 g(ncols / 32, K / 32);
    wsplit_kernel<<<g, dim3(32, 8)>>>(W, ldw, c0, Th, Tl, K);
}

extern "C" void kernel_launch(void* const* d_in, const int* in_sizes, int n_in,
                              void* d_out, int out_size) {
    (void)in_sizes; (void)n_in; (void)out_size;
    init_scratch();

    const float* obj_fmaps  = (const float*)d_in[1];
    const float* obj_logits = (const float*)d_in[2];
    const void*  rel_raw    = d_in[3];
    const float* vr         = (const float*)d_in[4];
    const float* boxes      = (const float*)d_in[5];
    const float* W_obj_proj = (const float*)d_in[6];
    const float* b_obj_proj = (const float*)d_in[7];
    const float* W_rel_proj = (const float*)d_in[8];
    const float* b_rel_proj = (const float*)d_in[9];
    const float* W_emb      = (const float*)d_in[10];
    const float* W_msg_rel  = (const float*)d_in[11];
    const float* W_msg_obj  = (const float*)d_in[12];
    const float* W_gru_obj  = (const float*)d_in[13];
    const float* U_gru_obj  = (const float*)d_in[14];
    const float* b_gru_obj  = (const float*)d_in[15];
    const float* W_gru_rel  = (const float*)d_in[16];
    const float* U_gru_rel  = (const float*)d_in[17];
    const float* b_gru_rel  = (const float*)d_in[18];
    const float* W_cls_rel  = (const float*)d_in[19];
    const float* b_cls_rel  = (const float*)d_in[20];
    const float* W_cls_obj  = (const float*)d_in[21];
    const float* b_cls_obj  = (const float*)d_in[22];

    float* out_obj_logits = (float*)d_out;
    float* out_preds      = out_obj_logits + NN * NOC_;
    float* out_rel_logits = out_preds + NN;

    // 0. decode rel indices; weight planes
    decode_rel_kernel<<<1, 1024>>>(rel_raw);
    wsplit(W_obj_proj, HD, 0, g_sc.Wop_h, g_sc.Wop_l, OBJD, HD);
    wsplit(W_rel_proj, HD, 0, g_sc.Wrp_h, g_sc.Wrp_l, OBJD, HD);
    // WCAT planes: rows 0-511 = W_msg_obj^T; rows 512-1535 = U_gru_rel[:, :1024]^T
    wsplit(W_msg_obj, HD, 0, g_sc.Wct_h, g_sc.Wct_l, HD, HD);
    wsplit(U_gru_rel, 3 * HD, 0, g_sc.Wct_h + (size_t)HD * HD, g_sc.Wct_l + (size_t)HD * HD,
           HD, 2 * HD);
    wsplit(U_gru_rel, 3 * HD, 2 * HD, g_sc.Ugr2_h, g_sc.Ugr2_l, HD, HD);
    wsplit(W_gru_obj, 3 * HD, 0, g_sc.Wgo_h, g_sc.Wgo_l, HD, 3 * HD);
    wsplit(U_gru_obj, 3 * HD, 0, g_sc.Ugo_h, g_sc.Ugo_l, HD, 3 * HD);
    // WCOMB = W_msg_rel @ W_gru_rel (f32), then planes
    sgemm(W_msg_rel, HD, W_gru_rel, 3 * HD, g_sc.WCOMB, 3 * HD, HD, 3 * HD, HD, nullptr, nullptr);
    wsplit(g_sc.WCOMB, 3 * HD, 0, g_sc.Wcb_h, g_sc.Wcb_l, HD, 3 * HD);

    // 1. obj_probs
    softmax_kernel<<<NN, 256>>>(obj_logits, g_sc.OBJ_PROBS);

    // 2. fo = obj_fmaps @ W_obj_proj + b
    asplit(obj_fmaps, g_sc.Pa_h, g_sc.Pa_l, NN * OBJD);
    hgemm(g_sc.Pa_h, g_sc.Pa_l, g_sc.Wop_h, g_sc.Wop_l, g_sc.FO, HD, NN, HD, OBJD, b_obj_proj);

    // 3. h_obj = fo + obj_probs @ W_emb  (SIMT), then planes
    sgemm(g_sc.OBJ_PROBS, NOC_, W_emb, HD, g_sc.HOBJ, HD, NN, HD, NOC_, nullptr, g_sc.FO);
    asplit(g_sc.HOBJ, g_sc.Po2_h, g_sc.Po2_l, NN * HD);

    // 4. h_rel = vr @ W_rel_proj + b  (+ planes from epilogue)
    asplit(vr, g_sc.Pa_h, g_sc.Pa_l, RR * OBJD);
    hgemm(g_sc.Pa_h, g_sc.Pa_l, g_sc.Wrp_h, g_sc.Wrp_l, g_sc.HREL, HD, RR, HD, OBJD, b_rel_proj,
          g_sc.Ph_h, g_sc.Ph_l);

    const int EW_REL = (RR * HD + 255) / 256;
    const int EW_OBJ = (NN * HD + 255) / 256;
    const __half* Ugo2_h = g_sc.Ugo_h + (size_t)2 * HD * HD;
    const __half* Ugo2_l = g_sc.Ugo_l + (size_t)2 * HD * HD;

    for (int t = 0; t < TSTEPS; t++) {
        // XWR = (h_obj[s]+h_obj[o]) @ WCOMB
        gather_split_kernel<<<EW_REL, 256>>>(g_sc.HOBJ, g_sc.Ps_h, g_sc.Ps_l);
        hgemm(g_sc.Ps_h, g_sc.Ps_l, g_sc.Wcb_h, g_sc.Wcb_l, g_sc.XWR, 3 * HD, RR, 3 * HD, HD, nullptr);

        // HMHU = h_rel @ [W_msg_obj | U_gru_rel[:, :1024]]  (single N=1536 GEMM)
        hgemm(g_sc.Ph_h, g_sc.Ph_l, g_sc.Wct_h, g_sc.Wct_l, g_sc.HMHU, 3 * HD, RR, 3 * HD, HD, nullptr);
        scatter_obj_kernel<<<NN, 512>>>(g_sc.HMHU, 3 * HD, g_sc.Po1_h, g_sc.Po1_l);

        // GRU rel
        gru_zr_kernel<<<EW_REL, 256>>>(g_sc.XWR, 3 * HD, g_sc.HMHU + HD, 3 * HD,
                                       b_gru_rel, g_sc.HREL, g_sc.ZR, g_sc.Ps_h, g_sc.Ps_l, RR);
        hgemm(g_sc.Ps_h, g_sc.Ps_l, g_sc.Ugr2_h, g_sc.Ugr2_l, g_sc.NUR, HD, RR, HD, HD, nullptr);
        gru_fin_kernel<<<EW_REL, 256>>>(g_sc.XWR, 3 * HD, g_sc.NUR, b_gru_rel, g_sc.ZR,
                                        g_sc.HREL, g_sc.Ph_h, g_sc.Ph_l, RR);

        // GRU obj
        hgemm(g_sc.Po1_h, g_sc.Po1_l, g_sc.Wgo_h, g_sc.Wgo_l, g_sc.XWO, 3 * HD, NN, 3 * HD, HD, nullptr);
        hgemm(g_sc.Po2_h, g_sc.Po2_l, g_sc.Ugo_h, g_sc.Ugo_l, g_sc.HUO, 2 * HD, NN, 2 * HD, HD, nullptr);
        gru_zr_kernel<<<EW_OBJ, 256>>>(g_sc.XWO, 3 * HD, g_sc.HUO, 2 * HD,
                                       b_gru_obj, g_sc.HOBJ, g_sc.ZO, g_sc.Po3_h, g_sc.Po3_l, NN);
        hgemm(g_sc.Po3_h, g_sc.Po3_l, Ugo2_h, Ugo2_l, g_sc.NUO, HD, NN, HD, HD, nullptr);
        gru_fin_kernel<<<EW_OBJ, 256>>>(g_sc.XWO, 3 * HD, g_sc.NUO, b_gru_obj, g_sc.ZO,
                                        g_sc.HOBJ, g_sc.Po2_h, g_sc.Po2_l, NN);
    }

    // classifiers (odd N -> SIMT)
    sgemm(g_sc.HREL, HD, W_cls_rel, NRC_, out_rel_logits, NRC_, RR, NRC_, HD, b_cls_rel, nullptr);
    sgemm(g_sc.HOBJ, HD, W_cls_obj, NOC_, out_obj_logits, NOC_, NN, NOC_, HD, b_cls_obj, nullptr);

    // softmax -> NMS -> preds
    softmax_kernel<<<NN, 256>>>(out_obj_logits, g_sc.SP);
    nms_kernel<<<150, 512>>>(g_sc.SP, boxes, g_sc.KEEP);
    preds_kernel<<<(NN + 255) / 256, 256>>>(g_sc.SP, g_sc.KEEP, out_preds);
}

// round 10
// speedup vs baseline: 1.9254x; 1.0742x over previous
#include <cuda_runtime.h>
#include <cuda_bf16.h>
#include <cuda_fp16.h>
#include <math.h>
#include <stdint.h>

// ---------------- problem constants ----------------
#define BIMG 8
#define OPI_ 64
#define RPI_ 1024
#define NN 512
#define RR 8192
#define OBJD 4096
#define HD 512
#define NOC_ 151
#define NRC_ 51
#define TSTEPS 3
#define IOU_THR_ 0.3f

// ---------------- helpers ----------------------------------------------------
__device__ __forceinline__ void split_h(float v, __half& hi, __half& lo) {
    hi = __float2half_rn(v);
    lo = __float2half_rn(v - __half2float(hi));
}
__device__ __forceinline__ void mma_f16(float* c, const uint32_t* a, const uint32_t* b) {
    asm volatile(
        "mma.sync.aligned.m16n8k16.row.col.f32.f16.f16.f32 "
        "{%0,%1,%2,%3},{%4,%5,%6,%7},{%8,%9},{%0,%1,%2,%3};"
        : "+f"(c[0]), "+f"(c[1]), "+f"(c[2]), "+f"(c[3])
        : "r"(a[0]), "r"(a[1]), "r"(a[2]), "r"(a[3]), "r"(b[0]), "r"(b[1]));
}
__device__ __forceinline__ void cp16(uint32_t dst, const void* src) {
    asm volatile("cp.async.cg.shared.global [%0], [%1], 16;" :: "r"(dst), "l"(src));
}
#define LDSM_X4(r0, r1, r2, r3, addr) \
    asm volatile("ldmatrix.sync.aligned.m8n8.x4.shared.b16 {%0,%1,%2,%3}, [%4];" \
        : "=r"(r0), "=r"(r1), "=r"(r2), "=r"(r3) : "r"(addr))

// ---------------- f32 scratch ------------------------------------------------
__device__ float g_obj_probs[NN * NOC_];
__device__ float g_fo[NN * HD];
__device__ float g_h_obj[NN * HD];
__device__ float g_h_rel[RR * HD];
__device__ float g_xw_rel[RR * 3 * HD];
__device__ float g_hmhu[RR * 3 * HD];       // also reused as padded rel-cls out
__device__ float g_z_rel[RR * HD];
__device__ float g_xw_obj[NN * 3 * HD];     // also reused as padded obj-cls out
__device__ float g_hu_obj[NN * 2 * HD];
__device__ float g_z_obj[NN * HD];
__device__ float g_sp[NN * NOC_];
__device__ float g_wcomb[HD * 3 * HD];
__device__ float g_bcr[128];
__device__ float g_bco[256];
__device__ unsigned char g_keep[150 * NN];
__device__ int g_s_idx[RR];
__device__ int g_o_idx[RR];

// ---------------- fp16 plane scratch -----------------------------------------
__device__ __half g_Pa_h[RR * OBJD], g_Pa_l[RR * OBJD];
__device__ __half g_Ps_h[RR * HD],  g_Ps_l[RR * HD];
__device__ __half g_Ph_h[RR * HD],  g_Ph_l[RR * HD];
__device__ __half g_Po1_h[NN * HD], g_Po1_l[NN * HD];
__device__ __half g_Po2_h[NN * HD], g_Po2_l[NN * HD];
__device__ __half g_Po3_h[NN * HD], g_Po3_l[NN * HD];
// weight planes, [N,K]
__device__ __half g_Wop_h[HD * OBJD], g_Wop_l[HD * OBJD];
__device__ __half g_Wrp_h[HD * OBJD], g_Wrp_l[HD * OBJD];
__device__ __half g_Wcb_h[3 * HD * HD], g_Wcb_l[3 * HD * HD];
__device__ __half g_Wct_h[3 * HD * HD], g_Wct_l[3 * HD * HD];
__device__ __half g_Ugr2_h[HD * HD],   g_Ugr2_l[HD * HD];
__device__ __half g_Wgo_h[3 * HD * HD], g_Wgo_l[3 * HD * HD];
__device__ __half g_Ugo_h[3 * HD * HD], g_Ugo_l[3 * HD * HD];
__device__ __half g_Wcr_h[128 * HD], g_Wcr_l[128 * HD];   // padded rel classifier
__device__ __half g_Wco_h[256 * HD], g_Wco_l[256 * HD];   // padded obj classifier

// ============================================================================
// fp16 3-pass GEMM body (hi/lo planes), ldmatrix fragments.
// mode 0: C = A@B^T (+bias), optional fp16 plane out.
// mode 1: GRU-fin fusion: h = (1-z)*h + z*tanh(acc + XW3 + bias); writes Hh
//         (f32) and plane outputs Ch/Cl. C unused.
// ============================================================================
#define HROW 20
#define HPLW (128 * HROW)
#define HSTW (4 * HPLW)
#define HG_SMEM (2 * HSTW * 4)

struct HGArgs {
    const __half *Ah, *Al, *Bh, *Bl;
    float* C; int ldc;
    int M, N, K;
    const float* bias;
    __half *Ch, *Cl;
    int mode;
    const float* XW3; int ldxw;
    const float* Z;
    float* Hh;
};

__device__ __forceinline__ void hgemm_body(const HGArgs& a, int blk) {
    extern __shared__ uint32_t sm[];
    const int tid = threadIdx.x;
    const int lane = tid & 31;
    const int warp = tid >> 5;
    const int wm = warp >> 2;
    const int wn = warp & 3;
    const int lr = lane >> 2;
    const int lc = lane & 3;
    const int nx = a.N >> 7;
    const int m0 = (blk / nx) * 128;
    const int n0 = (blk % nx) * 128;
    const int K = a.K;
    const int KT = K / 32;

    const uint32_t sbase = (uint32_t)__cvta_generic_to_shared(sm);
    const int aRowOff = (wm * 64 + (lane & 15)) * HROW + (lane >> 4) * 4;
    const int bRowOff = (wn * 32 + (lane & 7) + ((lane >> 4) << 3)) * HROW
                      + (((lane >> 3) & 1) * 4);

    const __half* Ah = a.Ah;
    const __half* Al = a.Al;
    const __half* Bh = a.Bh;
    const __half* Bl = a.Bl;

    auto load_stage = [&](int kt, int buf) {
        const int k0 = kt * 32;
        uint32_t sb = sbase + (uint32_t)(buf * HSTW * 4);
#pragma unroll
        for (int i = 0; i < 2; i++) {
            int cid = tid * 2 + i;
            int row = cid >> 2, ch = cid & 3;
            uint32_t d = sb + (uint32_t)((row * HROW + ch * 4) * 4);
            size_t src = (size_t)(m0 + row) * K + k0 + ch * 8;
            cp16(d, Ah + src);
            cp16(d + HPLW * 4, Al + src);
        }
#pragma unroll
        for (int i = 0; i < 2; i++) {
            int cid = tid * 2 + i;
            int row = cid >> 2, ch = cid & 3;
            uint32_t d = sb + (uint32_t)((2 * HPLW + row * HROW + ch * 4) * 4);
            size_t src = (size_t)(n0 + row) * K + k0 + ch * 8;
            cp16(d, Bh + src);
            cp16(d + HPLW * 4, Bl + src);
        }
        asm volatile("cp.async.commit_group;");
    };

    float acc[4][4][4];
#pragma unroll
    for (int i = 0; i < 4; i++)
#pragma unroll
        for (int j = 0; j < 4; j++)
#pragma unroll
            for (int l = 0; l < 4; l++) acc[i][j][l] = 0.f;

    load_stage(0, 0);
    if (KT > 1) load_stage(1, 1);
    asm volatile("cp.async.wait_group 1;");
    __syncthreads();

    for (int kt = 0; kt < KT; kt++) {
        const int cur = kt & 1;
        const uint32_t uA = sbase + (uint32_t)(cur * HSTW * 4);
        const uint32_t uB = uA + (uint32_t)(2 * HPLW * 4);

#pragma unroll
        for (int wc = 0; wc < 16; wc += 8) {
            uint32_t aH[4][4], aL[4][4], bH[4][2], bL[4][2];
#pragma unroll
            for (int mt = 0; mt < 4; mt++) {
                uint32_t ad = uA + (uint32_t)((aRowOff + mt * 16 * HROW + wc) * 4);
                LDSM_X4(aH[mt][0], aH[mt][1], aH[mt][2], aH[mt][3], ad);
                LDSM_X4(aL[mt][0], aL[mt][1], aL[mt][2], aL[mt][3], ad + HPLW * 4);
            }
#pragma unroll
            for (int pr = 0; pr < 2; pr++) {
                uint32_t bd = uB + (uint32_t)((bRowOff + pr * 16 * HROW + wc) * 4);
                LDSM_X4(bH[2 * pr][0], bH[2 * pr][1], bH[2 * pr + 1][0], bH[2 * pr + 1][1], bd);
                LDSM_X4(bL[2 * pr][0], bL[2 * pr][1], bL[2 * pr + 1][0], bL[2 * pr + 1][1],
                        bd + HPLW * 4);
            }
#pragma unroll
            for (int mt = 0; mt < 4; mt++)
#pragma unroll
                for (int nt = 0; nt < 4; nt++) {
                    mma_f16(acc[mt][nt], aH[mt], bH[nt]);
                    mma_f16(acc[mt][nt], aH[mt], bL[nt]);
                    mma_f16(acc[mt][nt], aL[mt], bH[nt]);
                }
        }
        __syncthreads();
        if (kt + 2 < KT) {
            load_stage(kt + 2, cur);
            asm volatile("cp.async.wait_group 1;");
        } else if (kt + 1 < KT) {
            asm volatile("cp.async.wait_group 0;");
        }
        __syncthreads();
    }

    if (a.mode == 0) {
#pragma unroll
        for (int mt = 0; mt < 4; mt++) {
            int gm0 = m0 + wm * 64 + mt * 16 + lr;
            int gm1 = gm0 + 8;
#pragma unroll
            for (int nt = 0; nt < 4; nt++) {
                int gn = n0 + wn * 32 + nt * 8 + lc * 2;
                float b0 = 0.f, b1 = 0.f;
                if (a.bias) { b0 = a.bias[gn]; b1 = a.bias[gn + 1]; }
                float2 v0 = make_float2(acc[mt][nt][0] + b0, acc[mt][nt][1] + b1);
                float2 v1 = make_float2(acc[mt][nt][2] + b0, acc[mt][nt][3] + b1);
                *(float2*)(a.C + (size_t)gm0 * a.ldc + gn) = v0;
                *(float2*)(a.C + (size_t)gm1 * a.ldc + gn) = v1;
                if (a.Ch) {
                    __half hx, lx, hy, ly;
                    split_h(v0.x, hx, lx); split_h(v0.y, hy, ly);
                    *(__half2*)(a.Ch + (size_t)gm0 * a.ldc + gn) = __halves2half2(hx, hy);
                    *(__half2*)(a.Cl + (size_t)gm0 * a.ldc + gn) = __halves2half2(lx, ly);
                    split_h(v1.x, hx, lx); split_h(v1.y, hy, ly);
                    *(__half2*)(a.Ch + (size_t)gm1 * a.ldc + gn) = __halves2half2(hx, hy);
                    *(__half2*)(a.Cl + (size_t)gm1 * a.ldc + gn) = __halves2half2(lx, ly);
                }
            }
        }
    } else {
        // GRU-fin fused epilogue: n = tanh(acc + XW3 + b); h = (1-z)h + z n
#pragma unroll
        for (int mt = 0; mt < 4; mt++) {
#pragma unroll
            for (int nt = 0; nt < 4; nt++) {
#pragma unroll
                for (int v = 0; v < 4; v++) {
                    int gm = m0 + wm * 64 + mt * 16 + lr + (v >> 1) * 8;
                    int gn = n0 + wn * 32 + nt * 8 + lc * 2 + (v & 1);
                    size_t off = (size_t)gm * a.ldc + gn;
                    float n = tanhf(acc[mt][nt][v] + a.XW3[(size_t)gm * a.ldxw + gn]
                                    + a.bias[gn]);
                    float z = a.Z[off];
                    float h = (1.f - z) * a.Hh[off] + z * n;
                    a.Hh[off] = h;
                    __half ph, pl;
                    split_h(h, ph, pl);
                    a.Ch[off] = ph;
                    a.Cl[off] = pl;
                }
            }
        }
    }
}

__global__ __launch_bounds__(256, 2) void hgemm_kernel(HGArgs a) {
    hgemm_body(a, blockIdx.x);
}
__global__ __launch_bounds__(256, 2) void hgemm_dual_kernel(HGArgs a, HGArgs b, int nblk_a) {
    int bx = blockIdx.x;
    if (bx < nblk_a) hgemm_body(a, bx);
    else hgemm_body(b, bx - nblk_a);
}

// ---------------- split kernels ---------------------------------------------
__global__ void asplit_kernel(const float2* __restrict__ in,
                              __half2* __restrict__ hi, __half2* __restrict__ lo, int n2) {
    int i = blockIdx.x * blockDim.x + threadIdx.x;
    if (i >= n2) return;
    float2 v = in[i];
    __half hx, lx, hy, ly;
    split_h(v.x, hx, lx);
    split_h(v.y, hy, ly);
    hi[i] = __halves2half2(hx, hy);
    lo[i] = __halves2half2(lx, ly);
}

// W [K, ldw] f32, cols [c0, c0+grid*32), bounds-checked vs wcols -> planes [*, K]
__global__ void wsplit_kernel(const float* __restrict__ W, int ldw, int c0, int wcols,
                              __half* __restrict__ Th, __half* __restrict__ Tl, int K) {
    __shared__ float t[32][33];
    int kb = blockIdx.y * 32, nb = blockIdx.x * 32;
    int tx = threadIdx.x, ty = threadIdx.y;
    int col = c0 + nb + tx;
#pragma unroll
    for (int i = 0; i < 32; i += 8)
        t[ty + i][tx] = (col < wcols) ? W[(size_t)(kb + ty + i) * ldw + col] : 0.f;
    __syncthreads();
#pragma unroll
    for (int i = 0; i < 32; i += 8) {
        int n = nb + ty + i, k = kb + tx;
        __half h, l;
        split_h(t[tx][ty + i], h, l);
        Th[(size_t)n * K + k] = h;
        Tl[(size_t)n * K + k] = l;
    }
}

__global__ void biaspad_kernel(const float* __restrict__ b, float* __restrict__ out,
                               int n, int npad) {
    int i = blockIdx.x * blockDim.x + threadIdx.x;
    if (i < npad) out[i] = (i < n) ? b[i] : 0.f;
}

__global__ void pack_kernel(const float* __restrict__ src, int lds,
                            float* __restrict__ dst, int ldd, int total) {
    int i = blockIdx.x * blockDim.x + threadIdx.x;
    if (i >= total) return;
    int r = i / ldd, c = i % ldd;
    dst[i] = src[(size_t)r * lds + c];
}

// ---------------- generic fp32 SGEMM (odd shapes) ----------------------------
__global__ __launch_bounds__(256) void sgemm_kernel(
    const float* __restrict__ A, int lda,
    const float* __restrict__ B, int ldb,
    float* __restrict__ C, int ldc,
    int M, int N, int K,
    const float* __restrict__ bias,
    const float* __restrict__ addm)
{
    __shared__ float As[8][132];
    __shared__ float Bs[8][128];
    const int tid = threadIdx.x;
    const int tx = tid & 15;
    const int ty = tid >> 4;
    const int m0 = blockIdx.y * 128;
    const int n0 = blockIdx.x * 128;

    float acc[8][8];
#pragma unroll
    for (int i = 0; i < 8; i++)
#pragma unroll
        for (int j = 0; j < 8; j++) acc[i][j] = 0.f;

    for (int k0 = 0; k0 < K; k0 += 8) {
#pragma unroll
        for (int l = 0; l < 4; l++) {
            int e = tid + l * 256;
            int r = e >> 3, c = e & 7;
            float v = 0.f;
            int gm = m0 + r, gk = k0 + c;
            if (gm < M && gk < K) v = A[(size_t)gm * lda + gk];
            As[c][r] = v;
        }
#pragma unroll
        for (int l = 0; l < 4; l++) {
            int e = tid + l * 256;
            int r = e >> 7, c = e & 127;
            float v = 0.f;
            int gk = k0 + r, gn = n0 + c;
            if (gk < K && gn < N) v = B[(size_t)gk * ldb + gn];
            Bs[r][c] = v;
        }
        __syncthreads();
#pragma unroll
        for (int k = 0; k < 8; k++) {
            float a[8], b[8];
#pragma unroll
            for (int i = 0; i < 8; i++) a[i] = As[k][ty * 8 + i];
#pragma unroll
            for (int j = 0; j < 8; j++) b[j] = Bs[k][tx * 8 + j];
#pragma unroll
            for (int i = 0; i < 8; i++)
#pragma unroll
                for (int j = 0; j < 8; j++)
                    acc[i][j] = fmaf(a[i], b[j], acc[i][j]);
        }
        __syncthreads();
    }
#pragma unroll
    for (int i = 0; i < 8; i++) {
        int gm = m0 + ty * 8 + i;
        if (gm >= M) continue;
#pragma unroll
        for (int j = 0; j < 8; j++) {
            int gn = n0 + tx * 8 + j;
            if (gn >= N) continue;
            float v = acc[i][j];
            if (bias) v += bias[gn];
            if (addm) v += addm[(size_t)gm * ldc + gn];
            C[(size_t)gm * ldc + gn] = v;
        }
    }
}

// ---------------- decode rel_inds --------------------------------------------
__global__ __launch_bounds__(1024) void decode_rel_kernel(const void* rel_raw) {
    __shared__ int s_or;
    int tid = threadIdx.x;
    if (tid == 0) s_or = 0;
    __syncthreads();
    const int* v32 = (const int*)rel_raw;
    int acc = 0;
    for (int i = tid; i < (3 * RR) / 2; i += 1024) acc |= v32[2 * i + 1];
    if (acc) atomicOr(&s_or, 1);
    __syncthreads();
    bool is64 = (s_or == 0);
    if (is64) {
        const long long* v = (const long long*)rel_raw;
        for (int r = tid; r < RR; r += 1024) {
            g_s_idx[r] = (int)v[3 * r + 1];
            g_o_idx[r] = (int)v[3 * r + 2];
        }
    } else {
        for (int r = tid; r < RR; r += 1024) {
            g_s_idx[r] = v32[3 * r + 1];
            g_o_idx[r] = v32[3 * r + 2];
        }
    }
}

// ---------------- row softmax --------------------------------------------------
__global__ void softmax_kernel(const float* __restrict__ X, float* __restrict__ Y) {
    int row = blockIdx.x;
    int tid = threadIdx.x;
    __shared__ float red[256];
    const float* x = X + (size_t)row * NOC_;
    float m = -3.4e38f;
    for (int c = tid; c < NOC_; c += 256) m = fmaxf(m, x[c]);
    red[tid] = m; __syncthreads();
    for (int s = 128; s > 0; s >>= 1) {
        if (tid < s) red[tid] = fmaxf(red[tid], red[tid + s]);
        __syncthreads();
    }
    m = red[0]; __syncthreads();
    float sum = 0.f;
    for (int c = tid; c < NOC_; c += 256) sum += expf(x[c] - m);
    red[tid] = sum; __syncthreads();
    for (int s = 128; s > 0; s >>= 1) {
        if (tid < s) red[tid] += red[tid + s];
        __syncthreads();
    }
    float inv = 1.f / red[0];
    for (int c = tid; c < NOC_; c += 256)
        Y[(size_t)row * NOC_ + c] = expf(x[c] - m) * inv;
}

// ---------------- gather + split ------------------------------------------------
__global__ void gather_split_kernel(const float* __restrict__ Hobj,
                                    __half* __restrict__ Sh, __half* __restrict__ Sl) {
    int idx = blockIdx.x * blockDim.x + threadIdx.x;
    if (idx >= RR * HD) return;
    int r = idx >> 9;
    int c = idx & 511;
    float v = Hobj[(size_t)g_s_idx[r] * HD + c] + Hobj[(size_t)g_o_idx[r] * HD + c];
    __half h, l;
    split_h(v, h, l);
    Sh[idx] = h; Sl[idx] = l;
}

// ---------------- m_obj scatter -> planes ---------------------------------------
__global__ __launch_bounds__(512) void scatter_obj_kernel(const float* __restrict__ HM, int ldhm,
                                                          __half* __restrict__ Mh,
                                                          __half* __restrict__ Ml) {
    int obj = blockIdx.x;
    int c = threadIdx.x;
    int img = obj >> 6;
    int base = img * RPI_;
    __shared__ int ss[RPI_];
    __shared__ int oo[RPI_];
    for (int j = c; j < RPI_; j += 512) {
        ss[j] = g_s_idx[base + j];
        oo[j] = g_o_idx[base + j];
    }
    __syncthreads();
    float acc = 0.f;
    for (int j = 0; j < RPI_; j++) {
        if (ss[j] == obj) acc += HM[(size_t)(base + j) * ldhm + c];
        if (oo[j] == obj) acc += HM[(size_t)(base + j) * ldhm + c];
    }
    __half h, l;
    split_h(acc, h, l);
    Mh[(size_t)obj * HD + c] = h;
    Ml[(size_t)obj * HD + c] = l;
}

// ---------------- GRU z, r*h -> planes ------------------------------------------
__global__ void gru_zr_kernel(const float* __restrict__ XW, int ldxw,
                              const float* __restrict__ HU, int ldhu,
                              const float* __restrict__ b, const float* __restrict__ Hh,
                              float* __restrict__ Z,
                              __half* __restrict__ RHh, __half* __restrict__ RHl, int M) {
    int idx = blockIdx.x * blockDim.x + threadIdx.x;
    if (idx >= M * HD) return;
    int row = idx >> 9;
    int c = idx & 511;
    float z = XW[(size_t)row * ldxw + c] + HU[(size_t)row * ldhu + c] + b[c];
    float r = XW[(size_t)row * ldxw + 512 + c] + HU[(size_t)row * ldhu + 512 + c] + b[512 + c];
    z = 1.f / (1.f + expf(-z));
    r = 1.f / (1.f + expf(-r));
    Z[idx] = z;
    __half h, l;
    split_h(r * Hh[idx], h, l);
    RHh[idx] = h; RHl[idx] = l;
}

// ---------------- NMS ------------------------------------------------------------
__global__ __launch_bounds__(512) void nms_kernel(const float* __restrict__ SP,
                                                  const float* __restrict__ BOX,
                                                  unsigned char* __restrict__ KEEP) {
    int cls = blockIdx.x + 1;
    int tid = threadIdx.x;
    __shared__ float sc[NN];
    __shared__ int sidx[NN];
    __shared__ float bx[NN][4];
    __shared__ float area[NN];
    __shared__ unsigned char keep[NN];

    sc[tid] = SP[(size_t)tid * NOC_ + cls];
    sidx[tid] = tid;
    __syncthreads();

    for (int k = 2; k <= NN; k <<= 1) {
        for (int j = k >> 1; j > 0; j >>= 1) {
            int ixj = tid ^ j;
            if (ixj > tid) {
                float s1 = sc[tid], s2 = sc[ixj];
                int i1 = sidx[tid], i2 = sidx[ixj];
                bool dir = ((tid & k) == 0);
                bool precBA = (s2 > s1) || (s2 == s1 && i2 < i1);
                if (precBA == dir) {
                    sc[tid] = s2; sc[ixj] = s1;
                    sidx[tid] = i2; sidx[ixj] = i1;
                }
            }
            __syncthreads();
        }
    }

    int oi = sidx[tid];
    float x1 = BOX[((size_t)oi * NOC_ + cls) * 4 + 0];
    float y1 = BOX[((size_t)oi * NOC_ + cls) * 4 + 1];
    float x2 = BOX[((size_t)oi * NOC_ + cls) * 4 + 2];
    float y2 = BOX[((size_t)oi * NOC_ + cls) * 4 + 3];
    bx[tid][0] = x1; bx[tid][1] = y1; bx[tid][2] = x2; bx[tid][3] = y2;
    area[tid] = (x2 - x1) * (y2 - y1);
    keep[tid] = 1;
    __syncthreads();

    for (int i = 0; i < NN - 1; i++) {
        if (tid > i && keep[i] && keep[tid]) {
            float lx = fmaxf(bx[i][0], x1);
            float ly = fmaxf(bx[i][1], y1);
            float rx = fminf(bx[i][2], x2);
            float ry = fminf(bx[i][3], y2);
            float w = fmaxf(rx - lx, 0.f);
            float h = fmaxf(ry - ly, 0.f);
            float inter = w * h;
            float iou = inter / (area[i] + area[tid] - inter + 1e-9f);
            if (iou > IOU_THR_) keep[tid] = 0;
        }
        __syncthreads();
    }
    KEEP[(size_t)(cls - 1) * NN + oi] = keep[tid];
}

// ---------------- obj_preds -------------------------------------------------------
__global__ void preds_kernel(const float* __restrict__ SP, const unsigned char* __restrict__ KEEP,
                             float* __restrict__ out) {
    int n = blockIdx.x * blockDim.x + threadIdx.x;
    if (n >= NN) return;
    float best = -1.f;
    int bi = 0;
    for (int c = 0; c < 150; c++) {
        float v = KEEP[(size_t)c * NN + n] ? SP[(size_t)n * NOC_ + c + 1] : 0.f;
        if (v > best) { best = v; bi = c; }
    }
    out[n] = (float)(bi + 1);
}

// ---------------- host orchestration ----------------------------------------------
static void sgemm(const float* A, int lda, const float* B, int ldb,
                  float* C, int ldc, int M, int N, int K,
                  const float* bias, const float* addm) {
    dim3 g((N + 127) / 128, (M + 127) / 128);
    sgemm_kernel<<<g, 256>>>(A, lda, B, ldb, C, ldc, M, N, K, bias, addm);
}

struct Scratch {
    float *OBJ_PROBS, *FO, *HOBJ, *HREL, *XWR, *HMHU, *ZR;
    float *XWO, *HUO, *ZO, *SP, *WCOMB, *BCR, *BCO;
    unsigned char* KEEP;
    __half *Pa_h, *Pa_l, *Ps_h, *Ps_l, *Ph_h, *Ph_l;
    __half *Po1_h, *Po1_l, *Po2_h, *Po2_l, *Po3_h, *Po3_l;
    __half *Wop_h, *Wop_l, *Wrp_h, *Wrp_l, *Wcb_h, *Wcb_l, *Wct_h, *Wct_l;
    __half *Ugr2_h, *Ugr2_l, *Wgo_h, *Wgo_l, *Ugo_h, *Ugo_l;
    __half *Wcr_h, *Wcr_l, *Wco_h, *Wco_l;
    bool init = false;
};
static Scratch g_sc;

static void init_scratch() {
    if (g_sc.init) return;
    void* p;
#define GET(sym, fld, T) cudaGetSymbolAddress(&p, sym); g_sc.fld = (T*)p;
    GET(g_obj_probs, OBJ_PROBS, float)
    GET(g_fo, FO, float)
    GET(g_h_obj, HOBJ, float)
    GET(g_h_rel, HREL, float)
    GET(g_xw_rel, XWR, float)
    GET(g_hmhu, HMHU, float)
    GET(g_z_rel, ZR, float)
    GET(g_xw_obj, XWO, float)
    GET(g_hu_obj, HUO, float)
    GET(g_z_obj, ZO, float)
    GET(g_sp, SP, float)
    GET(g_wcomb, WCOMB, float)
    GET(g_bcr, BCR, float)
    GET(g_bco, BCO, float)
    GET(g_keep, KEEP, unsigned char)
    GET(g_Pa_h, Pa_h, __half) GET(g_Pa_l, Pa_l, __half)
    GET(g_Ps_h, Ps_h, __half) GET(g_Ps_l, Ps_l, __half)
    GET(g_Ph_h, Ph_h, __half) GET(g_Ph_l, Ph_l, __half)
    GET(g_Po1_h, Po1_h, __half) GET(g_Po1_l, Po1_l, __half)
    GET(g_Po2_h, Po2_h, __half) GET(g_Po2_l, Po2_l, __half)
    GET(g_Po3_h, Po3_h, __half) GET(g_Po3_l, Po3_l, __half)
    GET(g_Wop_h, Wop_h, __half) GET(g_Wop_l, Wop_l, __half)
    GET(g_Wrp_h, Wrp_h, __half) GET(g_Wrp_l, Wrp_l, __half)
    GET(g_Wcb_h, Wcb_h, __half) GET(g_Wcb_l, Wcb_l, __half)
    GET(g_Wct_h, Wct_h, __half) GET(g_Wct_l, Wct_l, __half)
    GET(g_Ugr2_h, Ugr2_h, __half) GET(g_Ugr2_l, Ugr2_l, __half)
    GET(g_Wgo_h, Wgo_h, __half) GET(g_Wgo_l, Wgo_l, __half)
    GET(g_Ugo_h, Ugo_h, __half) GET(g_Ugo_l, Ugo_l, __half)
    GET(g_Wcr_h, Wcr_h, __half) GET(g_Wcr_l, Wcr_l, __half)
    GET(g_Wco_h, Wco_h, __half) GET(g_Wco_l, Wco_l, __half)
#undef GET
    cudaFuncSetAttribute(hgemm_kernel, cudaFuncAttributeMaxDynamicSharedMemorySize, HG_SMEM);
    cudaFuncSetAttribute(hgemm_dual_kernel, cudaFuncAttributeMaxDynamicSharedMemorySize, HG_SMEM);
    g_sc.init = true;
}

static HGArgs mkargs(const __half* Ah, const __half* Al, const __half* Bh, const __half* Bl,
                     float* C, int ldc, int M, int N, int K, const float* bias,
                     __half* Ch = nullptr, __half* Cl = nullptr) {
    HGArgs a;
    a.Ah = Ah; a.Al = Al; a.Bh = Bh; a.Bl = Bl;
    a.C = C; a.ldc = ldc; a.M = M; a.N = N; a.K = K;
    a.bias = bias; a.Ch = Ch; a.Cl = Cl;
    a.mode = 0; a.XW3 = nullptr; a.ldxw = 0; a.Z = nullptr; a.Hh = nullptr;
    return a;
}

static void hgemm1(const HGArgs& a) {
    hgemm_kernel<<<(a.M / 128) * (a.N / 128), 256, HG_SMEM>>>(a);
}
static void hgemm2(const HGArgs& a, const HGArgs& b) {
    int na = (a.M / 128) * (a.N / 128);
    int nb = (b.M / 128) * (b.N / 128);
    hgemm_dual_kernel<<<na + nb, 256, HG_SMEM>>>(a, b, na);
}

static void asplit(const float* A, __half* hi, __half* lo, int n) {
    int n2 = n / 2;
    asplit_kernel<<<(n2 + 255) / 256, 256>>>((const float2*)A, (__half2*)hi, (__half2*)lo, n2);
}

static void wsplit(const float* W, int ldw, int c0, int wcols,
                   __half* Th, __half* Tl, int K, int ncols) {
    dim3 g(ncols / 32, K / 32);
    wsplit_kernel<<<g, dim3(32, 8)>>>(W, ldw, c0, wcols, Th, Tl, K);
}

extern "C" void kernel_launch(void* const* d_in, const int* in_sizes, int n_in,
                              void* d_out, int out_size) {
    (void)in_sizes; (void)n_in; (void)out_size;
    init_scratch();

    const float* obj_fmaps  = (const float*)d_in[1];
    const float* obj_logits = (const float*)d_in[2];
    const void*  rel_raw    = d_in[3];
    const float* vr         = (const float*)d_in[4];
    const float* boxes      = (const float*)d_in[5];
    const float* W_obj_proj = (const float*)d_in[6];
    const float* b_obj_proj = (const float*)d_in[7];
    const float* W_rel_proj = (const float*)d_in[8];
    const float* b_rel_proj = (const float*)d_in[9];
    const float* W_emb      = (const float*)d_in[10];
    const float* W_msg_rel  = (const float*)d_in[11];
    const float* W_msg_obj  = (const float*)d_in[12];
    const float* W_gru_obj  = (const float*)d_in[13];
    const float* U_gru_obj  = (const float*)d_in[14];
    const float* b_gru_obj  = (const float*)d_in[15];
    const float* W_gru_rel  = (const float*)d_in[16];
    const float* U_gru_rel  = (const float*)d_in[17];
    const float* b_gru_rel  = (const float*)d_in[18];
    const float* W_cls_rel  = (const float*)d_in[19];
    const float* b_cls_rel  = (const float*)d_in[20];
    const float* W_cls_obj  = (const float*)d_in[21];
    const float* b_cls_obj  = (const float*)d_in[22];

    float* out_obj_logits = (float*)d_out;
    float* out_preds      = out_obj_logits + NN * NOC_;
    float* out_rel_logits = out_preds + NN;

    // 0. decode rel indices; weight planes
    decode_rel_kernel<<<1, 1024>>>(rel_raw);
    wsplit(W_obj_proj, HD, 0, HD, g_sc.Wop_h, g_sc.Wop_l, OBJD, HD);
    wsplit(W_rel_proj, HD, 0, HD, g_sc.Wrp_h, g_sc.Wrp_l, OBJD, HD);
    wsplit(W_msg_obj, HD, 0, HD, g_sc.Wct_h, g_sc.Wct_l, HD, HD);
    wsplit(U_gru_rel, 3 * HD, 0, 3 * HD, g_sc.Wct_h + (size_t)HD * HD,
           g_sc.Wct_l + (size_t)HD * HD, HD, 2 * HD);
    wsplit(U_gru_rel, 3 * HD, 2 * HD, 3 * HD, g_sc.Ugr2_h, g_sc.Ugr2_l, HD, HD);
    wsplit(W_gru_obj, 3 * HD, 0, 3 * HD, g_sc.Wgo_h, g_sc.Wgo_l, HD, 3 * HD);
    wsplit(U_gru_obj, 3 * HD, 0, 3 * HD, g_sc.Ugo_h, g_sc.Ugo_l, HD, 3 * HD);
    // padded classifier planes + biases
    wsplit(W_cls_rel, NRC_, 0, NRC_, g_sc.Wcr_h, g_sc.Wcr_l, HD, 128);
    wsplit(W_cls_obj, NOC_, 0, NOC_, g_sc.Wco_h, g_sc.Wco_l, HD, 256);
    biaspad_kernel<<<1, 128>>>(b_cls_rel, g_sc.BCR, NRC_, 128);
    biaspad_kernel<<<1, 256>>>(b_cls_obj, g_sc.BCO, NOC_, 256);
    // WCOMB = W_msg_rel @ W_gru_rel (f32), then planes
    sgemm(W_msg_rel, HD, W_gru_rel, 3 * HD, g_sc.WCOMB, 3 * HD, HD, 3 * HD, HD, nullptr, nullptr);
    wsplit(g_sc.WCOMB, 3 * HD, 0, 3 * HD, g_sc.Wcb_h, g_sc.Wcb_l, HD, 3 * HD);

    // 1. obj_probs
    softmax_kernel<<<NN, 256>>>(obj_logits, g_sc.OBJ_PROBS);

    // 2. fo = obj_fmaps @ W_obj_proj + b
    asplit(obj_fmaps, g_sc.Pa_h, g_sc.Pa_l, NN * OBJD);
    hgemm1(mkargs(g_sc.Pa_h, g_sc.Pa_l, g_sc.Wop_h, g_sc.Wop_l, g_sc.FO, HD,
                  NN, HD, OBJD, b_obj_proj));

    // 3. h_obj = fo + obj_probs @ W_emb  (SIMT), then planes
    sgemm(g_sc.OBJ_PROBS, NOC_, W_emb, HD, g_sc.HOBJ, HD, NN, HD, NOC_, nullptr, g_sc.FO);
    asplit(g_sc.HOBJ, g_sc.Po2_h, g_sc.Po2_l, NN * HD);

    // 4. h_rel = vr @ W_rel_proj + b  (+ planes)
    asplit(vr, g_sc.Pa_h, g_sc.Pa_l, RR * OBJD);
    hgemm1(mkargs(g_sc.Pa_h, g_sc.Pa_l, g_sc.Wrp_h, g_sc.Wrp_l, g_sc.HREL, HD,
                  RR, HD, OBJD, b_rel_proj, g_sc.Ph_h, g_sc.Ph_l));

    const int EW_REL = (RR * HD + 255) / 256;
    const int EW_OBJ = (NN * HD + 255) / 256;
    const __half* Ugo2_h = g_sc.Ugo_h + (size_t)2 * HD * HD;
    const __half* Ugo2_l = g_sc.Ugo_l + (size_t)2 * HD * HD;

    for (int t = 0; t < TSTEPS; t++) {
        // XWR = SUMSO @ WCOMB ; HMHU = h_rel @ WCAT   (one dual launch)
        gather_split_kernel<<<EW_REL, 256>>>(g_sc.HOBJ, g_sc.Ps_h, g_sc.Ps_l);
        hgemm2(mkargs(g_sc.Ps_h, g_sc.Ps_l, g_sc.Wcb_h, g_sc.Wcb_l, g_sc.XWR, 3 * HD,
                      RR, 3 * HD, HD, nullptr),
               mkargs(g_sc.Ph_h, g_sc.Ph_l, g_sc.Wct_h, g_sc.Wct_l, g_sc.HMHU, 3 * HD,
                      RR, 3 * HD, HD, nullptr));
        scatter_obj_kernel<<<NN, 512>>>(g_sc.HMHU, 3 * HD, g_sc.Po1_h, g_sc.Po1_l);

        // GRU rel: zr then NU-GEMM with fused fin epilogue
        gru_zr_kernel<<<EW_REL, 256>>>(g_sc.XWR, 3 * HD, g_sc.HMHU + HD, 3 * HD,
                                       b_gru_rel, g_sc.HREL, g_sc.ZR, g_sc.Ps_h, g_sc.Ps_l, RR);
        {
            HGArgs a = mkargs(g_sc.Ps_h, g_sc.Ps_l, g_sc.Ugr2_h, g_sc.Ugr2_l,
                              nullptr, HD, RR, HD, HD, b_gru_rel + 2 * HD,
                              g_sc.Ph_h, g_sc.Ph_l);
            a.mode = 1; a.XW3 = g_sc.XWR + 2 * HD; a.ldxw = 3 * HD;
            a.Z = g_sc.ZR; a.Hh = g_sc.HREL;
            hgemm1(a);
        }

        // GRU obj: XWO + HUO dual, zr, NU-GEMM fused fin
        hgemm2(mkargs(g_sc.Po1_h, g_sc.Po1_l, g_sc.Wgo_h, g_sc.Wgo_l, g_sc.XWO, 3 * HD,
                      NN, 3 * HD, HD, nullptr),
               mkargs(g_sc.Po2_h, g_sc.Po2_l, g_sc.Ugo_h, g_sc.Ugo_l, g_sc.HUO, 2 * HD,
                      NN, 2 * HD, HD, nullptr));
        gru_zr_kernel<<<EW_OBJ, 256>>>(g_sc.XWO, 3 * HD, g_sc.HUO, 2 * HD,
                                       b_gru_obj, g_sc.HOBJ, g_sc.ZO, g_sc.Po3_h, g_sc.Po3_l, NN);
        {
            HGArgs a = mkargs(g_sc.Po3_h, g_sc.Po3_l, Ugo2_h, Ugo2_l,
                              nullptr, HD, NN, HD, HD, b_gru_obj + 2 * HD,
                              g_sc.Po2_h, g_sc.Po2_l);
            a.mode = 1; a.XW3 = g_sc.XWO + 2 * HD; a.ldxw = 3 * HD;
            a.Z = g_sc.ZO; a.Hh = g_sc.HOBJ;
            hgemm1(a);
        }
    }

    // classifiers on tensor path (padded N), then pack
    hgemm2(mkargs(g_sc.Ph_h, g_sc.Ph_l, g_sc.Wcr_h, g_sc.Wcr_l, g_sc.HMHU, 128,
                  RR, 128, HD, g_sc.BCR),
           mkargs(g_sc.Po2_h, g_sc.Po2_l, g_sc.Wco_h, g_sc.Wco_l, g_sc.XWO, 256,
                  NN, 256, HD, g_sc.BCO));
    pack_kernel<<<(RR * NRC_ + 255) / 256, 256>>>(g_sc.HMHU, 128, out_rel_logits, NRC_, RR * NRC_);
    pack_kernel<<<(NN * NOC_ + 255) / 256, 256>>>(g_sc.XWO, 256, out_obj_logits, NOC_, NN * NOC_);

    // softmax -> NMS -> preds
    softmax_kernel<<<NN, 256>>>(out_obj_logits, g_sc.SP);
    nms_kernel<<<150, 512>>>(g_sc.SP, boxes, g_sc.KEEP);
    preds_kernel<<<(NN + 255) / 256, 256>>>(g_sc.SP, g_sc.KEEP, out_preds);
}

// round 11
// speedup vs baseline: 2.5223x; 1.3100x over previous
#include <cuda_runtime.h>
#include <cuda_bf16.h>
#include <cuda_fp16.h>
#include <math.h>
#include <stdint.h>

// ---------------- problem constants ----------------
#define BIMG 8
#define OPI_ 64
#define RPI_ 1024
#define NN 512
#define RR 8192
#define OBJD 4096
#define HD 512
#define NOC_ 151
#define NRC_ 51
#define TSTEPS 3
#define IOU_THR_ 0.3f
#define KEMB 160   // padded K for W_emb GEMM

// ---------------- helpers ----------------------------------------------------
__device__ __forceinline__ void split_h(float v, __half& hi, __half& lo) {
    hi = __float2half_rn(v);
    lo = __float2half_rn(v - __half2float(hi));
}
__device__ __forceinline__ void mma_f16(float* c, const uint32_t* a, const uint32_t* b) {
    asm volatile(
        "mma.sync.aligned.m16n8k16.row.col.f32.f16.f16.f32 "
        "{%0,%1,%2,%3},{%4,%5,%6,%7},{%8,%9},{%0,%1,%2,%3};"
        : "+f"(c[0]), "+f"(c[1]), "+f"(c[2]), "+f"(c[3])
        : "r"(a[0]), "r"(a[1]), "r"(a[2]), "r"(a[3]), "r"(b[0]), "r"(b[1]));
}
__device__ __forceinline__ void cp16(uint32_t dst, const void* src) {
    asm volatile("cp.async.cg.shared.global [%0], [%1], 16;" :: "r"(dst), "l"(src));
}
#define LDSM_X4(r0, r1, r2, r3, addr) \
    asm volatile("ldmatrix.sync.aligned.m8n8.x4.shared.b16 {%0,%1,%2,%3}, [%4];" \
        : "=r"(r0), "=r"(r1), "=r"(r2), "=r"(r3) : "r"(addr))

// ---------------- f32 scratch ------------------------------------------------
__device__ float g_fo[NN * HD];
__device__ float g_h_obj[NN * HD];
__device__ float g_h_rel[RR * HD];
__device__ float g_xw_rel[RR * 3 * HD];
__device__ float g_hmhu[RR * 3 * HD];       // also reused as padded rel-cls out
__device__ float g_hw[NN * 3 * HD];
__device__ float g_z_rel[RR * HD];
__device__ float g_xw_obj[NN * 3 * HD];     // also reused as padded obj-cls out
__device__ float g_hu_obj[NN * 2 * HD];
__device__ float g_z_obj[NN * HD];
__device__ float g_sp[NN * NOC_];
__device__ float g_wcomb[HD * 3 * HD];
__device__ float g_bcr[128];
__device__ float g_bco[256];
__device__ unsigned char g_keep[150 * NN];
__device__ int g_s_idx[RR];
__device__ int g_o_idx[RR];

// ---------------- fp16 plane scratch -----------------------------------------
__device__ __half g_Pa_h[RR * OBJD], g_Pa_l[RR * OBJD];     // vr planes
__device__ __half g_Pb_h[NN * OBJD], g_Pb_l[NN * OBJD];     // obj_fmaps planes
__device__ __half g_Ps_h[RR * HD],  g_Ps_l[RR * HD];        // RHR planes
__device__ __half g_Ph_h[RR * HD],  g_Ph_l[RR * HD];        // HREL planes
__device__ __half g_Po1_h[NN * HD], g_Po1_l[NN * HD];       // MOBJ
__device__ __half g_Po2_h[NN * HD], g_Po2_l[NN * HD];       // HOBJ
__device__ __half g_Po3_h[NN * HD], g_Po3_l[NN * HD];       // RHO
__device__ __half g_OP_h[NN * KEMB], g_OP_l[NN * KEMB];     // softmax probs padded
// weight planes, [N,K]
__device__ __half g_Wop_h[HD * OBJD], g_Wop_l[HD * OBJD];
__device__ __half g_Wrp_h[HD * OBJD], g_Wrp_l[HD * OBJD];
__device__ __half g_Wemb_h[HD * KEMB], g_Wemb_l[HD * KEMB];
__device__ __half g_Wcb_h[3 * HD * HD], g_Wcb_l[3 * HD * HD];
__device__ __half g_Wct_h[3 * HD * HD], g_Wct_l[3 * HD * HD];
__device__ __half g_Ugr2_h[HD * HD],   g_Ugr2_l[HD * HD];
__device__ __half g_Wgo_h[3 * HD * HD], g_Wgo_l[3 * HD * HD];
__device__ __half g_Ugo_h[3 * HD * HD], g_Ugo_l[3 * HD * HD];
__device__ __half g_Wcr_h[128 * HD], g_Wcr_l[128 * HD];
__device__ __half g_Wco_h[256 * HD], g_Wco_l[256 * HD];

// ============================================================================
// fp16 3-pass GEMM body (hi/lo planes), ldmatrix fragments.
// mode 0: C = A@B^T (+bias) (+addm), optional fp16 plane out.
// mode 1: GRU-fin fusion.
// ============================================================================
#define HROW 20
#define HPLW (128 * HROW)
#define HSTW (4 * HPLW)
#define HG_SMEM (2 * HSTW * 4)

struct HGArgs {
    const __half *Ah, *Al, *Bh, *Bl;
    float* C; int ldc;
    int M, N, K;
    const float* bias;
    const float* addm;
    __half *Ch, *Cl;
    int mode;
    const float* XW3; int ldxw;
    const float* Z;
    float* Hh;
};

__device__ __forceinline__ void hgemm_body(const HGArgs& a, int blk) {
    extern __shared__ uint32_t sm[];
    const int tid = threadIdx.x;
    const int lane = tid & 31;
    const int warp = tid >> 5;
    const int wm = warp >> 2;
    const int wn = warp & 3;
    const int lr = lane >> 2;
    const int lc = lane & 3;
    const int nx = a.N >> 7;
    const int m0 = (blk / nx) * 128;
    const int n0 = (blk % nx) * 128;
    const int K = a.K;
    const int KT = K / 32;

    const uint32_t sbase = (uint32_t)__cvta_generic_to_shared(sm);
    const int aRowOff = (wm * 64 + (lane & 15)) * HROW + (lane >> 4) * 4;
    const int bRowOff = (wn * 32 + (lane & 7) + ((lane >> 4) << 3)) * HROW
                      + (((lane >> 3) & 1) * 4);

    const __half* Ah = a.Ah;
    const __half* Al = a.Al;
    const __half* Bh = a.Bh;
    const __half* Bl = a.Bl;

    auto load_stage = [&](int kt, int buf) {
        const int k0 = kt * 32;
        uint32_t sb = sbase + (uint32_t)(buf * HSTW * 4);
#pragma unroll
        for (int i = 0; i < 2; i++) {
            int cid = tid * 2 + i;
            int row = cid >> 2, ch = cid & 3;
            uint32_t d = sb + (uint32_t)((row * HROW + ch * 4) * 4);
            size_t src = (size_t)(m0 + row) * K + k0 + ch * 8;
            cp16(d, Ah + src);
            cp16(d + HPLW * 4, Al + src);
        }
#pragma unroll
        for (int i = 0; i < 2; i++) {
            int cid = tid * 2 + i;
            int row = cid >> 2, ch = cid & 3;
            uint32_t d = sb + (uint32_t)((2 * HPLW + row * HROW + ch * 4) * 4);
            size_t src = (size_t)(n0 + row) * K + k0 + ch * 8;
            cp16(d, Bh + src);
            cp16(d + HPLW * 4, Bl + src);
        }
        asm volatile("cp.async.commit_group;");
    };

    float acc[4][4][4];
#pragma unroll
    for (int i = 0; i < 4; i++)
#pragma unroll
        for (int j = 0; j < 4; j++)
#pragma unroll
            for (int l = 0; l < 4; l++) acc[i][j][l] = 0.f;

    load_stage(0, 0);
    if (KT > 1) load_stage(1, 1);
    asm volatile("cp.async.wait_group 1;");
    __syncthreads();

    for (int kt = 0; kt < KT; kt++) {
        const int cur = kt & 1;
        const uint32_t uA = sbase + (uint32_t)(cur * HSTW * 4);
        const uint32_t uB = uA + (uint32_t)(2 * HPLW * 4);

#pragma unroll
        for (int wc = 0; wc < 16; wc += 8) {
            uint32_t aH[4][4], aL[4][4], bH[4][2], bL[4][2];
#pragma unroll
            for (int mt = 0; mt < 4; mt++) {
                uint32_t ad = uA + (uint32_t)((aRowOff + mt * 16 * HROW + wc) * 4);
                LDSM_X4(aH[mt][0], aH[mt][1], aH[mt][2], aH[mt][3], ad);
                LDSM_X4(aL[mt][0], aL[mt][1], aL[mt][2], aL[mt][3], ad + HPLW * 4);
            }
#pragma unroll
            for (int pr = 0; pr < 2; pr++) {
                uint32_t bd = uB + (uint32_t)((bRowOff + pr * 16 * HROW + wc) * 4);
                LDSM_X4(bH[2 * pr][0], bH[2 * pr][1], bH[2 * pr + 1][0], bH[2 * pr + 1][1], bd);
                LDSM_X4(bL[2 * pr][0], bL[2 * pr][1], bL[2 * pr + 1][0], bL[2 * pr + 1][1],
                        bd + HPLW * 4);
            }
#pragma unroll
            for (int mt = 0; mt < 4; mt++)
#pragma unroll
                for (int nt = 0; nt < 4; nt++) {
                    mma_f16(acc[mt][nt], aH[mt], bH[nt]);
                    mma_f16(acc[mt][nt], aH[mt], bL[nt]);
                    mma_f16(acc[mt][nt], aL[mt], bH[nt]);
                }
        }
        __syncthreads();
        if (kt + 2 < KT) {
            load_stage(kt + 2, cur);
            asm volatile("cp.async.wait_group 1;");
        } else if (kt + 1 < KT) {
            asm volatile("cp.async.wait_group 0;");
        }
        __syncthreads();
    }

    if (a.mode == 0) {
#pragma unroll
        for (int mt = 0; mt < 4; mt++) {
            int gm0 = m0 + wm * 64 + mt * 16 + lr;
            int gm1 = gm0 + 8;
#pragma unroll
            for (int nt = 0; nt < 4; nt++) {
                int gn = n0 + wn * 32 + nt * 8 + lc * 2;
                float b0 = 0.f, b1 = 0.f;
                if (a.bias) { b0 = a.bias[gn]; b1 = a.bias[gn + 1]; }
                float2 v0 = make_float2(acc[mt][nt][0] + b0, acc[mt][nt][1] + b1);
                float2 v1 = make_float2(acc[mt][nt][2] + b0, acc[mt][nt][3] + b1);
                if (a.addm) {
                    float2 m0v = *(const float2*)(a.addm + (size_t)gm0 * a.ldc + gn);
                    float2 m1v = *(const float2*)(a.addm + (size_t)gm1 * a.ldc + gn);
                    v0.x += m0v.x; v0.y += m0v.y;
                    v1.x += m1v.x; v1.y += m1v.y;
                }
                *(float2*)(a.C + (size_t)gm0 * a.ldc + gn) = v0;
                *(float2*)(a.C + (size_t)gm1 * a.ldc + gn) = v1;
                if (a.Ch) {
                    __half hx, lx, hy, ly;
                    split_h(v0.x, hx, lx); split_h(v0.y, hy, ly);
                    *(__half2*)(a.Ch + (size_t)gm0 * a.ldc + gn) = __halves2half2(hx, hy);
                    *(__half2*)(a.Cl + (size_t)gm0 * a.ldc + gn) = __halves2half2(lx, ly);
                    split_h(v1.x, hx, lx); split_h(v1.y, hy, ly);
                    *(__half2*)(a.Ch + (size_t)gm1 * a.ldc + gn) = __halves2half2(hx, hy);
                    *(__half2*)(a.Cl + (size_t)gm1 * a.ldc + gn) = __halves2half2(lx, ly);
                }
            }
        }
    } else {
#pragma unroll
        for (int mt = 0; mt < 4; mt++) {
#pragma unroll
            for (int nt = 0; nt < 4; nt++) {
#pragma unroll
                for (int v = 0; v < 4; v++) {
                    int gm = m0 + wm * 64 + mt * 16 + lr + (v >> 1) * 8;
                    int gn = n0 + wn * 32 + nt * 8 + lc * 2 + (v & 1);
                    size_t off = (size_t)gm * a.ldc + gn;
                    float n = tanhf(acc[mt][nt][v] + a.XW3[(size_t)gm * a.ldxw + gn]
                                    + a.bias[gn]);
                    float z = a.Z[off];
                    float h = (1.f - z) * a.Hh[off] + z * n;
                    a.Hh[off] = h;
                    __half ph, pl;
                    split_h(h, ph, pl);
                    a.Ch[off] = ph;
                    a.Cl[off] = pl;
                }
            }
        }
    }
}

__global__ __launch_bounds__(256, 2) void hgemm_kernel(HGArgs a) {
    hgemm_body(a, blockIdx.x);
}
__global__ __launch_bounds__(256, 2) void hgemm_dual_kernel(HGArgs a, HGArgs b, int na) {
    int bx = blockIdx.x;
    if (bx < na) hgemm_body(a, bx);
    else hgemm_body(b, bx - na);
}
__global__ __launch_bounds__(256, 2) void hgemm_tri_kernel(HGArgs a, HGArgs b, HGArgs c,
                                                           int na, int nab) {
    int bx = blockIdx.x;
    if (bx < na) hgemm_body(a, bx);
    else if (bx < nab) hgemm_body(b, bx - na);
    else hgemm_body(c, bx - nab);
}

// ---------------- split kernels ---------------------------------------------
__global__ void asplit_kernel(const float2* __restrict__ in,
                              __half2* __restrict__ hi, __half2* __restrict__ lo, int n2) {
    int i = blockIdx.x * blockDim.x + threadIdx.x;
    if (i >= n2) return;
    float2 v = in[i];
    __half hx, lx, hy, ly;
    split_h(v.x, hx, lx);
    split_h(v.y, hy, ly);
    hi[i] = __halves2half2(hx, hy);
    lo[i] = __halves2half2(lx, ly);
}

// W [wrows, ldw] f32, cols [c0, ...) -> planes [*, K] fp16 (zero padded)
__global__ void wsplit_kernel(const float* __restrict__ W, int ldw, int c0, int wcols, int wrows,
                              __half* __restrict__ Th, __half* __restrict__ Tl, int K) {
    __shared__ float t[32][33];
    int kb = blockIdx.y * 32, nb = blockIdx.x * 32;
    int tx = threadIdx.x, ty = threadIdx.y;
    int col = c0 + nb + tx;
#pragma unroll
    for (int i = 0; i < 32; i += 8) {
        int kr = kb + ty + i;
        t[ty + i][tx] = (col < wcols && kr < wrows) ? W[(size_t)kr * ldw + col] : 0.f;
    }
    __syncthreads();
#pragma unroll
    for (int i = 0; i < 32; i += 8) {
        int n = nb + ty + i, k = kb + tx;
        __half h, l;
        split_h(t[tx][ty + i], h, l);
        Th[(size_t)n * K + k] = h;
        Tl[(size_t)n * K + k] = l;
    }
}

__global__ void biaspad_kernel(const float* __restrict__ b, float* __restrict__ out,
                               int n, int npad) {
    int i = blockIdx.x * blockDim.x + threadIdx.x;
    if (i < npad) out[i] = (i < n) ? b[i] : 0.f;
}

__global__ void pack_kernel(const float* __restrict__ src, int lds,
                            float* __restrict__ dst, int ldd, int total) {
    int i = blockIdx.x * blockDim.x + threadIdx.x;
    if (i >= total) return;
    int r = i / ldd, c = i % ldd;
    dst[i] = src[(size_t)r * lds + c];
}

// ---------------- generic fp32 SGEMM (WCOMB only) -----------------------------
__global__ __launch_bounds__(256) void sgemm_kernel(
    const float* __restrict__ A, int lda,
    const float* __restrict__ B, int ldb,
    float* __restrict__ C, int ldc,
    int M, int N, int K)
{
    __shared__ float As[8][132];
    __shared__ float Bs[8][128];
    const int tid = threadIdx.x;
    const int tx = tid & 15;
    const int ty = tid >> 4;
    const int m0 = blockIdx.y * 128;
    const int n0 = blockIdx.x * 128;

    float acc[8][8];
#pragma unroll
    for (int i = 0; i < 8; i++)
#pragma unroll
        for (int j = 0; j < 8; j++) acc[i][j] = 0.f;

    for (int k0 = 0; k0 < K; k0 += 8) {
#pragma unroll
        for (int l = 0; l < 4; l++) {
            int e = tid + l * 256;
            int r = e >> 3, c = e & 7;
            float v = 0.f;
            int gm = m0 + r, gk = k0 + c;
            if (gm < M && gk < K) v = A[(size_t)gm * lda + gk];
            As[c][r] = v;
        }
#pragma unroll
        for (int l = 0; l < 4; l++) {
            int e = tid + l * 256;
            int r = e >> 7, c = e & 127;
            float v = 0.f;
            int gk = k0 + r, gn = n0 + c;
            if (gk < K && gn < N) v = B[(size_t)gk * ldb + gn];
            Bs[r][c] = v;
        }
        __syncthreads();
#pragma unroll
        for (int k = 0; k < 8; k++) {
            float a[8], b[8];
#pragma unroll
            for (int i = 0; i < 8; i++) a[i] = As[k][ty * 8 + i];
#pragma unroll
            for (int j = 0; j < 8; j++) b[j] = Bs[k][tx * 8 + j];
#pragma unroll
            for (int i = 0; i < 8; i++)
#pragma unroll
                for (int j = 0; j < 8; j++)
                    acc[i][j] = fmaf(a[i], b[j], acc[i][j]);
        }
        __syncthreads();
    }
#pragma unroll
    for (int i = 0; i < 8; i++) {
        int gm = m0 + ty * 8 + i;
        if (gm >= M) continue;
#pragma unroll
        for (int j = 0; j < 8; j++) {
            int gn = n0 + tx * 8 + j;
            if (gn >= N) continue;
            C[(size_t)gm * ldc + gn] = acc[i][j];
        }
    }
}

// ---------------- decode rel_inds --------------------------------------------
__global__ __launch_bounds__(1024) void decode_rel_kernel(const void* rel_raw) {
    __shared__ int s_or;
    int tid = threadIdx.x;
    if (tid == 0) s_or = 0;
    __syncthreads();
    const int* v32 = (const int*)rel_raw;
    int acc = 0;
    for (int i = tid; i < (3 * RR) / 2; i += 1024) acc |= v32[2 * i + 1];
    if (acc) atomicOr(&s_or, 1);
    __syncthreads();
    bool is64 = (s_or == 0);
    if (is64) {
        const long long* v = (const long long*)rel_raw;
        for (int r = tid; r < RR; r += 1024) {
            g_s_idx[r] = (int)v[3 * r + 1];
            g_o_idx[r] = (int)v[3 * r + 2];
        }
    } else {
        for (int r = tid; r < RR; r += 1024) {
            g_s_idx[r] = v32[3 * r + 1];
            g_o_idx[r] = v32[3 * r + 2];
        }
    }
}

// ---------------- softmax -> padded fp16 planes -------------------------------
__global__ void softmax_split_kernel(const float* __restrict__ X,
                                     __half* __restrict__ Ph, __half* __restrict__ Pl) {
    int row = blockIdx.x;
    int tid = threadIdx.x;
    __shared__ float red[256];
    const float* x = X + (size_t)row * NOC_;
    float m = -3.4e38f;
    for (int c = tid; c < NOC_; c += 256) m = fmaxf(m, x[c]);
    red[tid] = m; __syncthreads();
    for (int s = 128; s > 0; s >>= 1) {
        if (tid < s) red[tid] = fmaxf(red[tid], red[tid + s]);
        __syncthreads();
    }
    m = red[0]; __syncthreads();
    float sum = 0.f;
    for (int c = tid; c < NOC_; c += 256) sum += expf(x[c] - m);
    red[tid] = sum; __syncthreads();
    for (int s = 128; s > 0; s >>= 1) {
        if (tid < s) red[tid] += red[tid + s];
        __syncthreads();
    }
    float inv = 1.f / red[0];
    for (int c = tid; c < KEMB; c += 256) {
        float v = (c < NOC_) ? expf(x[c] - m) * inv : 0.f;
        __half h, l;
        split_h(v, h, l);
        Ph[(size_t)row * KEMB + c] = h;
        Pl[(size_t)row * KEMB + c] = l;
    }
}

// ---------------- plain row softmax (for SP) ----------------------------------
__global__ void softmax_kernel(const float* __restrict__ X, float* __restrict__ Y) {
    int row = blockIdx.x;
    int tid = threadIdx.x;
    __shared__ float red[256];
    const float* x = X + (size_t)row * NOC_;
    float m = -3.4e38f;
    for (int c = tid; c < NOC_; c += 256) m = fmaxf(m, x[c]);
    red[tid] = m; __syncthreads();
    for (int s = 128; s > 0; s >>= 1) {
        if (tid < s) red[tid] = fmaxf(red[tid], red[tid + s]);
        __syncthreads();
    }
    m = red[0]; __syncthreads();
    float sum = 0.f;
    for (int c = tid; c < NOC_; c += 256) sum += expf(x[c] - m);
    red[tid] = sum; __syncthreads();
    for (int s = 128; s > 0; s >>= 1) {
        if (tid < s) red[tid] += red[tid + s];
        __syncthreads();
    }
    float inv = 1.f / red[0];
    for (int c = tid; c < NOC_; c += 256)
        Y[(size_t)row * NOC_ + c] = expf(x[c] - m) * inv;
}

// ---------------- XWR[r] = HW[s_r] + HW[o_r]  (float4) ------------------------
__global__ void xwr_gather_kernel(const float4* __restrict__ HW, float4* __restrict__ XWR) {
    int i = blockIdx.x * blockDim.x + threadIdx.x;
    if (i >= RR * 384) return;   // 1536/4 = 384
    int r = i / 384;
    int c = i - r * 384;
    float4 a = HW[g_s_idx[r] * 384 + c];
    float4 b = HW[g_o_idx[r] * 384 + c];
    XWR[i] = make_float4(a.x + b.x, a.y + b.y, a.z + b.z, a.w + b.w);
}

// ---------------- m_obj scatter -> planes -------------------------------------
__global__ __launch_bounds__(512) void scatter_obj_kernel(const float* __restrict__ HM, int ldhm,
                                                          __half* __restrict__ Mh,
                                                          __half* __restrict__ Ml) {
    int obj = blockIdx.x;
    int c = threadIdx.x;
    int img = obj >> 6;
    int base = img * RPI_;
    __shared__ int ss[RPI_];
    __shared__ int oo[RPI_];
    for (int j = c; j < RPI_; j += 512) {
        ss[j] = g_s_idx[base + j];
        oo[j] = g_o_idx[base + j];
    }
    __syncthreads();
    float acc = 0.f;
    for (int j = 0; j < RPI_; j++) {
        if (ss[j] == obj) acc += HM[(size_t)(base + j) * ldhm + c];
        if (oo[j] == obj) acc += HM[(size_t)(base + j) * ldhm + c];
    }
    __half h, l;
    split_h(acc, h, l);
    Mh[(size_t)obj * HD + c] = h;
    Ml[(size_t)obj * HD + c] = l;
}

// ---------------- GRU z, r*h -> planes ----------------------------------------
__global__ void gru_zr_kernel(const float* __restrict__ XW, int ldxw,
                              const float* __restrict__ HU, int ldhu,
                              const float* __restrict__ b, const float* __restrict__ Hh,
                              float* __restrict__ Z,
                              __half* __restrict__ RHh, __half* __restrict__ RHl, int M) {
    int idx = blockIdx.x * blockDim.x + threadIdx.x;
    if (idx >= M * HD) return;
    int row = idx >> 9;
    int c = idx & 511;
    float z = XW[(size_t)row * ldxw + c] + HU[(size_t)row * ldhu + c] + b[c];
    float r = XW[(size_t)row * ldxw + 512 + c] + HU[(size_t)row * ldhu + 512 + c] + b[512 + c];
    z = 1.f / (1.f + expf(-z));
    r = 1.f / (1.f + expf(-r));
    Z[idx] = z;
    __half h, l;
    split_h(r * Hh[idx], h, l);
    RHh[idx] = h; RHl[idx] = l;
}

// ---------------- NMS ----------------------------------------------------------
__global__ __launch_bounds__(512) void nms_kernel(const float* __restrict__ SP,
                                                  const float* __restrict__ BOX,
                                                  unsigned char* __restrict__ KEEP) {
    int cls = blockIdx.x + 1;
    int tid = threadIdx.x;
    __shared__ float sc[NN];
    __shared__ int sidx[NN];
    __shared__ float bx[NN][4];
    __shared__ float area[NN];
    __shared__ unsigned char keep[NN];

    sc[tid] = SP[(size_t)tid * NOC_ + cls];
    sidx[tid] = tid;
    __syncthreads();

    for (int k = 2; k <= NN; k <<= 1) {
        for (int j = k >> 1; j > 0; j >>= 1) {
            int ixj = tid ^ j;
            if (ixj > tid) {
                float s1 = sc[tid], s2 = sc[ixj];
                int i1 = sidx[tid], i2 = sidx[ixj];
                bool dir = ((tid & k) == 0);
                bool precBA = (s2 > s1) || (s2 == s1 && i2 < i1);
                if (precBA == dir) {
                    sc[tid] = s2; sc[ixj] = s1;
                    sidx[tid] = i2; sidx[ixj] = i1;
                }
            }
            __syncthreads();
        }
    }

    int oi = sidx[tid];
    float x1 = BOX[((size_t)oi * NOC_ + cls) * 4 + 0];
    float y1 = BOX[((size_t)oi * NOC_ + cls) * 4 + 1];
    float x2 = BOX[((size_t)oi * NOC_ + cls) * 4 + 2];
    float y2 = BOX[((size_t)oi * NOC_ + cls) * 4 + 3];
    bx[tid][0] = x1; bx[tid][1] = y1; bx[tid][2] = x2; bx[tid][3] = y2;
    area[tid] = (x2 - x1) * (y2 - y1);
    keep[tid] = 1;
    __syncthreads();

    for (int i = 0; i < NN - 1; i++) {
        if (tid > i && keep[i] && keep[tid]) {
            float lx = fmaxf(bx[i][0], x1);
            float ly = fmaxf(bx[i][1], y1);
            float rx = fminf(bx[i][2], x2);
            float ry = fminf(bx[i][3], y2);
            float w = fmaxf(rx - lx, 0.f);
            float h = fmaxf(ry - ly, 0.f);
            float inter = w * h;
            float iou = inter / (area[i] + area[tid] - inter + 1e-9f);
            if (iou > IOU_THR_) keep[tid] = 0;
        }
        __syncthreads();
    }
    KEEP[(size_t)(cls - 1) * NN + oi] = keep[tid];
}

// ---------------- obj_preds -----------------------------------------------------
__global__ void preds_kernel(const float* __restrict__ SP, const unsigned char* __restrict__ KEEP,
                             float* __restrict__ out) {
    int n = blockIdx.x * blockDim.x + threadIdx.x;
    if (n >= NN) return;
    float best = -1.f;
    int bi = 0;
    for (int c = 0; c < 150; c++) {
        float v = KEEP[(size_t)c * NN + n] ? SP[(size_t)n * NOC_ + c + 1] : 0.f;
        if (v > best) { best = v; bi = c; }
    }
    out[n] = (float)(bi + 1);
}

// ---------------- host orchestration --------------------------------------------
struct Scratch {
    float *FO, *HOBJ, *HREL, *XWR, *HMHU, *HW, *ZR;
    float *XWO, *HUO, *ZO, *SP, *WCOMB, *BCR, *BCO;
    unsigned char* KEEP;
    __half *Pa_h, *Pa_l, *Pb_h, *Pb_l, *Ps_h, *Ps_l, *Ph_h, *Ph_l;
    __half *Po1_h, *Po1_l, *Po2_h, *Po2_l, *Po3_h, *Po3_l, *OP_h, *OP_l;
    __half *Wop_h, *Wop_l, *Wrp_h, *Wrp_l, *Wemb_h, *Wemb_l;
    __half *Wcb_h, *Wcb_l, *Wct_h, *Wct_l;
    __half *Ugr2_h, *Ugr2_l, *Wgo_h, *Wgo_l, *Ugo_h, *Ugo_l;
    __half *Wcr_h, *Wcr_l, *Wco_h, *Wco_l;
    bool init = false;
};
static Scratch g_sc;

static void init_scratch() {
    if (g_sc.init) return;
    void* p;
#define GET(sym, fld, T) cudaGetSymbolAddress(&p, sym); g_sc.fld = (T*)p;
    GET(g_fo, FO, float)
    GET(g_h_obj, HOBJ, float)
    GET(g_h_rel, HREL, float)
    GET(g_xw_rel, XWR, float)
    GET(g_hmhu, HMHU, float)
    GET(g_hw, HW, float)
    GET(g_z_rel, ZR, float)
    GET(g_xw_obj, XWO, float)
    GET(g_hu_obj, HUO, float)
    GET(g_z_obj, ZO, float)
    GET(g_sp, SP, float)
    GET(g_wcomb, WCOMB, float)
    GET(g_bcr, BCR, float)
    GET(g_bco, BCO, float)
    GET(g_keep, KEEP, unsigned char)
    GET(g_Pa_h, Pa_h, __half) GET(g_Pa_l, Pa_l, __half)
    GET(g_Pb_h, Pb_h, __half) GET(g_Pb_l, Pb_l, __half)
    GET(g_Ps_h, Ps_h, __half) GET(g_Ps_l, Ps_l, __half)
    GET(g_Ph_h, Ph_h, __half) GET(g_Ph_l, Ph_l, __half)
    GET(g_Po1_h, Po1_h, __half) GET(g_Po1_l, Po1_l, __half)
    GET(g_Po2_h, Po2_h, __half) GET(g_Po2_l, Po2_l, __half)
    GET(g_Po3_h, Po3_h, __half) GET(g_Po3_l, Po3_l, __half)
    GET(g_OP_h, OP_h, __half)  GET(g_OP_l, OP_l, __half)
    GET(g_Wop_h, Wop_h, __half) GET(g_Wop_l, Wop_l, __half)
    GET(g_Wrp_h, Wrp_h, __half) GET(g_Wrp_l, Wrp_l, __half)
    GET(g_Wemb_h, Wemb_h, __half) GET(g_Wemb_l, Wemb_l, __half)
    GET(g_Wcb_h, Wcb_h, __half) GET(g_Wcb_l, Wcb_l, __half)
    GET(g_Wct_h, Wct_h, __half) GET(g_Wct_l, Wct_l, __half)
    GET(g_Ugr2_h, Ugr2_h, __half) GET(g_Ugr2_l, Ugr2_l, __half)
    GET(g_Wgo_h, Wgo_h, __half) GET(g_Wgo_l, Wgo_l, __half)
    GET(g_Ugo_h, Ugo_h, __half) GET(g_Ugo_l, Ugo_l, __half)
    GET(g_Wcr_h, Wcr_h, __half) GET(g_Wcr_l, Wcr_l, __half)
    GET(g_Wco_h, Wco_h, __half) GET(g_Wco_l, Wco_l, __half)
#undef GET
    cudaFuncSetAttribute(hgemm_kernel, cudaFuncAttributeMaxDynamicSharedMemorySize, HG_SMEM);
    cudaFuncSetAttribute(hgemm_dual_kernel, cudaFuncAttributeMaxDynamicSharedMemorySize, HG_SMEM);
    cudaFuncSetAttribute(hgemm_tri_kernel, cudaFuncAttributeMaxDynamicSharedMemorySize, HG_SMEM);
    g_sc.init = true;
}

static HGArgs mkargs(const __half* Ah, const __half* Al, const __half* Bh, const __half* Bl,
                     float* C, int ldc, int M, int N, int K, const float* bias,
                     __half* Ch = nullptr, __half* Cl = nullptr) {
    HGArgs a;
    a.Ah = Ah; a.Al = Al; a.Bh = Bh; a.Bl = Bl;
    a.C = C; a.ldc = ldc; a.M = M; a.N = N; a.K = K;
    a.bias = bias; a.addm = nullptr; a.Ch = Ch; a.Cl = Cl;
    a.mode = 0; a.XW3 = nullptr; a.ldxw = 0; a.Z = nullptr; a.Hh = nullptr;
    return a;
}

static int nblk(const HGArgs& a) { return (a.M / 128) * (a.N / 128); }
static void hgemm1(const HGArgs& a) {
    hgemm_kernel<<<nblk(a), 256, HG_SMEM>>>(a);
}
static void hgemm2(const HGArgs& a, const HGArgs& b) {
    hgemm_dual_kernel<<<nblk(a) + nblk(b), 256, HG_SMEM>>>(a, b, nblk(a));
}
static void hgemm3(const HGArgs& a, const HGArgs& b, const HGArgs& c) {
    int na = nblk(a), nab = na + nblk(b);
    hgemm_tri_kernel<<<nab + nblk(c), 256, HG_SMEM>>>(a, b, c, na, nab);
}

static void asplit(const float* A, __half* hi, __half* lo, int n) {
    int n2 = n / 2;
    asplit_kernel<<<(n2 + 255) / 256, 256>>>((const float2*)A, (__half2*)hi, (__half2*)lo, n2);
}

static void wsplit(const float* W, int ldw, int c0, int wcols, int wrows,
                   __half* Th, __half* Tl, int K, int ncols) {
    dim3 g(ncols / 32, K / 32);
    wsplit_kernel<<<g, dim3(32, 8)>>>(W, ldw, c0, wcols, wrows, Th, Tl, K);
}

extern "C" void kernel_launch(void* const* d_in, const int* in_sizes, int n_in,
                              void* d_out, int out_size) {
    (void)in_sizes; (void)n_in; (void)out_size;
    init_scratch();

    const float* obj_fmaps  = (const float*)d_in[1];
    const float* obj_logits = (const float*)d_in[2];
    const void*  rel_raw    = d_in[3];
    const float* vr         = (const float*)d_in[4];
    const float* boxes      = (const float*)d_in[5];
    const float* W_obj_proj = (const float*)d_in[6];
    const float* b_obj_proj = (const float*)d_in[7];
    const float* W_rel_proj = (const float*)d_in[8];
    const float* b_rel_proj = (const float*)d_in[9];
    const float* W_emb      = (const float*)d_in[10];
    const float* W_msg_rel  = (const float*)d_in[11];
    const float* W_msg_obj  = (const float*)d_in[12];
    const float* W_gru_obj  = (const float*)d_in[13];
    const float* U_gru_obj  = (const float*)d_in[14];
    const float* b_gru_obj  = (const float*)d_in[15];
    const float* W_gru_rel  = (const float*)d_in[16];
    const float* U_gru_rel  = (const float*)d_in[17];
    const float* b_gru_rel  = (const float*)d_in[18];
    const float* W_cls_rel  = (const float*)d_in[19];
    const float* b_cls_rel  = (const float*)d_in[20];
    const float* W_cls_obj  = (const float*)d_in[21];
    const float* b_cls_obj  = (const float*)d_in[22];

    float* out_obj_logits = (float*)d_out;
    float* out_preds      = out_obj_logits + NN * NOC_;
    float* out_rel_logits = out_preds + NN;

    // 0. decode; weight planes
    decode_rel_kernel<<<1, 1024>>>(rel_raw);
    wsplit(W_obj_proj, HD, 0, HD, OBJD, g_sc.Wop_h, g_sc.Wop_l, OBJD, HD);
    wsplit(W_rel_proj, HD, 0, HD, OBJD, g_sc.Wrp_h, g_sc.Wrp_l, OBJD, HD);
    wsplit(W_emb, HD, 0, HD, NOC_, g_sc.Wemb_h, g_sc.Wemb_l, KEMB, HD);
    wsplit(W_msg_obj, HD, 0, HD, HD, g_sc.Wct_h, g_sc.Wct_l, HD, HD);
    wsplit(U_gru_rel, 3 * HD, 0, 3 * HD, HD, g_sc.Wct_h + (size_t)HD * HD,
           g_sc.Wct_l + (size_t)HD * HD, HD, 2 * HD);
    wsplit(U_gru_rel, 3 * HD, 2 * HD, 3 * HD, HD, g_sc.Ugr2_h, g_sc.Ugr2_l, HD, HD);
    wsplit(W_gru_obj, 3 * HD, 0, 3 * HD, HD, g_sc.Wgo_h, g_sc.Wgo_l, HD, 3 * HD);
    wsplit(U_gru_obj, 3 * HD, 0, 3 * HD, HD, g_sc.Ugo_h, g_sc.Ugo_l, HD, 3 * HD);
    wsplit(W_cls_rel, NRC_, 0, NRC_, HD, g_sc.Wcr_h, g_sc.Wcr_l, HD, 128);
    wsplit(W_cls_obj, NOC_, 0, NOC_, HD, g_sc.Wco_h, g_sc.Wco_l, HD, 256);
    biaspad_kernel<<<1, 128>>>(b_cls_rel, g_sc.BCR, NRC_, 128);
    biaspad_kernel<<<1, 256>>>(b_cls_obj, g_sc.BCO, NOC_, 256);
    // WCOMB = W_msg_rel @ W_gru_rel (f32 SIMT), then planes
    {
        dim3 g((3 * HD + 127) / 128, (HD + 127) / 128);
        sgemm_kernel<<<g, 256>>>(W_msg_rel, HD, W_gru_rel, 3 * HD, g_sc.WCOMB, 3 * HD,
                                 HD, 3 * HD, HD);
    }
    wsplit(g_sc.WCOMB, 3 * HD, 0, 3 * HD, HD, g_sc.Wcb_h, g_sc.Wcb_l, HD, 3 * HD);

    // 1. activation splits
    asplit(obj_fmaps, g_sc.Pb_h, g_sc.Pb_l, NN * OBJD);
    asplit(vr, g_sc.Pa_h, g_sc.Pa_l, RR * OBJD);
    softmax_split_kernel<<<NN, 256>>>(obj_logits, g_sc.OP_h, g_sc.OP_l);

    // 2. fo + h_rel (paired)
    hgemm2(mkargs(g_sc.Pb_h, g_sc.Pb_l, g_sc.Wop_h, g_sc.Wop_l, g_sc.FO, HD,
                  NN, HD, OBJD, b_obj_proj),
           mkargs(g_sc.Pa_h, g_sc.Pa_l, g_sc.Wrp_h, g_sc.Wrp_l, g_sc.HREL, HD,
                  RR, HD, OBJD, b_rel_proj, g_sc.Ph_h, g_sc.Ph_l));

    // 3. h_obj = obj_probs @ W_emb + fo (tensor path, addm), planes out
    {
        HGArgs a = mkargs(g_sc.OP_h, g_sc.OP_l, g_sc.Wemb_h, g_sc.Wemb_l, g_sc.HOBJ, HD,
                          NN, HD, KEMB, nullptr, g_sc.Po2_h, g_sc.Po2_l);
        a.addm = g_sc.FO;
        hgemm1(a);
    }

    const int EW_REL = (RR * HD + 255) / 256;
    const int EW_OBJ = (NN * HD + 255) / 256;
    const int XG_BLOCKS = (RR * 384 + 255) / 256;
    const __half* Ugo2_h = g_sc.Ugo_h + (size_t)2 * HD * HD;
    const __half* Ugo2_l = g_sc.Ugo_l + (size_t)2 * HD * HD;

    for (int t = 0; t < TSTEPS; t++) {
        // HW = HOBJ@WCOMB ; HMHU = h_rel@WCAT ; HUO = HOBJ@Ugo01  (one tri launch)
        hgemm3(mkargs(g_sc.Po2_h, g_sc.Po2_l, g_sc.Wcb_h, g_sc.Wcb_l, g_sc.HW, 3 * HD,
                      NN, 3 * HD, HD, nullptr),
               mkargs(g_sc.Ph_h, g_sc.Ph_l, g_sc.Wct_h, g_sc.Wct_l, g_sc.HMHU, 3 * HD,
                      RR, 3 * HD, HD, nullptr),
               mkargs(g_sc.Po2_h, g_sc.Po2_l, g_sc.Ugo_h, g_sc.Ugo_l, g_sc.HUO, 2 * HD,
                      NN, 2 * HD, HD, nullptr));
        // XWR[r] = HW[s_r] + HW[o_r]
        xwr_gather_kernel<<<XG_BLOCKS, 256>>>((const float4*)g_sc.HW, (float4*)g_sc.XWR);
        scatter_obj_kernel<<<NN, 512>>>(g_sc.HMHU, 3 * HD, g_sc.Po1_h, g_sc.Po1_l);

        // GRU rel zr; then (rel NU+fin) paired with XWO
        gru_zr_kernel<<<EW_REL, 256>>>(g_sc.XWR, 3 * HD, g_sc.HMHU + HD, 3 * HD,
                                       b_gru_rel, g_sc.HREL, g_sc.ZR, g_sc.Ps_h, g_sc.Ps_l, RR);
        {
            HGArgs fin = mkargs(g_sc.Ps_h, g_sc.Ps_l, g_sc.Ugr2_h, g_sc.Ugr2_l,
                                nullptr, HD, RR, HD, HD, b_gru_rel + 2 * HD,
                                g_sc.Ph_h, g_sc.Ph_l);
            fin.mode = 1; fin.XW3 = g_sc.XWR + 2 * HD; fin.ldxw = 3 * HD;
            fin.Z = g_sc.ZR; fin.Hh = g_sc.HREL;
            hgemm2(fin,
                   mkargs(g_sc.Po1_h, g_sc.Po1_l, g_sc.Wgo_h, g_sc.Wgo_l, g_sc.XWO, 3 * HD,
                          NN, 3 * HD, HD, nullptr));
        }

        // GRU obj zr; NU+fin
        gru_zr_kernel<<<EW_OBJ, 256>>>(g_sc.XWO, 3 * HD, g_sc.HUO, 2 * HD,
                                       b_gru_obj, g_sc.HOBJ, g_sc.ZO, g_sc.Po3_h, g_sc.Po3_l, NN);
        {
            HGArgs fin = mkargs(g_sc.Po3_h, g_sc.Po3_l, Ugo2_h, Ugo2_l,
                                nullptr, HD, NN, HD, HD, b_gru_obj + 2 * HD,
                                g_sc.Po2_h, g_sc.Po2_l);
            fin.mode = 1; fin.XW3 = g_sc.XWO + 2 * HD; fin.ldxw = 3 * HD;
            fin.Z = g_sc.ZO; fin.Hh = g_sc.HOBJ;
            hgemm1(fin);
        }
    }

    // classifiers (padded N tensor path) + pack
    hgemm2(mkargs(g_sc.Ph_h, g_sc.Ph_l, g_sc.Wcr_h, g_sc.Wcr_l, g_sc.HMHU, 128,
                  RR, 128, HD, g_sc.BCR),
           mkargs(g_sc.Po2_h, g_sc.Po2_l, g_sc.Wco_h, g_sc.Wco_l, g_sc.XWO, 256,
                  NN, 256, HD, g_sc.BCO));
    pack_kernel<<<(RR * NRC_ + 255) / 256, 256>>>(g_sc.HMHU, 128, out_rel_logits, NRC_, RR * NRC_);
    pack_kernel<<<(NN * NOC_ + 255) / 256, 256>>>(g_sc.XWO, 256, out_obj_logits, NOC_, NN * NOC_);

    // softmax -> NMS -> preds
    softmax_kernel<<<NN, 256>>>(out_obj_logits, g_sc.SP);
    nms_kernel<<<150, 512>>>(g_sc.SP, boxes, g_sc.KEEP);
    preds_kernel<<<(NN + 255) / 256, 256>>>(g_sc.SP, g_sc.KEEP, out_preds);
}